// round 4
// baseline (speedup 1.0000x reference)
#include <cuda_runtime.h>
#include <math.h>

#define NB 64
#define NN 300
#define NH 64
#define ROWS (NB*NN)        /* 19200 */
#define HC2  4096           /* HC*HC */

typedef unsigned long long ull;

// ---------------- scratch (device globals; no allocations allowed) ----------
__device__ float g_H   [NB*NN*NH];      // relu(z W_in^T + b)      [b][n][i]
__device__ float g_A   [NN*NN];         // supports                [n][m]
__device__ float g_At  [NN*NN];         // supports^T              [m][n]
__device__ float g_S2t [NN*NN];         // (2A^2 - I)^T            [m][n]
__device__ float g_Wn  [NN*3*NH*NH];    // per-node weights        [n][k*64+i][o]
__device__ float g_bn  [NN*NH];         // per-node bias           [n][o]
__device__ float g_XG  [NN*NB*192];     // diffused features       [n][b][k*64+i]
__device__ float g_H2T [NH*ROWS];       // agc output, transposed  [i][row]
__device__ float g_WoT [NH*HC2];        // W_out^T                 [i][c]

// ---------------- f32x2 helpers (Blackwell packed fp32) ---------------------
__device__ __forceinline__ ull ffma2(ull a, ull b, ull c) {
    ull d;
    asm("fma.rn.f32x2 %0, %1, %2, %3;" : "=l"(d) : "l"(a), "l"(b), "l"(c));
    return d;
}
__device__ __forceinline__ ull pack2(float x, float y) {
    ull d;
    asm("mov.b64 %0, {%1, %2};" : "=l"(d) : "f"(x), "f"(y));
    return d;
}
__device__ __forceinline__ float2 unpack2(ull v) {
    float2 r;
    asm("mov.b64 {%0, %1}, %2;" : "=f"(r.x), "=f"(r.y) : "l"(v));
    return r;
}

// Accurate fast tanh: series near 0 (avoids exp cancellation), exp form else.
__device__ __forceinline__ float my_tanh(float x) {
    float x2 = x * x;
    float poly = x * fmaf(x2, fmaf(x2, 0.13333333f, -0.33333333f), 1.0f);
    float xc = fminf(fmaxf(x, -15.f), 15.f);
    float e = __expf(2.f * xc);
    float ef = __fdividef(e - 1.f, e + 1.f);
    return (fabsf(x) < 0.1f) ? poly : ef;
}

// ---------------- K0: transpose W_out [4096,64] -> WoT [64][4096] -----------
__global__ void k0_transW(const float* __restrict__ W_out) {
    int c = blockIdx.x * 128 + threadIdx.x;
    if (c < HC2) {
        #pragma unroll 8
        for (int i = 0; i < 64; i++)
            g_WoT[i*HC2 + c] = W_out[c*64 + i];
    }
}

// ---------------- K1: H = relu(z W_in^T + b_in); also XG k=0 slice ---------
__global__ void __launch_bounds__(256) k1_inproj(const float* __restrict__ z,
                                                 const float* __restrict__ W_in,
                                                 const float* __restrict__ b_in) {
    __shared__ float Wt[64*64];  // Wt[i][o] = W_in[o][i]
    __shared__ float zs[256];    // 4 rows x 64
    int t = threadIdx.x;
    int rowBase = blockIdx.x * 4;
    for (int idx = t; idx < 4096; idx += 256) {
        int o = idx >> 6, i = idx & 63;
        Wt[i*64 + o] = W_in[idx];
    }
    zs[t] = z[rowBase*64 + t];
    __syncthreads();
    int o = t & 63, rr = t >> 6;
    float acc = b_in[o];
    #pragma unroll
    for (int i = 0; i < 64; i++)
        acc = fmaf(zs[rr*64 + i], Wt[i*64 + o], acc);
    float h = fmaxf(acc, 0.f);
    int row = rowBase + rr;
    g_H[row*64 + o] = h;
    int b = row / NN, n = row - b*NN;
    g_XG[n*12288 + b*192 + o] = h;   // k = 0 slice (identity support)
}

// ---------------- K2: A = softmax_row(relu(E E^T)); also A^T ---------------
__global__ void __launch_bounds__(320) k2_supports(const float* __restrict__ node_emb) {
    __shared__ float E[NN*10];
    __shared__ float red[512];
    int t = threadIdx.x, n = blockIdx.x;
    for (int idx = t; idx < NN*10; idx += 320) E[idx] = node_emb[idx];
    if (t < 192) red[320 + t] = -1e30f;
    __syncthreads();

    float v = 0.f;
    if (t < NN) {
        float dot = 0.f;
        #pragma unroll
        for (int d = 0; d < 10; d++) dot = fmaf(E[n*10+d], E[t*10+d], dot);
        v = fmaxf(dot, 0.f);
    }
    red[t] = (t < NN) ? v : -1e30f;
    __syncthreads();
    #pragma unroll
    for (int s = 256; s > 0; s >>= 1) {
        if (t < s) red[t] = fmaxf(red[t], red[t+s]);
        __syncthreads();
    }
    float mx = red[0];
    __syncthreads();

    float ev = (t < NN) ? __expf(v - mx) : 0.f;
    red[t] = ev;
    if (t < 192) red[320 + t] = 0.f;
    __syncthreads();
    #pragma unroll
    for (int s = 256; s > 0; s >>= 1) {
        if (t < s) red[t] += red[t+s];
        __syncthreads();
    }
    float inv = 1.f / red[0];
    if (t < NN) {
        float a = ev * inv;
        g_A [n*NN + t] = a;
        g_At[t*NN + n] = a;
    }
}

// ---------------- K3: S2 = 2 A A - I, stored transposed --------------------
__global__ void __launch_bounds__(320) k3_cheb() {
    __shared__ float arow[NN];
    int t = threadIdx.x, n = blockIdx.x;
    for (int idx = t; idx < NN; idx += 320) arow[idx] = g_A[n*NN + idx];
    __syncthreads();
    if (t < NN) {
        float acc = 0.f;
        for (int p = 0; p < NN; p++)
            acc = fmaf(arow[p], g_A[p*NN + t], acc);
        g_S2t[t*NN + n] = 2.f*acc - ((t == n) ? 1.f : 0.f);
    }
}

// ---------------- K3b: per-node weights & bias (contract over D=10) --------
__global__ void __launch_bounds__(256) k3b_nodeparams(const float* __restrict__ node_emb,
                                                      const float* __restrict__ wpool,
                                                      const float* __restrict__ bpool) {
    __shared__ float e[10];
    int n = blockIdx.x, t = threadIdx.x;
    if (t < 10) e[t] = node_emb[n*10 + t];
    __syncthreads();
    for (int j = t; j < 12288; j += 256) {
        float acc = 0.f;
        #pragma unroll
        for (int d = 0; d < 10; d++)
            acc = fmaf(e[d], wpool[d*12288 + j], acc);
        g_Wn[n*12288 + j] = acc;
    }
    if (t < 64) {
        float acc = 0.f;
        #pragma unroll
        for (int d = 0; d < 10; d++)
            acc = fmaf(e[d], bpool[d*64 + t], acc);
        g_bn[n*64 + t] = acc;
    }
}

// ---------------- K4: XG[n][b][kk+1] = sum_m S_k[n][m] * H[b][m][:] --------
// grid (b=64, kk=2, half=2), 160 threads; one thread owns node n, 64 channels
// as 32 f32x2 accumulators. All shared reads are warp-broadcasts.
__global__ void __launch_bounds__(160) k4_diffuse() {
    __shared__ float Hs[32*64];
    int t = threadIdx.x;
    int b = blockIdx.x, kk = blockIdx.y, half = blockIdx.z;
    const float* St = (kk == 0) ? g_At : g_S2t;   // transposed supports
    const float* Hb = g_H + b*NN*NH;
    int n = half*150 + t;
    bool act = (t < 150);

    ull acc[32];
    #pragma unroll
    for (int q = 0; q < 32; q++) acc[q] = 0ull;

    for (int mt = 0; mt < NN; mt += 32) {
        int tile = min(32, NN - mt);
        __syncthreads();
        for (int idx = t; idx < tile*64; idx += 160) Hs[idx] = Hb[mt*64 + idx];
        __syncthreads();
        if (act) {
            float s = St[mt*NN + n];
            for (int mm = 0; mm < tile; mm++) {
                float sn = (mm+1 < tile) ? St[(mt+mm+1)*NN + n] : 0.f;
                ull sd = pack2(s, s);
                const ulonglong2* hp = (const ulonglong2*)(Hs + mm*64);
                #pragma unroll
                for (int q = 0; q < 16; q++) {
                    ulonglong2 hv = hp[q];
                    acc[2*q]   = ffma2(sd, hv.x, acc[2*q]);
                    acc[2*q+1] = ffma2(sd, hv.y, acc[2*q+1]);
                }
                s = sn;
            }
        }
    }
    if (act) {
        float2* dst = (float2*)(g_XG + n*12288 + b*192 + (kk+1)*64);
        #pragma unroll
        for (int q = 0; q < 32; q++) dst[q] = unpack2(acc[q]);
    }
}

// ---------------- K5: per-node [64,192]@[192,64] + bias -> H2T (transposed) -
__global__ void __launch_bounds__(256) k5_nodegemm() {
    extern __shared__ float sm5[];
    float* XGs = sm5;               // [64][196] padded pitch
    float* Wns = sm5 + 64*196;      // [192][64]
    int n = blockIdx.x, t = threadIdx.x;
    const float* xg = g_XG + n*12288;
    const float* wn = g_Wn + n*12288;
    for (int idx = t; idx < 12288; idx += 256) {
        int bb = idx / 192, j = idx - bb*192;
        XGs[bb*196 + j] = xg[idx];
        Wns[idx] = wn[idx];
    }
    __syncthreads();

    int o4 = (t & 15) * 4;
    int b4 = (t >> 4) * 4;
    float acc[4][4];
    #pragma unroll
    for (int a = 0; a < 4; a++)
        #pragma unroll
        for (int c = 0; c < 4; c++) acc[a][c] = 0.f;

    const float* x0 = XGs + b4*196;
    #pragma unroll 2
    for (int j = 0; j < 192; j++) {
        float4 wv = *(const float4*)(Wns + j*64 + o4);
        #pragma unroll
        for (int bb = 0; bb < 4; bb++) {
            float xv = x0[bb*196 + j];
            acc[bb][0] = fmaf(xv, wv.x, acc[bb][0]);
            acc[bb][1] = fmaf(xv, wv.y, acc[bb][1]);
            acc[bb][2] = fmaf(xv, wv.z, acc[bb][2]);
            acc[bb][3] = fmaf(xv, wv.w, acc[bb][3]);
        }
    }
    float4 bias = *(const float4*)(g_bn + n*64 + o4);
    #pragma unroll
    for (int bb = 0; bb < 4; bb++) {
        int row = (b4+bb)*NN + n;
        g_H2T[(o4+0)*ROWS + row] = acc[bb][0] + bias.x;
        g_H2T[(o4+1)*ROWS + row] = acc[bb][1] + bias.y;
        g_H2T[(o4+2)*ROWS + row] = acc[bb][2] + bias.z;
        g_H2T[(o4+3)*ROWS + row] = acc[bb][3] + bias.w;
    }
}

// ---------------- K6: out = tanh(H2 @ W_out^T + b_out) ---------------------
// 128x128 tile, K=64 single stage. Per thread: 8 rows x 8 cols = 32 f32x2.
__global__ void __launch_bounds__(256) k6_outproj(const float* __restrict__ b_out,
                                                  float* __restrict__ out) {
    extern __shared__ float sm6[];
    float* As = sm6;             // [64][128]  As[i][r] = h2[rowBase+r][i]
    float* Bs = sm6 + 64*128;    // [64][128]  Bs[i][c] = WoT[i][colBase+c]
    int t = threadIdx.x;
    int rowBase = blockIdx.x * 128;
    int colBase = blockIdx.y * 128;

    // load tiles (float4, coalesced)
    for (int idx4 = t; idx4 < 2048; idx4 += 256) {
        int i = idx4 >> 5, r4 = (idx4 & 31) * 4;
        *(float4*)(As + i*128 + r4) = *(const float4*)(g_H2T + i*ROWS + rowBase + r4);
        *(float4*)(Bs + i*128 + r4) = *(const float4*)(g_WoT + i*HC2  + colBase + r4);
    }
    __syncthreads();

    int tx = t & 15, ty = t >> 4;
    int r0 = ty * 8, c0 = tx * 8;

    ull acc[8][4];
    #pragma unroll
    for (int r = 0; r < 8; r++)
        #pragma unroll
        for (int q = 0; q < 4; q++) acc[r][q] = 0ull;

    #pragma unroll 4
    for (int k = 0; k < 64; k++) {
        float4 a0 = *(const float4*)(As + k*128 + r0);
        float4 a1 = *(const float4*)(As + k*128 + r0 + 4);
        ulonglong2 bv0 = *(const ulonglong2*)(Bs + k*128 + c0);
        ulonglong2 bv1 = *(const ulonglong2*)(Bs + k*128 + c0 + 4);
        ull bq[4] = {bv0.x, bv0.y, bv1.x, bv1.y};
        float ar[8] = {a0.x, a0.y, a0.z, a0.w, a1.x, a1.y, a1.z, a1.w};
        #pragma unroll
        for (int r = 0; r < 8; r++) {
            ull ad = pack2(ar[r], ar[r]);
            #pragma unroll
            for (int q = 0; q < 4; q++)
                acc[r][q] = ffma2(ad, bq[q], acc[r][q]);
        }
    }

    float4 bo0 = *(const float4*)(b_out + colBase + c0);
    float4 bo1 = *(const float4*)(b_out + colBase + c0 + 4);
    float bb[8] = {bo0.x, bo0.y, bo0.z, bo0.w, bo1.x, bo1.y, bo1.z, bo1.w};

    #pragma unroll
    for (int r = 0; r < 8; r++) {
        float o[8];
        #pragma unroll
        for (int q = 0; q < 4; q++) {
            float2 v = unpack2(acc[r][q]);
            o[2*q]   = my_tanh(v.x + bb[2*q]);
            o[2*q+1] = my_tanh(v.y + bb[2*q+1]);
        }
        float* dst = out + (size_t)(rowBase + r0 + r) * HC2 + colBase + c0;
        *(float4*)(dst)     = make_float4(o[0], o[1], o[2], o[3]);
        *(float4*)(dst + 4) = make_float4(o[4], o[5], o[6], o[7]);
    }
}

// ---------------- launch -----------------------------------------------------
extern "C" void kernel_launch(void* const* d_in, const int* in_sizes, int n_in,
                              void* d_out, int out_size) {
    const float* z      = (const float*)d_in[0];
    const float* W_in   = (const float*)d_in[1];
    const float* b_in   = (const float*)d_in[2];
    const float* W_out  = (const float*)d_in[3];
    const float* b_out  = (const float*)d_in[4];
    const float* emb    = (const float*)d_in[5];
    const float* wpool  = (const float*)d_in[6];
    const float* bpool  = (const float*)d_in[7];
    float* out = (float*)d_out;

    static bool attr_set = false;
    if (!attr_set) {
        cudaFuncSetAttribute(k5_nodegemm,
            cudaFuncAttributeMaxDynamicSharedMemorySize, 64*196*4 + 192*64*4);
        cudaFuncSetAttribute(k6_outproj,
            cudaFuncAttributeMaxDynamicSharedMemorySize, 2*64*128*4);
        attr_set = true;
    }

    k0_transW  <<<32, 128>>>(W_out);
    k1_inproj  <<<ROWS/4, 256>>>(z, W_in, b_in);
    k2_supports<<<NN, 320>>>(emb);
    k3_cheb    <<<NN, 320>>>();
    k3b_nodeparams<<<NN, 256>>>(emb, wpool, bpool);
    k4_diffuse <<<dim3(NB, 2, 2), 160>>>();
    k5_nodegemm<<<NN, 256, 64*196*4 + 192*64*4>>>();
    k6_outproj <<<dim3(ROWS/128, HC2/128), 256, 2*64*128*4>>>(b_out, out);
}

// round 5
// speedup vs baseline: 1.0389x; 1.0389x over previous
#include <cuda_runtime.h>
#include <math.h>

#define NB 64
#define NN 300
#define NH 64
#define ROWS (NB*NN)        /* 19200 */
#define HC2  4096           /* HC*HC */

typedef unsigned long long ull;

// ---------------- scratch (device globals; no allocations allowed) ----------
__device__ float g_H   [NB*NN*NH];      // relu(z W_in^T + b)      [b][n][i]
__device__ float g_A   [NN*NN];         // supports                [n][m]
__device__ float g_At  [NN*NN];         // supports^T              [m][n]
__device__ float g_S2t [NN*NN];         // (2A^2 - I)^T            [m][n]
__device__ float g_Wn  [NN*3*NH*NH];    // per-node weights        [n][k*64+i][o]
__device__ float g_bn  [NN*NH];         // per-node bias           [n][o]
__device__ float g_XG  [NN*NB*192];     // diffused features       [n][b][k*64+i]
__device__ float g_H2T [NH*ROWS];       // agc output, transposed  [i][row]
__device__ float g_WoT [NH*HC2];        // W_out^T                 [i][c]

// ---------------- f32x2 helpers (Blackwell packed fp32) ---------------------
__device__ __forceinline__ ull ffma2(ull a, ull b, ull c) {
    ull d;
    asm("fma.rn.f32x2 %0, %1, %2, %3;" : "=l"(d) : "l"(a), "l"(b), "l"(c));
    return d;
}
__device__ __forceinline__ ull pack2(float x, float y) {
    ull d;
    asm("mov.b64 %0, {%1, %2};" : "=l"(d) : "f"(x), "f"(y));
    return d;
}
__device__ __forceinline__ float2 unpack2(ull v) {
    float2 r;
    asm("mov.b64 {%0, %1}, %2;" : "=f"(r.x), "=f"(r.y) : "l"(v));
    return r;
}

// Accurate fast tanh: series near 0 (avoids exp cancellation), exp form else.
__device__ __forceinline__ float my_tanh(float x) {
    float x2 = x * x;
    float poly = x * fmaf(x2, fmaf(x2, 0.13333333f, -0.33333333f), 1.0f);
    float xc = fminf(fmaxf(x, -15.f), 15.f);
    float e = __expf(2.f * xc);
    float ef = __fdividef(e - 1.f, e + 1.f);
    return (fabsf(x) < 0.1f) ? poly : ef;
}

// ---------------- KA: in-projection (blocks 0..299) + W_out transpose -------
// blocks [0,300): H = relu(z W_in^T + b_in), 64 rows/block; also XG k=0 slice.
// blocks [300,332): transpose W_out [4096,64] -> WoT [64][4096] via smem.
__global__ void __launch_bounds__(256) kA_inproj_transW(
        const float* __restrict__ z,
        const float* __restrict__ W_in,
        const float* __restrict__ b_in,
        const float* __restrict__ W_out) {
    __shared__ float sm[8320];
    int t = threadIdx.x;
    if (blockIdx.x < 300) {
        float* Wt = sm;            // [64][64]  Wt[i][o] = W_in[o][i]
        float* zs = sm + 4096;     // [64][64]  64 rows of z
        int rowBase = blockIdx.x * 64;
        for (int idx = t; idx < 4096; idx += 256) {
            int o = idx >> 6, i = idx & 63;
            Wt[i*64 + o] = W_in[idx];
        }
        for (int idx4 = t; idx4 < 1024; idx4 += 256)
            *(float4*)(zs + idx4*4) = *(const float4*)(z + (size_t)rowBase*64 + idx4*4);
        __syncthreads();

        int o = t & 63, rg = t >> 6;           // each thread: 16 rows, 1 column
        float acc[16];
        float bo = b_in[o];
        #pragma unroll
        for (int r = 0; r < 16; r++) acc[r] = bo;
        const float* zrow = zs + rg*16*64;
        #pragma unroll 4
        for (int i = 0; i < 64; i++) {
            float w = Wt[i*64 + o];
            #pragma unroll
            for (int r = 0; r < 16; r++)
                acc[r] = fmaf(zrow[r*64 + i], w, acc[r]);
        }
        #pragma unroll
        for (int r = 0; r < 16; r++) {
            float h = fmaxf(acc[r], 0.f);
            int row = rowBase + rg*16 + r;
            g_H[row*64 + o] = h;
            int b = row / NN, n = row - b*NN;
            g_XG[n*12288 + b*192 + o] = h;     // k = 0 slice (identity support)
        }
    } else {
        // transpose 128 columns of W_out per block
        float* Ts = sm;                        // [128][65] padded
        int cb = (blockIdx.x - 300) * 128;
        for (int idx = t; idx < 8192; idx += 256) {
            int cl = idx >> 6, i = idx & 63;   // coalesced gmem read
            Ts[cl*65 + i] = W_out[(size_t)(cb + cl)*64 + i];
        }
        __syncthreads();
        for (int idx = t; idx < 8192; idx += 256) {
            int i = idx >> 7, cl = idx & 127;  // coalesced gmem write
            g_WoT[i*HC2 + cb + cl] = Ts[cl*65 + i];
        }
    }
}

// ---------------- KB: supports softmax (blocks 0..299) + node params --------
__global__ void __launch_bounds__(320) kB_supports_nodeparams(
        const float* __restrict__ node_emb,
        const float* __restrict__ wpool,
        const float* __restrict__ bpool) {
    __shared__ float E[NN*10];
    __shared__ float red[512];
    int t = threadIdx.x;
    if (blockIdx.x < 300) {
        int n = blockIdx.x;
        for (int idx = t; idx < NN*10; idx += 320) E[idx] = node_emb[idx];
        if (t < 192) red[320 + t] = -1e30f;
        __syncthreads();

        float v = 0.f;
        if (t < NN) {
            float dot = 0.f;
            #pragma unroll
            for (int d = 0; d < 10; d++) dot = fmaf(E[n*10+d], E[t*10+d], dot);
            v = fmaxf(dot, 0.f);
        }
        red[t] = (t < NN) ? v : -1e30f;
        __syncthreads();
        #pragma unroll
        for (int s = 256; s > 0; s >>= 1) {
            if (t < s) red[t] = fmaxf(red[t], red[t+s]);
            __syncthreads();
        }
        float mx = red[0];
        __syncthreads();

        float ev = (t < NN) ? __expf(v - mx) : 0.f;
        red[t] = ev;
        if (t < 192) red[320 + t] = 0.f;
        __syncthreads();
        #pragma unroll
        for (int s = 256; s > 0; s >>= 1) {
            if (t < s) red[t] += red[t+s];
            __syncthreads();
        }
        float inv = 1.f / red[0];
        if (t < NN) {
            float a = ev * inv;
            g_A [n*NN + t] = a;
            g_At[t*NN + n] = a;
        }
    } else {
        int n = blockIdx.x - 300;
        float* e = red;                         // reuse smem
        if (t < 10) e[t] = node_emb[n*10 + t];
        __syncthreads();
        for (int j = t; j < 12288; j += 320) {
            float acc = 0.f;
            #pragma unroll
            for (int d = 0; d < 10; d++)
                acc = fmaf(e[d], wpool[d*12288 + j], acc);
            g_Wn[n*12288 + j] = acc;
        }
        if (t < 64) {
            float acc = 0.f;
            #pragma unroll
            for (int d = 0; d < 10; d++)
                acc = fmaf(e[d], bpool[d*64 + t], acc);
            g_bn[n*64 + t] = acc;
        }
    }
}

// ---------------- K3: S2 = 2 A A - I, stored transposed --------------------
__global__ void __launch_bounds__(320) k3_cheb() {
    __shared__ float arow[NN];
    int t = threadIdx.x, n = blockIdx.x;
    for (int idx = t; idx < NN; idx += 320) arow[idx] = g_A[n*NN + idx];
    __syncthreads();
    if (t < NN) {
        float acc = 0.f;
        #pragma unroll 4
        for (int p = 0; p < NN; p++)
            acc = fmaf(arow[p], g_A[p*NN + t], acc);
        g_S2t[t*NN + n] = 2.f*acc - ((t == n) ? 1.f : 0.f);
    }
}

// ---------------- K4: XG[n][b][kk+1] = sum_m S_k[n][m] * H[b][m][:] --------
__global__ void __launch_bounds__(160) k4_diffuse() {
    __shared__ float Hs[32*64];
    int t = threadIdx.x;
    int b = blockIdx.x, kk = blockIdx.y, half = blockIdx.z;
    const float* St = (kk == 0) ? g_At : g_S2t;   // transposed supports
    const float* Hb = g_H + b*NN*NH;
    int n = half*150 + t;
    bool act = (t < 150);

    ull acc[32];
    #pragma unroll
    for (int q = 0; q < 32; q++) acc[q] = 0ull;

    for (int mt = 0; mt < NN; mt += 32) {
        int tile = min(32, NN - mt);
        __syncthreads();
        for (int idx = t; idx < tile*64; idx += 160) Hs[idx] = Hb[mt*64 + idx];
        __syncthreads();
        if (act) {
            float s = St[mt*NN + n];
            for (int mm = 0; mm < tile; mm++) {
                float sn = (mm+1 < tile) ? St[(mt+mm+1)*NN + n] : 0.f;
                ull sd = pack2(s, s);
                const ulonglong2* hp = (const ulonglong2*)(Hs + mm*64);
                #pragma unroll
                for (int q = 0; q < 16; q++) {
                    ulonglong2 hv = hp[q];
                    acc[2*q]   = ffma2(sd, hv.x, acc[2*q]);
                    acc[2*q+1] = ffma2(sd, hv.y, acc[2*q+1]);
                }
                s = sn;
            }
        }
    }
    if (act) {
        float2* dst = (float2*)(g_XG + n*12288 + b*192 + (kk+1)*64);
        #pragma unroll
        for (int q = 0; q < 32; q++) dst[q] = unpack2(acc[q]);
    }
}

// ---------------- K5: per-node [64,192]@[192,64] + bias -> H2T (transposed) -
__global__ void __launch_bounds__(256) k5_nodegemm() {
    extern __shared__ float sm5[];
    float* XGs = sm5;               // [64][196] padded pitch
    float* Wns = sm5 + 64*196;      // [192][64]
    int n = blockIdx.x, t = threadIdx.x;
    const float* xg = g_XG + n*12288;
    const float* wn = g_Wn + n*12288;
    for (int idx = t; idx < 12288; idx += 256) {
        int bb = idx / 192, j = idx - bb*192;
        XGs[bb*196 + j] = xg[idx];
        Wns[idx] = wn[idx];
    }
    __syncthreads();

    int o4 = (t & 15) * 4;
    int b4 = (t >> 4) * 4;
    float acc[4][4];
    #pragma unroll
    for (int a = 0; a < 4; a++)
        #pragma unroll
        for (int c = 0; c < 4; c++) acc[a][c] = 0.f;

    const float* x0 = XGs + b4*196;
    #pragma unroll 2
    for (int j = 0; j < 192; j++) {
        float4 wv = *(const float4*)(Wns + j*64 + o4);
        #pragma unroll
        for (int bb = 0; bb < 4; bb++) {
            float xv = x0[bb*196 + j];
            acc[bb][0] = fmaf(xv, wv.x, acc[bb][0]);
            acc[bb][1] = fmaf(xv, wv.y, acc[bb][1]);
            acc[bb][2] = fmaf(xv, wv.z, acc[bb][2]);
            acc[bb][3] = fmaf(xv, wv.w, acc[bb][3]);
        }
    }
    float4 bias = *(const float4*)(g_bn + n*64 + o4);
    #pragma unroll
    for (int bb = 0; bb < 4; bb++) {
        int row = (b4+bb)*NN + n;
        g_H2T[(o4+0)*ROWS + row] = acc[bb][0] + bias.x;
        g_H2T[(o4+1)*ROWS + row] = acc[bb][1] + bias.y;
        g_H2T[(o4+2)*ROWS + row] = acc[bb][2] + bias.z;
        g_H2T[(o4+3)*ROWS + row] = acc[bb][3] + bias.w;
    }
}

// ---------------- K6: out = tanh(H2 @ W_out^T + b_out) ---------------------
// 128x128 tile, K=64 single stage. A pre-duplicated in smem as f32x2 pairs:
// per k-step 6x LDS.128 + 32x FFMA2, zero pack movs. 2 CTAs/SM.
__global__ void __launch_bounds__(256, 2) k6_outproj(const float* __restrict__ b_out,
                                                     float* __restrict__ out) {
    extern __shared__ float sm6[];
    ull*   As2 = (ull*)sm6;              // [64][128] ull, As2[i][r]=(a,a)
    float* Bs  = sm6 + 64*128*2;         // [64][128] float
    int t = threadIdx.x;
    int rowBase = blockIdx.x * 128;
    int colBase = blockIdx.y * 128;

    for (int idx4 = t; idx4 < 2048; idx4 += 256) {
        int i = idx4 >> 5, r4 = (idx4 & 31) * 4;
        float4 av = *(const float4*)(g_H2T + (size_t)i*ROWS + rowBase + r4);
        ulonglong2 d0, d1;
        d0.x = pack2(av.x, av.x); d0.y = pack2(av.y, av.y);
        d1.x = pack2(av.z, av.z); d1.y = pack2(av.w, av.w);
        *(ulonglong2*)(As2 + i*128 + r4)     = d0;
        *(ulonglong2*)(As2 + i*128 + r4 + 2) = d1;
        *(float4*)(Bs + i*128 + r4) = *(const float4*)(g_WoT + (size_t)i*HC2 + colBase + r4);
    }
    __syncthreads();

    int tx = t & 15, ty = t >> 4;
    int r0 = ty * 8, c0 = tx * 8;

    ull acc[8][4];
    #pragma unroll
    for (int r = 0; r < 8; r++)
        #pragma unroll
        for (int q = 0; q < 4; q++) acc[r][q] = 0ull;

    #pragma unroll 4
    for (int k = 0; k < 64; k++) {
        ulonglong2 a01 = *(const ulonglong2*)(As2 + k*128 + r0);
        ulonglong2 a23 = *(const ulonglong2*)(As2 + k*128 + r0 + 2);
        ulonglong2 a45 = *(const ulonglong2*)(As2 + k*128 + r0 + 4);
        ulonglong2 a67 = *(const ulonglong2*)(As2 + k*128 + r0 + 6);
        ulonglong2 bv0 = *(const ulonglong2*)(Bs + k*128 + c0);
        ulonglong2 bv1 = *(const ulonglong2*)(Bs + k*128 + c0 + 4);
        ull aq[8] = {a01.x, a01.y, a23.x, a23.y, a45.x, a45.y, a67.x, a67.y};
        ull bq[4] = {bv0.x, bv0.y, bv1.x, bv1.y};
        #pragma unroll
        for (int r = 0; r < 8; r++) {
            #pragma unroll
            for (int q = 0; q < 4; q++)
                acc[r][q] = ffma2(aq[r], bq[q], acc[r][q]);
        }
    }

    float4 bo0 = *(const float4*)(b_out + colBase + c0);
    float4 bo1 = *(const float4*)(b_out + colBase + c0 + 4);
    float bb[8] = {bo0.x, bo0.y, bo0.z, bo0.w, bo1.x, bo1.y, bo1.z, bo1.w};

    #pragma unroll
    for (int r = 0; r < 8; r++) {
        float o[8];
        #pragma unroll
        for (int q = 0; q < 4; q++) {
            float2 v = unpack2(acc[r][q]);
            o[2*q]   = my_tanh(v.x + bb[2*q]);
            o[2*q+1] = my_tanh(v.y + bb[2*q+1]);
        }
        float* dst = out + (size_t)(rowBase + r0 + r) * HC2 + colBase + c0;
        *(float4*)(dst)     = make_float4(o[0], o[1], o[2], o[3]);
        *(float4*)(dst + 4) = make_float4(o[4], o[5], o[6], o[7]);
    }
}

// ---------------- launch -----------------------------------------------------
extern "C" void kernel_launch(void* const* d_in, const int* in_sizes, int n_in,
                              void* d_out, int out_size) {
    const float* z      = (const float*)d_in[0];
    const float* W_in   = (const float*)d_in[1];
    const float* b_in   = (const float*)d_in[2];
    const float* W_out  = (const float*)d_in[3];
    const float* b_out  = (const float*)d_in[4];
    const float* emb    = (const float*)d_in[5];
    const float* wpool  = (const float*)d_in[6];
    const float* bpool  = (const float*)d_in[7];
    float* out = (float*)d_out;

    cudaFuncSetAttribute(k5_nodegemm,
        cudaFuncAttributeMaxDynamicSharedMemorySize, 64*196*4 + 192*64*4);
    cudaFuncSetAttribute(k6_outproj,
        cudaFuncAttributeMaxDynamicSharedMemorySize, 64*128*8 + 64*128*4);

    kA_inproj_transW<<<332, 256>>>(z, W_in, b_in, W_out);
    kB_supports_nodeparams<<<600, 320>>>(emb, wpool, bpool);
    k3_cheb    <<<NN, 320>>>();
    k4_diffuse <<<dim3(NB, 2, 2), 160>>>();
    k5_nodegemm<<<NN, 256, 64*196*4 + 192*64*4>>>();
    k6_outproj <<<dim3(ROWS/128, HC2/128), 256, 64*128*8 + 64*128*4>>>(b_out, out);
}

// round 7
// speedup vs baseline: 1.2986x; 1.2499x over previous
#include <cuda_runtime.h>
#include <math.h>

#define NB 64
#define NN 300
#define NH 64
#define ROWS (NB*NN)        /* 19200 */
#define HC2  4096           /* HC*HC */
#define ATP  384            /* padded pitch for transposed supports */

typedef unsigned long long ull;

// ---------------- scratch (device globals; .bss => zero-initialized) --------
__device__ float g_Hm  [NN*HC2];        // H node-major: [n][b*64+c]
__device__ float g_A   [NN*NN];         // supports                [n][m]
__device__ float g_Atp [NN*ATP];        // supports^T padded       [m][n]
__device__ float g_S2tp[NN*ATP];        // (2A^2-I)^T padded       [m][n]
__device__ float g_Wn  [NN*3*NH*NH];    // per-node weights        [n][(k*64+i)*64+o]
__device__ float g_bn  [NN*NH];         // per-node bias           [n][o]
__device__ float g_XG12[2*NN*HC2];      // diffusion results k=1,2 [k][n][b*64+c]
__device__ float g_H2T [NH*ROWS];       // agc output, transposed  [i][row]
__device__ float g_WoT [NH*HC2];        // W_out^T                 [i][c]

// ---------------- f32x2 helpers (Blackwell packed fp32) ---------------------
__device__ __forceinline__ ull ffma2(ull a, ull b, ull c) {
    ull d;
    asm("fma.rn.f32x2 %0, %1, %2, %3;" : "=l"(d) : "l"(a), "l"(b), "l"(c));
    return d;
}
__device__ __forceinline__ ull pack2(float x, float y) {
    ull d;
    asm("mov.b64 %0, {%1, %2};" : "=l"(d) : "f"(x), "f"(y));
    return d;
}
__device__ __forceinline__ float2 unpack2(ull v) {
    float2 r;
    asm("mov.b64 {%0, %1}, %2;" : "=f"(r.x), "=f"(r.y) : "l"(v));
    return r;
}

// Fast tanh via exp form: 4 FMA-pipe ops + 2 MUFU. x -> +inf clamped to avoid
// inf/inf; x -> -inf gives (0-1)/(0+1) = -1 exactly. Small-x cancellation in
// (e-1) costs <= ~3e-5 elementwise near |x|~1e-3 — far inside the 1e-3 budget.
__device__ __forceinline__ float my_tanh(float x) {
    float xc = fminf(x, 15.f);
    float e = __expf(2.f * xc);
    return __fdividef(e - 1.f, e + 1.f);
}

// ---------------- KA: in-projection (blocks 0..299) + W_out transpose -------
__global__ void __launch_bounds__(256) kA_inproj_transW(
        const float* __restrict__ z,
        const float* __restrict__ W_in,
        const float* __restrict__ b_in,
        const float* __restrict__ W_out) {
    __shared__ float sm[8320];
    int t = threadIdx.x;
    if (blockIdx.x < 300) {
        float* Wt = sm;            // [64][64]  Wt[i][o] = W_in[o][i]
        float* zs = sm + 4096;     // 64 rows of z
        int rowBase = blockIdx.x * 64;
        for (int idx = t; idx < 4096; idx += 256) {
            int o = idx >> 6, i = idx & 63;
            Wt[i*64 + o] = W_in[idx];
        }
        for (int idx4 = t; idx4 < 1024; idx4 += 256)
            *(float4*)(zs + idx4*4) = *(const float4*)(z + (size_t)rowBase*64 + idx4*4);
        __syncthreads();

        int o = t & 63, rg = t >> 6;           // 16 rows, 1 column per thread
        float acc[16];
        float bo = b_in[o];
        #pragma unroll
        for (int r = 0; r < 16; r++) acc[r] = bo;
        const float* zrow = zs + rg*16*64;
        #pragma unroll 4
        for (int i = 0; i < 64; i++) {
            float w = Wt[i*64 + o];
            #pragma unroll
            for (int r = 0; r < 16; r++)
                acc[r] = fmaf(zrow[r*64 + i], w, acc[r]);
        }
        #pragma unroll
        for (int r = 0; r < 16; r++) {
            float h = fmaxf(acc[r], 0.f);
            int row = rowBase + rg*16 + r;
            int b = row / NN, n = row - b*NN;
            g_Hm[(size_t)n*HC2 + b*64 + o] = h;
        }
    } else {
        float* Ts = sm;                        // [128][65] padded
        int cb = (blockIdx.x - 300) * 128;
        for (int idx = t; idx < 8192; idx += 256) {
            int cl = idx >> 6, i = idx & 63;
            Ts[cl*65 + i] = W_out[(size_t)(cb + cl)*64 + i];
        }
        __syncthreads();
        for (int idx = t; idx < 8192; idx += 256) {
            int i = idx >> 7, cl = idx & 127;
            g_WoT[i*HC2 + cb + cl] = Ts[cl*65 + i];
        }
    }
}

// ---------------- KB: supports softmax (0..299), Wn j-tiles (300..395), bias (396)
__global__ void __launch_bounds__(320) kB_supports_nodeparams(
        const float* __restrict__ node_emb,
        const float* __restrict__ wpool,
        const float* __restrict__ bpool) {
    __shared__ float E[NN*10];
    __shared__ float red[512];
    __shared__ float wps[1280];
    int t = threadIdx.x;
    int blk = blockIdx.x;
    if (blk < 300) {
        int n = blk;
        for (int idx = t; idx < NN*10; idx += 320) E[idx] = node_emb[idx];
        if (t < 192) red[320 + t] = -1e30f;
        __syncthreads();

        float v = 0.f;
        if (t < NN) {
            float dot = 0.f;
            #pragma unroll
            for (int d = 0; d < 10; d++) dot = fmaf(E[n*10+d], E[t*10+d], dot);
            v = fmaxf(dot, 0.f);
        }
        red[t] = (t < NN) ? v : -1e30f;
        __syncthreads();
        #pragma unroll
        for (int s = 256; s > 0; s >>= 1) {
            if (t < s) red[t] = fmaxf(red[t], red[t+s]);
            __syncthreads();
        }
        float mx = red[0];
        __syncthreads();

        float ev = (t < NN) ? __expf(v - mx) : 0.f;
        red[t] = ev;
        if (t < 192) red[320 + t] = 0.f;
        __syncthreads();
        #pragma unroll
        for (int s = 256; s > 0; s >>= 1) {
            if (t < s) red[t] += red[t+s];
            __syncthreads();
        }
        float inv = 1.f / red[0];
        if (t < NN) {
            float a = ev * inv;
            g_A  [n*NN + t]  = a;
            g_Atp[t*ATP + n] = a;
        }
    } else if (blk < 396) {
        // Wn[n][j] = sum_d emb[n][d] * wpool[d][j], one j-tile of 128 per block
        int jt = (blk - 300) * 128;
        for (int idx = t; idx < NN*10; idx += 320) E[idx] = node_emb[idx];
        for (int idx = t; idx < 1280; idx += 320) {
            int d = idx >> 7, jj = idx & 127;
            wps[idx] = wpool[(size_t)d*12288 + jt + jj];
        }
        __syncthreads();
        if (t < 256) {
            int jj = t & 127, half = t >> 7;
            const float* w0 = wps + jj;
            for (int n = half; n < NN; n += 2) {
                float acc = 0.f;
                const float* en = E + n*10;
                #pragma unroll
                for (int d = 0; d < 10; d++)
                    acc = fmaf(en[d], w0[d*128], acc);
                g_Wn[(size_t)n*12288 + jt + jj] = acc;
            }
        }
    } else {
        // bias: bn = emb @ bias_pool   (FIX: strided load, 640 > blockDim)
        for (int idx = t; idx < 640; idx += 320) wps[idx] = bpool[idx];
        for (int idx = t; idx < NN*10; idx += 320) E[idx] = node_emb[idx];
        __syncthreads();
        for (int idx = t; idx < NN*64; idx += 320) {
            int n = idx >> 6, o = idx & 63;
            float acc = 0.f;
            #pragma unroll
            for (int d = 0; d < 10; d++)
                acc = fmaf(E[n*10+d], wps[d*64 + o], acc);
            g_bn[idx] = acc;
        }
    }
}

// ---------------- K3: S2 = 2 A A - I, stored transposed+padded -------------
__global__ void __launch_bounds__(320) k3_cheb() {
    __shared__ float arow[NN];
    int t = threadIdx.x, n = blockIdx.x;
    for (int idx = t; idx < NN; idx += 320) arow[idx] = g_A[n*NN + idx];
    __syncthreads();
    if (t < NN) {
        float acc = 0.f;
        #pragma unroll 4
        for (int p = 0; p < NN; p++)
            acc = fmaf(arow[p], g_A[p*NN + t], acc);
        g_S2tp[t*ATP + n] = 2.f*acc - ((t == n) ? 1.f : 0.f);
    }
}

// ---------------- K4: XG_k = S_k @ Hm   ([300,300] @ [300,4096], k=1,2) ----
// 128x128 tiles, m-chunks of 30. A^T is g_Atp/g_S2tp (pad region is zeros).
__global__ void __launch_bounds__(256, 2) k4_gemm() {
    __shared__ float As[30*128];
    __shared__ float Bs[30*128];
    int t = threadIdx.x;
    int rowBase = blockIdx.x * 128;    // node tile (0,128,256)
    int colBase = blockIdx.y * 128;    // (b,c) tile
    const float* At = blockIdx.z ? g_S2tp : g_Atp;
    float* C = g_XG12 + (size_t)blockIdx.z * NN * HC2;

    int tx = t & 15, ty = t >> 4;
    int r0 = ty * 8, c0 = tx * 8;

    ull acc[8][4];
    #pragma unroll
    for (int r = 0; r < 8; r++)
        #pragma unroll
        for (int q = 0; q < 4; q++) acc[r][q] = 0ull;

    for (int m0 = 0; m0 < NN; m0 += 30) {
        __syncthreads();
        for (int idx4 = t; idx4 < 960; idx4 += 256) {
            int j = idx4 >> 5, r4 = (idx4 & 31) * 4;
            *(float4*)(As + j*128 + r4) = *(const float4*)(At + (m0+j)*ATP + rowBase + r4);
            *(float4*)(Bs + j*128 + r4) = *(const float4*)(g_Hm + (size_t)(m0+j)*HC2 + colBase + r4);
        }
        __syncthreads();
        #pragma unroll 3
        for (int j = 0; j < 30; j++) {
            float4 a0 = *(const float4*)(As + j*128 + r0);
            float4 a1 = *(const float4*)(As + j*128 + r0 + 4);
            ulonglong2 bv0 = *(const ulonglong2*)(Bs + j*128 + c0);
            ulonglong2 bv1 = *(const ulonglong2*)(Bs + j*128 + c0 + 4);
            ull bq[4] = {bv0.x, bv0.y, bv1.x, bv1.y};
            float ar[8] = {a0.x, a0.y, a0.z, a0.w, a1.x, a1.y, a1.z, a1.w};
            #pragma unroll
            for (int r = 0; r < 8; r++) {
                ull ad = pack2(ar[r], ar[r]);
                #pragma unroll
                for (int q = 0; q < 4; q++)
                    acc[r][q] = ffma2(ad, bq[q], acc[r][q]);
            }
        }
    }
    #pragma unroll
    for (int r = 0; r < 8; r++) {
        int n = rowBase + r0 + r;
        if (n < NN) {
            float2 v0 = unpack2(acc[r][0]), v1 = unpack2(acc[r][1]);
            float2 v2 = unpack2(acc[r][2]), v3 = unpack2(acc[r][3]);
            float* dst = C + (size_t)n*HC2 + colBase + c0;
            *(float4*)(dst)     = make_float4(v0.x, v0.y, v1.x, v1.y);
            *(float4*)(dst + 4) = make_float4(v2.x, v2.y, v3.x, v3.y);
        }
    }
}

// ---------------- K5: per-node [64,192]@[192,64] + bias -> H2T (transposed) -
__global__ void __launch_bounds__(256) k5_nodegemm() {
    extern __shared__ float sm5[];
    float* XGs = sm5;               // [64 b][196] : 3 planes of 64
    float* Wns = sm5 + 64*196;      // [192][64]
    int n = blockIdx.x, t = threadIdx.x;
    const float* p0 = g_Hm   + (size_t)n*HC2;
    const float* p1 = g_XG12 + (size_t)n*HC2;
    const float* p2 = g_XG12 + (size_t)(NN + n)*HC2;
    const float* wn = g_Wn + (size_t)n*12288;
    for (int idx = t; idx < 4096; idx += 256) {
        int b = idx >> 6, i = idx & 63;
        XGs[b*196 + i]       = p0[idx];
        XGs[b*196 + 64 + i]  = p1[idx];
        XGs[b*196 + 128 + i] = p2[idx];
    }
    for (int idx = t; idx < 12288; idx += 256) Wns[idx] = wn[idx];
    __syncthreads();

    int o4 = (t & 15) * 4;
    int b4 = (t >> 4) * 4;
    ull acc[4][2];
    #pragma unroll
    for (int a = 0; a < 4; a++) { acc[a][0] = 0ull; acc[a][1] = 0ull; }

    const float* x0 = XGs + b4*196;
    #pragma unroll 2
    for (int j = 0; j < 192; j++) {
        ulonglong2 wv = *(const ulonglong2*)(Wns + j*64 + o4);
        #pragma unroll
        for (int bb = 0; bb < 4; bb++) {
            float xv = x0[bb*196 + j];
            ull xd = pack2(xv, xv);
            acc[bb][0] = ffma2(xd, wv.x, acc[bb][0]);
            acc[bb][1] = ffma2(xd, wv.y, acc[bb][1]);
        }
    }
    float4 bias = *(const float4*)(g_bn + n*64 + o4);
    #pragma unroll
    for (int bb = 0; bb < 4; bb++) {
        int row = (b4+bb)*NN + n;
        float2 v0 = unpack2(acc[bb][0]), v1 = unpack2(acc[bb][1]);
        g_H2T[(o4+0)*ROWS + row] = v0.x + bias.x;
        g_H2T[(o4+1)*ROWS + row] = v0.y + bias.y;
        g_H2T[(o4+2)*ROWS + row] = v1.x + bias.z;
        g_H2T[(o4+3)*ROWS + row] = v1.y + bias.w;
    }
}

// ---------------- K6: out = tanh(H2 @ W_out^T + b_out) ---------------------
// 128x128 tile, K=64. Balanced smem traffic: float A-tile, pack in registers.
__global__ void __launch_bounds__(256, 2) k6_outproj(const float* __restrict__ b_out,
                                                     float* __restrict__ out) {
    extern __shared__ float sm6[];
    float* As = sm6;             // [64][128]  As[i][r]
    float* Bs = sm6 + 64*128;    // [64][128]  Bs[i][c]
    int t = threadIdx.x;
    int rowBase = blockIdx.x * 128;
    int colBase = blockIdx.y * 128;

    for (int idx4 = t; idx4 < 2048; idx4 += 256) {
        int i = idx4 >> 5, r4 = (idx4 & 31) * 4;
        *(float4*)(As + i*128 + r4) = *(const float4*)(g_H2T + (size_t)i*ROWS + rowBase + r4);
        *(float4*)(Bs + i*128 + r4) = *(const float4*)(g_WoT + (size_t)i*HC2  + colBase + r4);
    }
    __syncthreads();

    int tx = t & 15, ty = t >> 4;
    int r0 = ty * 8, c0 = tx * 8;

    ull acc[8][4];
    #pragma unroll
    for (int r = 0; r < 8; r++)
        #pragma unroll
        for (int q = 0; q < 4; q++) acc[r][q] = 0ull;

    #pragma unroll 4
    for (int k = 0; k < 64; k++) {
        float4 a0 = *(const float4*)(As + k*128 + r0);
        float4 a1 = *(const float4*)(As + k*128 + r0 + 4);
        ulonglong2 bv0 = *(const ulonglong2*)(Bs + k*128 + c0);
        ulonglong2 bv1 = *(const ulonglong2*)(Bs + k*128 + c0 + 4);
        ull bq[4] = {bv0.x, bv0.y, bv1.x, bv1.y};
        float ar[8] = {a0.x, a0.y, a0.z, a0.w, a1.x, a1.y, a1.z, a1.w};
        #pragma unroll
        for (int r = 0; r < 8; r++) {
            ull ad = pack2(ar[r], ar[r]);
            #pragma unroll
            for (int q = 0; q < 4; q++)
                acc[r][q] = ffma2(ad, bq[q], acc[r][q]);
        }
    }

    float4 bo0 = *(const float4*)(b_out + colBase + c0);
    float4 bo1 = *(const float4*)(b_out + colBase + c0 + 4);
    float bb[8] = {bo0.x, bo0.y, bo0.z, bo0.w, bo1.x, bo1.y, bo1.z, bo1.w};

    #pragma unroll
    for (int r = 0; r < 8; r++) {
        float o[8];
        #pragma unroll
        for (int q = 0; q < 4; q++) {
            float2 v = unpack2(acc[r][q]);
            o[2*q]   = my_tanh(v.x + bb[2*q]);
            o[2*q+1] = my_tanh(v.y + bb[2*q+1]);
        }
        float* dst = out + (size_t)(rowBase + r0 + r) * HC2 + colBase + c0;
        *(float4*)(dst)     = make_float4(o[0], o[1], o[2], o[3]);
        *(float4*)(dst + 4) = make_float4(o[4], o[5], o[6], o[7]);
    }
}

// ---------------- launch -----------------------------------------------------
extern "C" void kernel_launch(void* const* d_in, const int* in_sizes, int n_in,
                              void* d_out, int out_size) {
    const float* z      = (const float*)d_in[0];
    const float* W_in   = (const float*)d_in[1];
    const float* b_in   = (const float*)d_in[2];
    const float* W_out  = (const float*)d_in[3];
    const float* b_out  = (const float*)d_in[4];
    const float* emb    = (const float*)d_in[5];
    const float* wpool  = (const float*)d_in[6];
    const float* bpool  = (const float*)d_in[7];
    float* out = (float*)d_out;

    cudaFuncSetAttribute(k5_nodegemm,
        cudaFuncAttributeMaxDynamicSharedMemorySize, (64*196 + 12288)*4);
    cudaFuncSetAttribute(k6_outproj,
        cudaFuncAttributeMaxDynamicSharedMemorySize, 2*64*128*4);

    kA_inproj_transW<<<332, 256>>>(z, W_in, b_in, W_out);
    kB_supports_nodeparams<<<397, 320>>>(emb, wpool, bpool);
    k3_cheb   <<<NN, 320>>>();
    k4_gemm   <<<dim3(3, 32, 2), 256>>>();
    k5_nodegemm<<<NN, 256, (64*196 + 12288)*4>>>();
    k6_outproj<<<dim3(ROWS/128, HC2/128), 256, 2*64*128*4>>>(b_out, out);
}

// round 9
// speedup vs baseline: 1.9237x; 1.4813x over previous
#include <cuda_runtime.h>
#include <cuda_bf16.h>
#include <math.h>
#include <cstdint>

#define NB 64
#define NN 300
#define NH 64
#define ROWS (NB*NN)        /* 19200 */
#define HC2  4096           /* HC*HC */
#define ATP  384            /* padded pitch for transposed supports */

typedef unsigned long long ull;

// ---------------- scratch (device globals; .bss => zero-initialized) --------
__device__ float g_Hm  [NN*HC2];        // H node-major: [n][b*64+c]
__device__ float g_A   [NN*NN];         // supports                [n][m]
__device__ float g_Atp [NN*ATP];        // supports^T padded       [m][n]
__device__ float g_S2tp[NN*ATP];        // (2A^2-I)^T padded       [m][n]
__device__ float g_Wn  [NN*3*NH*NH];    // per-node weights        [n][(k*64+i)*64+o]
__device__ float g_bn  [NN*NH];         // per-node bias           [n][o]
__device__ float g_XG12[2*NN*HC2];      // diffusion results k=1,2 [k][n][b*64+c]
__device__ __align__(16) __nv_bfloat16 g_H2h[ROWS*NH]; // H2 hi split [row][i]
__device__ __align__(16) __nv_bfloat16 g_H2l[ROWS*NH]; // H2 lo split
__device__ __align__(16) __nv_bfloat16 g_Wh [HC2*NH];  // W_out hi (native [c][i])
__device__ __align__(16) __nv_bfloat16 g_Wl [HC2*NH];  // W_out lo

// ---------------- f32x2 helpers (Blackwell packed fp32) ---------------------
__device__ __forceinline__ ull ffma2(ull a, ull b, ull c) {
    ull d;
    asm("fma.rn.f32x2 %0, %1, %2, %3;" : "=l"(d) : "l"(a), "l"(b), "l"(c));
    return d;
}
__device__ __forceinline__ ull pack2(float x, float y) {
    ull d;
    asm("mov.b64 %0, {%1, %2};" : "=l"(d) : "f"(x), "f"(y));
    return d;
}
__device__ __forceinline__ float2 unpack2(ull v) {
    float2 r;
    asm("mov.b64 {%0, %1}, %2;" : "=f"(r.x), "=f"(r.y) : "l"(v));
    return r;
}

// Fast tanh via exp form (2 MUFU on the SFU pipe, hidden under DRAM stores).
__device__ __forceinline__ float my_tanh(float x) {
    float xc = fminf(x, 15.f);
    float e = __expf(2.f * xc);
    return __fdividef(e - 1.f, e + 1.f);
}

// ---------------- stable-PTX tensor helpers ---------------------------------
__device__ __forceinline__ uint32_t smem_u32(const void* p) {
    uint32_t a;
    asm("{ .reg .u64 t; cvta.to.shared.u64 t, %1; cvt.u32.u64 %0, t; }"
        : "=r"(a) : "l"(p));
    return a;
}
__device__ __forceinline__ void ldm4(uint32_t* r, uint32_t addr) {
    asm volatile("ldmatrix.sync.aligned.m8n8.x4.shared.b16 {%0,%1,%2,%3}, [%4];"
                 : "=r"(r[0]), "=r"(r[1]), "=r"(r[2]), "=r"(r[3]) : "r"(addr));
}
__device__ __forceinline__ void ldm2(uint32_t* r, uint32_t addr) {
    asm volatile("ldmatrix.sync.aligned.m8n8.x2.shared.b16 {%0,%1}, [%2];"
                 : "=r"(r[0]), "=r"(r[1]) : "r"(addr));
}
__device__ __forceinline__ void mma_bf16(float* c, const uint32_t* a,
                                         const uint32_t* b) {
    asm volatile(
        "mma.sync.aligned.m16n8k16.row.col.f32.bf16.bf16.f32 "
        "{%0,%1,%2,%3}, {%4,%5,%6,%7}, {%8,%9}, {%0,%1,%2,%3};"
        : "+f"(c[0]), "+f"(c[1]), "+f"(c[2]), "+f"(c[3])
        : "r"(a[0]), "r"(a[1]), "r"(a[2]), "r"(a[3]), "r"(b[0]), "r"(b[1]));
}
__device__ __forceinline__ void cp16(uint32_t smem, const void* g) {
    asm volatile("cp.async.cg.shared.global [%0], [%1], 16;"
                 :: "r"(smem), "l"(__cvta_generic_to_global(g)));
}
__device__ __forceinline__ void cp_commit() {
    asm volatile("cp.async.commit_group;" ::: "memory");
}
__device__ __forceinline__ void cp_wait0() {
    asm volatile("cp.async.wait_group 0;" ::: "memory");
}

// ---------------- KA: in-projection (blocks 0..299) + W_out bf16 split ------
__global__ void __launch_bounds__(256) kA_inproj_splitW(
        const float* __restrict__ z,
        const float* __restrict__ W_in,
        const float* __restrict__ b_in,
        const float* __restrict__ W_out) {
    __shared__ float sm[8320];
    int t = threadIdx.x;
    if (blockIdx.x < 300) {
        float* Wt = sm;            // [64][64]  Wt[i][o] = W_in[o][i]
        float* zs = sm + 4096;     // 64 rows of z
        int rowBase = blockIdx.x * 64;
        for (int idx = t; idx < 4096; idx += 256) {
            int o = idx >> 6, i = idx & 63;
            Wt[i*64 + o] = W_in[idx];
        }
        for (int idx4 = t; idx4 < 1024; idx4 += 256)
            *(float4*)(zs + idx4*4) = *(const float4*)(z + (size_t)rowBase*64 + idx4*4);
        __syncthreads();

        int o = t & 63, rg = t >> 6;           // 16 rows, 1 column per thread
        float acc[16];
        float bo = b_in[o];
        #pragma unroll
        for (int r = 0; r < 16; r++) acc[r] = bo;
        const float* zrow = zs + rg*16*64;
        #pragma unroll 4
        for (int i = 0; i < 64; i++) {
            float w = Wt[i*64 + o];
            #pragma unroll
            for (int r = 0; r < 16; r++)
                acc[r] = fmaf(zrow[r*64 + i], w, acc[r]);
        }
        #pragma unroll
        for (int r = 0; r < 16; r++) {
            float h = fmaxf(acc[r], 0.f);
            int row = rowBase + rg*16 + r;
            int b = row / NN, n = row - b*NN;
            g_Hm[(size_t)n*HC2 + b*64 + o] = h;
        }
    } else {
        // bf16 hi/lo split of W_out (already n-major [c][i] = mma 'col' layout)
        size_t base = (size_t)(blockIdx.x - 300) * 8192;
        for (int idx = t; idx < 8192; idx += 256) {
            float wv = W_out[base + idx];
            __nv_bfloat16 h = __float2bfloat16(wv);
            __nv_bfloat16 l = __float2bfloat16(wv - __bfloat162float(h));
            g_Wh[base + idx] = h;
            g_Wl[base + idx] = l;
        }
    }
}

// ---------------- KB: supports softmax (0..299), Wn j-tiles (300..395), bias (396)
__global__ void __launch_bounds__(320) kB_supports_nodeparams(
        const float* __restrict__ node_emb,
        const float* __restrict__ wpool,
        const float* __restrict__ bpool) {
    __shared__ float E[NN*10];
    __shared__ float red[512];
    __shared__ float wps[1280];
    int t = threadIdx.x;
    int blk = blockIdx.x;
    if (blk < 300) {
        int n = blk;
        for (int idx = t; idx < NN*10; idx += 320) E[idx] = node_emb[idx];
        if (t < 192) red[320 + t] = -1e30f;
        __syncthreads();

        float v = 0.f;
        if (t < NN) {
            float dot = 0.f;
            #pragma unroll
            for (int d = 0; d < 10; d++) dot = fmaf(E[n*10+d], E[t*10+d], dot);
            v = fmaxf(dot, 0.f);
        }
        red[t] = (t < NN) ? v : -1e30f;
        __syncthreads();
        #pragma unroll
        for (int s = 256; s > 0; s >>= 1) {
            if (t < s) red[t] = fmaxf(red[t], red[t+s]);
            __syncthreads();
        }
        float mx = red[0];
        __syncthreads();

        float ev = (t < NN) ? __expf(v - mx) : 0.f;
        red[t] = ev;
        if (t < 192) red[320 + t] = 0.f;
        __syncthreads();
        #pragma unroll
        for (int s = 256; s > 0; s >>= 1) {
            if (t < s) red[t] += red[t+s];
            __syncthreads();
        }
        float inv = 1.f / red[0];
        if (t < NN) {
            float a = ev * inv;
            g_A  [n*NN + t]  = a;
            g_Atp[t*ATP + n] = a;
        }
    } else if (blk < 396) {
        int jt = (blk - 300) * 128;
        for (int idx = t; idx < NN*10; idx += 320) E[idx] = node_emb[idx];
        for (int idx = t; idx < 1280; idx += 320) {
            int d = idx >> 7, jj = idx & 127;
            wps[idx] = wpool[(size_t)d*12288 + jt + jj];
        }
        __syncthreads();
        if (t < 256) {
            int jj = t & 127, half = t >> 7;
            const float* w0 = wps + jj;
            for (int n = half; n < NN; n += 2) {
                float acc = 0.f;
                const float* en = E + n*10;
                #pragma unroll
                for (int d = 0; d < 10; d++)
                    acc = fmaf(en[d], w0[d*128], acc);
                g_Wn[(size_t)n*12288 + jt + jj] = acc;
            }
        }
    } else {
        for (int idx = t; idx < 640; idx += 320) wps[idx] = bpool[idx];
        for (int idx = t; idx < NN*10; idx += 320) E[idx] = node_emb[idx];
        __syncthreads();
        for (int idx = t; idx < NN*64; idx += 320) {
            int n = idx >> 6, o = idx & 63;
            float acc = 0.f;
            #pragma unroll
            for (int d = 0; d < 10; d++)
                acc = fmaf(E[n*10+d], wps[d*64 + o], acc);
            g_bn[idx] = acc;
        }
    }
}

// ---------------- K3: S2 = 2 A A - I, stored transposed+padded -------------
__global__ void __launch_bounds__(320) k3_cheb() {
    __shared__ float arow[NN];
    int t = threadIdx.x, n = blockIdx.x;
    for (int idx = t; idx < NN; idx += 320) arow[idx] = g_A[n*NN + idx];
    __syncthreads();
    if (t < NN) {
        float acc = 0.f;
        #pragma unroll 4
        for (int p = 0; p < NN; p++)
            acc = fmaf(arow[p], g_A[p*NN + t], acc);
        g_S2tp[t*ATP + n] = 2.f*acc - ((t == n) ? 1.f : 0.f);
    }
}

// ---------------- K4: XG_k = S_k @ Hm   ([300,300] @ [300,4096], k=1,2) ----
__global__ void __launch_bounds__(256, 2) k4_gemm() {
    __shared__ float As[30*128];
    __shared__ float Bs[30*128];
    int t = threadIdx.x;
    int rowBase = blockIdx.x * 128;
    int colBase = blockIdx.y * 128;
    const float* At = blockIdx.z ? g_S2tp : g_Atp;
    float* C = g_XG12 + (size_t)blockIdx.z * NN * HC2;

    int tx = t & 15, ty = t >> 4;
    int r0 = ty * 8, c0 = tx * 8;

    ull acc[8][4];
    #pragma unroll
    for (int r = 0; r < 8; r++)
        #pragma unroll
        for (int q = 0; q < 4; q++) acc[r][q] = 0ull;

    for (int m0 = 0; m0 < NN; m0 += 30) {
        __syncthreads();
        for (int idx4 = t; idx4 < 960; idx4 += 256) {
            int j = idx4 >> 5, r4 = (idx4 & 31) * 4;
            *(float4*)(As + j*128 + r4) = *(const float4*)(At + (m0+j)*ATP + rowBase + r4);
            *(float4*)(Bs + j*128 + r4) = *(const float4*)(g_Hm + (size_t)(m0+j)*HC2 + colBase + r4);
        }
        __syncthreads();
        #pragma unroll 3
        for (int j = 0; j < 30; j++) {
            float4 a0 = *(const float4*)(As + j*128 + r0);
            float4 a1 = *(const float4*)(As + j*128 + r0 + 4);
            ulonglong2 bv0 = *(const ulonglong2*)(Bs + j*128 + c0);
            ulonglong2 bv1 = *(const ulonglong2*)(Bs + j*128 + c0 + 4);
            ull bq[4] = {bv0.x, bv0.y, bv1.x, bv1.y};
            float ar[8] = {a0.x, a0.y, a0.z, a0.w, a1.x, a1.y, a1.z, a1.w};
            #pragma unroll
            for (int r = 0; r < 8; r++) {
                ull ad = pack2(ar[r], ar[r]);
                #pragma unroll
                for (int q = 0; q < 4; q++)
                    acc[r][q] = ffma2(ad, bq[q], acc[r][q]);
            }
        }
    }
    #pragma unroll
    for (int r = 0; r < 8; r++) {
        int n = rowBase + r0 + r;
        if (n < NN) {
            float2 v0 = unpack2(acc[r][0]), v1 = unpack2(acc[r][1]);
            float2 v2 = unpack2(acc[r][2]), v3 = unpack2(acc[r][3]);
            float* dst = C + (size_t)n*HC2 + colBase + c0;
            *(float4*)(dst)     = make_float4(v0.x, v0.y, v1.x, v1.y);
            *(float4*)(dst + 4) = make_float4(v2.x, v2.y, v3.x, v3.y);
        }
    }
}

// ---------------- K5: per-node [64,192]@[192,64] + bias -> H2 bf16 splits ---
__global__ void __launch_bounds__(256) k5_nodegemm() {
    extern __shared__ float sm5[];
    float* XGs = sm5;               // [64 b][196] : 3 planes of 64
    float* Wns = sm5 + 64*196;      // [192][64]
    int n = blockIdx.x, t = threadIdx.x;
    const float* p0 = g_Hm   + (size_t)n*HC2;
    const float* p1 = g_XG12 + (size_t)n*HC2;
    const float* p2 = g_XG12 + (size_t)(NN + n)*HC2;
    const float* wn = g_Wn + (size_t)n*12288;
    for (int idx = t; idx < 4096; idx += 256) {
        int b = idx >> 6, i = idx & 63;
        XGs[b*196 + i]       = p0[idx];
        XGs[b*196 + 64 + i]  = p1[idx];
        XGs[b*196 + 128 + i] = p2[idx];
    }
    for (int idx = t; idx < 12288; idx += 256) Wns[idx] = wn[idx];
    __syncthreads();

    int o4 = (t & 15) * 4;
    int b4 = (t >> 4) * 4;
    ull acc[4][2];
    #pragma unroll
    for (int a = 0; a < 4; a++) { acc[a][0] = 0ull; acc[a][1] = 0ull; }

    const float* x0 = XGs + b4*196;
    #pragma unroll 2
    for (int j = 0; j < 192; j++) {
        ulonglong2 wv = *(const ulonglong2*)(Wns + j*64 + o4);
        #pragma unroll
        for (int bb = 0; bb < 4; bb++) {
            float xv = x0[bb*196 + j];
            ull xd = pack2(xv, xv);
            acc[bb][0] = ffma2(xd, wv.x, acc[bb][0]);
            acc[bb][1] = ffma2(xd, wv.y, acc[bb][1]);
        }
    }
    float4 bias = *(const float4*)(g_bn + n*64 + o4);
    #pragma unroll
    for (int bb = 0; bb < 4; bb++) {
        int row = (b4+bb)*NN + n;
        float2 v0 = unpack2(acc[bb][0]), v1 = unpack2(acc[bb][1]);
        float o0 = v0.x + bias.x, o1 = v0.y + bias.y;
        float o2 = v1.x + bias.z, o3 = v1.y + bias.w;
        __nv_bfloat16 h0 = __float2bfloat16(o0), h1 = __float2bfloat16(o1);
        __nv_bfloat16 h2 = __float2bfloat16(o2), h3 = __float2bfloat16(o3);
        __nv_bfloat16 l0 = __float2bfloat16(o0 - __bfloat162float(h0));
        __nv_bfloat16 l1 = __float2bfloat16(o1 - __bfloat162float(h1));
        __nv_bfloat16 l2 = __float2bfloat16(o2 - __bfloat162float(h2));
        __nv_bfloat16 l3 = __float2bfloat16(o3 - __bfloat162float(h3));
        size_t base = (size_t)row*64 + o4;
        *(__nv_bfloat162*)(g_H2h + base)     = __halves2bfloat162(h0, h1);
        *(__nv_bfloat162*)(g_H2h + base + 2) = __halves2bfloat162(h2, h3);
        *(__nv_bfloat162*)(g_H2l + base)     = __halves2bfloat162(l0, l1);
        *(__nv_bfloat162*)(g_H2l + base + 2) = __halves2bfloat162(l2, l3);
    }
}

// ---------------- K6: out = tanh(H2 @ W_out^T + b_out) via mma.sync bf16 ----
// Block: 128 rows x 16 col-tiles of 128. 8 warps of 64x32 warp tiles.
// A (hi/lo) in smem once; B (hi/lo) double-buffered via cp.async.
// D = Ah*Bh + Ah*Bl + Al*Bh  (fp32 accumulate).
#define APITCH 72                      /* halves per padded row */
#define ASPLIT 18432                   /* 128*72*2 bytes per split */
__global__ void __launch_bounds__(256, 2) k6_mma(const float* __restrict__ b_out,
                                                 float* __restrict__ out) {
    extern __shared__ char smem[];
    uint32_t sb = smem_u32(smem);
    const int OFF_B = 2 * ASPLIT;      // B: stage*36864 + split*18432
    int t = threadIdx.x, w = t >> 5, lane = t & 31;
    int rowBase = blockIdx.x * 128;
    int colSec  = blockIdx.y * 2048;
    int wm = (w & 1) * 64, wn = (w >> 1) * 32;

    // ---- load A hi/lo (rows padded to 72 halves) ----
    for (int idx = t; idx < 2048; idx += 256) {
        int arr = idx >> 10, rem = idx & 1023;
        int r = rem >> 3, cb = rem & 7;            // row, 16B-chunk
        const __nv_bfloat16* src = (arr ? g_H2l : g_H2h)
                                 + (size_t)(rowBase + r)*64 + cb*8;
        cp16(sb + arr*ASPLIT + r*144 + cb*16, src);
    }
    // ---- B stage 0 ----
    for (int idx = t; idx < 2048; idx += 256) {
        int arr = idx >> 10, rem = idx & 1023;
        int r = rem >> 3, cb = rem & 7;
        const __nv_bfloat16* src = (arr ? g_Wl : g_Wh)
                                 + (size_t)(colSec + r)*64 + cb*8;
        cp16(sb + OFF_B + arr*ASPLIT + r*144 + cb*16, src);
    }
    cp_commit();
    cp_wait0();
    __syncthreads();

    // ---- per-lane ldmatrix address components ----
    int g4 = lane >> 3;                            // 0..3 (x4 groups)
    int rsel = (g4 & 1) * 8 + (lane & 7);
    int kselA = (g4 >> 1) * 8;
    int g2 = (lane >> 3) & 1;                      // x2 groups
    int nsel = lane & 7;
    int kselB = g2 * 8;

    uint32_t aBase[4][2];                          // [mt][hi/lo]
    #pragma unroll
    for (int mt = 0; mt < 4; mt++) {
        uint32_t off = (uint32_t)((wm + mt*16 + rsel)*144 + kselA*2);
        aBase[mt][0] = sb + off;
        aBase[mt][1] = sb + ASPLIT + off;
    }
    uint32_t bOff[4];
    #pragma unroll
    for (int nt = 0; nt < 4; nt++)
        bOff[nt] = (uint32_t)((wn + nt*8 + nsel)*144 + kselB*2);

    for (int it = 0; it < 16; it++) {
        int stage = it & 1;
        // prefetch next B into other stage (overlaps compute below)
        if (it + 1 < 16) {
            int nc = colSec + (it + 1) * 128;
            for (int idx = t; idx < 2048; idx += 256) {
                int arr = idx >> 10, rem = idx & 1023;
                int r = rem >> 3, cb = rem & 7;
                const __nv_bfloat16* src = (arr ? g_Wl : g_Wh)
                                         + (size_t)(nc + r)*64 + cb*8;
                cp16(sb + OFF_B + (stage^1)*2*ASPLIT + arr*ASPLIT + r*144 + cb*16, src);
            }
        }
        cp_commit();

        // ---- compute from current stage ----
        float acc[4][4][4];
        #pragma unroll
        for (int mt = 0; mt < 4; mt++)
            #pragma unroll
            for (int nt = 0; nt < 4; nt++)
                #pragma unroll
                for (int q = 0; q < 4; q++) acc[mt][nt][q] = 0.f;

        uint32_t bStage = sb + OFF_B + stage*2*ASPLIT;
        #pragma unroll
        for (int ks = 0; ks < 4; ks++) {
            uint32_t ah[4][4], al[4][4], bh[4][2], bl[4][2];
            #pragma unroll
            for (int mt = 0; mt < 4; mt++) {
                ldm4(ah[mt], aBase[mt][0] + ks*32);
                ldm4(al[mt], aBase[mt][1] + ks*32);
            }
            #pragma unroll
            for (int nt = 0; nt < 4; nt++) {
                ldm2(bh[nt], bStage + bOff[nt] + ks*32);
                ldm2(bl[nt], bStage + ASPLIT + bOff[nt] + ks*32);
            }
            #pragma unroll
            for (int mt = 0; mt < 4; mt++)
                #pragma unroll
                for (int nt = 0; nt < 4; nt++) {
                    mma_bf16(acc[mt][nt], ah[mt], bh[nt]);
                    mma_bf16(acc[mt][nt], ah[mt], bl[nt]);
                    mma_bf16(acc[mt][nt], al[mt], bh[nt]);
                }
        }

        // ---- epilogue: bias + tanh + store ----
        int colT = colSec + it*128 + wn;
        #pragma unroll
        for (int nt = 0; nt < 4; nt++) {
            int col = colT + nt*8 + (lane & 3)*2;
            float2 bv = *(const float2*)(b_out + col);
            #pragma unroll
            for (int mt = 0; mt < 4; mt++) {
                int row0 = rowBase + wm + mt*16 + (lane >> 2);
                float2 o0, o1;
                o0.x = my_tanh(acc[mt][nt][0] + bv.x);
                o0.y = my_tanh(acc[mt][nt][1] + bv.y);
                o1.x = my_tanh(acc[mt][nt][2] + bv.x);
                o1.y = my_tanh(acc[mt][nt][3] + bv.y);
                *(float2*)(out + (size_t)row0*HC2 + col)       = o0;
                *(float2*)(out + (size_t)(row0+8)*HC2 + col)   = o1;
            }
        }

        cp_wait0();
        __syncthreads();
    }
}

// ---------------- launch -----------------------------------------------------
extern "C" void kernel_launch(void* const* d_in, const int* in_sizes, int n_in,
                              void* d_out, int out_size) {
    const float* z      = (const float*)d_in[0];
    const float* W_in   = (const float*)d_in[1];
    const float* b_in   = (const float*)d_in[2];
    const float* W_out  = (const float*)d_in[3];
    const float* b_out  = (const float*)d_in[4];
    const float* emb    = (const float*)d_in[5];
    const float* wpool  = (const float*)d_in[6];
    const float* bpool  = (const float*)d_in[7];
    float* out = (float*)d_out;

    const int SM6 = 6 * ASPLIT;   // A(2) + B(2 stages x 2 splits) = 110592 B
    cudaFuncSetAttribute(k5_nodegemm,
        cudaFuncAttributeMaxDynamicSharedMemorySize, (64*196 + 12288)*4);
    cudaFuncSetAttribute(k6_mma,
        cudaFuncAttributeMaxDynamicSharedMemorySize, SM6);

    kA_inproj_splitW<<<332, 256>>>(z, W_in, b_in, W_out);
    kB_supports_nodeparams<<<397, 320>>>(emb, wpool, bpool);
    k3_cheb   <<<NN, 320>>>();
    k4_gemm   <<<dim3(3, 32, 2), 256>>>();
    k5_nodegemm<<<NN, 256, (64*196 + 12288)*4>>>();
    k6_mma    <<<dim3(150, 2), 256, SM6>>>(b_out, out);
}

// round 10
// speedup vs baseline: 2.2040x; 1.1457x over previous
#include <cuda_runtime.h>
#include <cuda_bf16.h>
#include <math.h>
#include <cstdint>

#define NB 64
#define NN 300
#define NH 64
#define ROWS (NB*NN)        /* 19200 */
#define HC2  4096           /* HC*HC */
#define SP   320            /* padded contraction dim for S / H^T */

typedef unsigned long long ull;

// ---------------- scratch (device globals; .bss => zero-initialized) --------
__device__ float g_Hm  [NN*HC2];        // H node-major: [n][b*64+c]
__device__ float g_A   [NN*NN];         // supports fp32           [n][m]
__device__ float g_Wn  [NN*3*NH*NH];    // per-node weights        [n][(k*64+i)*64+o]
__device__ float g_bn  [NN*NH];         // per-node bias           [n][o]
__device__ float g_XG12[2*NN*HC2];      // diffusion results k=1,2 [k][n][b*64+c]
__device__ __align__(16) __nv_bfloat16 g_H2h[ROWS*NH]; // H2 hi split [row][i]
__device__ __align__(16) __nv_bfloat16 g_H2l[ROWS*NH]; // H2 lo split
__device__ __align__(16) __nv_bfloat16 g_Wh [HC2*NH];  // W_out hi (native [c][i])
__device__ __align__(16) __nv_bfloat16 g_Wl [HC2*NH];  // W_out lo
__device__ __align__(16) __nv_bfloat16 g_Sh [2*384*SP]; // S_k hi [k][n][m] rowmaj
__device__ __align__(16) __nv_bfloat16 g_Sl [2*384*SP]; // S_k lo
__device__ __align__(16) __nv_bfloat16 g_HTh[HC2*SP];   // H^T hi [col][m]
__device__ __align__(16) __nv_bfloat16 g_HTl[HC2*SP];   // H^T lo

// ---------------- f32x2 helpers ----------------------------------------------
__device__ __forceinline__ ull ffma2(ull a, ull b, ull c) {
    ull d;
    asm("fma.rn.f32x2 %0, %1, %2, %3;" : "=l"(d) : "l"(a), "l"(b), "l"(c));
    return d;
}
__device__ __forceinline__ ull pack2(float x, float y) {
    ull d;
    asm("mov.b64 %0, {%1, %2};" : "=l"(d) : "f"(x), "f"(y));
    return d;
}
__device__ __forceinline__ float2 unpack2(ull v) {
    float2 r;
    asm("mov.b64 {%0, %1}, %2;" : "=f"(r.x), "=f"(r.y) : "l"(v));
    return r;
}

__device__ __forceinline__ float my_tanh(float x) {
    float xc = fminf(x, 15.f);
    float e = __expf(2.f * xc);
    return __fdividef(e - 1.f, e + 1.f);
}

// ---------------- stable-PTX tensor helpers ---------------------------------
__device__ __forceinline__ uint32_t smem_u32(const void* p) {
    uint32_t a;
    asm("{ .reg .u64 t; cvta.to.shared.u64 t, %1; cvt.u32.u64 %0, t; }"
        : "=r"(a) : "l"(p));
    return a;
}
__device__ __forceinline__ void ldm4(uint32_t* r, uint32_t addr) {
    asm volatile("ldmatrix.sync.aligned.m8n8.x4.shared.b16 {%0,%1,%2,%3}, [%4];"
                 : "=r"(r[0]), "=r"(r[1]), "=r"(r[2]), "=r"(r[3]) : "r"(addr));
}
__device__ __forceinline__ void ldm2(uint32_t* r, uint32_t addr) {
    asm volatile("ldmatrix.sync.aligned.m8n8.x2.shared.b16 {%0,%1}, [%2];"
                 : "=r"(r[0]), "=r"(r[1]) : "r"(addr));
}
__device__ __forceinline__ void mma_bf16(float* c, const uint32_t* a,
                                         const uint32_t* b) {
    asm volatile(
        "mma.sync.aligned.m16n8k16.row.col.f32.bf16.bf16.f32 "
        "{%0,%1,%2,%3}, {%4,%5,%6,%7}, {%8,%9}, {%0,%1,%2,%3};"
        : "+f"(c[0]), "+f"(c[1]), "+f"(c[2]), "+f"(c[3])
        : "r"(a[0]), "r"(a[1]), "r"(a[2]), "r"(a[3]), "r"(b[0]), "r"(b[1]));
}
__device__ __forceinline__ void cp16(uint32_t smem, const void* g) {
    asm volatile("cp.async.cg.shared.global [%0], [%1], 16;"
                 :: "r"(smem), "l"(__cvta_generic_to_global(g)));
}
__device__ __forceinline__ void cp_commit() {
    asm volatile("cp.async.commit_group;" ::: "memory");
}
__device__ __forceinline__ void cp_wait0() {
    asm volatile("cp.async.wait_group 0;" ::: "memory");
}
__device__ __forceinline__ void cp_wait1() {
    asm volatile("cp.async.wait_group 1;" ::: "memory");
}
__device__ __forceinline__ void bf16_split(float v, __nv_bfloat16& h,
                                           __nv_bfloat16& l) {
    h = __float2bfloat16(v);
    l = __float2bfloat16(v - __bfloat162float(h));
}

// ---------------- KA: in-projection (blocks 0..299) + W_out bf16 split ------
__global__ void __launch_bounds__(256) kA_inproj_splitW(
        const float* __restrict__ z,
        const float* __restrict__ W_in,
        const float* __restrict__ b_in,
        const float* __restrict__ W_out) {
    __shared__ float sm[8320];
    int t = threadIdx.x;
    if (blockIdx.x < 300) {
        float* Wt = sm;            // [64][64]  Wt[i][o] = W_in[o][i]
        float* zs = sm + 4096;     // 64 rows of z
        int rowBase = blockIdx.x * 64;
        for (int idx = t; idx < 4096; idx += 256) {
            int o = idx >> 6, i = idx & 63;
            Wt[i*64 + o] = W_in[idx];
        }
        for (int idx4 = t; idx4 < 1024; idx4 += 256)
            *(float4*)(zs + idx4*4) = *(const float4*)(z + (size_t)rowBase*64 + idx4*4);
        __syncthreads();

        int o = t & 63, rg = t >> 6;
        float acc[16];
        float bo = b_in[o];
        #pragma unroll
        for (int r = 0; r < 16; r++) acc[r] = bo;
        const float* zrow = zs + rg*16*64;
        #pragma unroll 4
        for (int i = 0; i < 64; i++) {
            float w = Wt[i*64 + o];
            #pragma unroll
            for (int r = 0; r < 16; r++)
                acc[r] = fmaf(zrow[r*64 + i], w, acc[r]);
        }
        #pragma unroll
        for (int r = 0; r < 16; r++) {
            float h = fmaxf(acc[r], 0.f);
            int row = rowBase + rg*16 + r;
            int b = row / NN, n = row - b*NN;
            g_Hm[(size_t)n*HC2 + b*64 + o] = h;
        }
    } else {
        size_t base = (size_t)(blockIdx.x - 300) * 8192;
        for (int idx = t; idx < 8192; idx += 256) {
            float wv = W_out[base + idx];
            __nv_bfloat16 h, l;
            bf16_split(wv, h, l);
            g_Wh[base + idx] = h;
            g_Wl[base + idx] = l;
        }
    }
}

// ---------------- KB: supports (0..299), Wn (300..395), bias (396),
//                      H transpose+split (397..460) -------------------------
__global__ void __launch_bounds__(320) kB_supports_nodeparams(
        const float* __restrict__ node_emb,
        const float* __restrict__ wpool,
        const float* __restrict__ bpool) {
    __shared__ float E[NN*10];
    __shared__ float red[512];
    __shared__ float wps[1280];
    __shared__ float Ts[64*65];
    int t = threadIdx.x;
    int blk = blockIdx.x;
    if (blk < 300) {
        int n = blk;
        for (int idx = t; idx < NN*10; idx += 320) E[idx] = node_emb[idx];
        if (t < 192) red[320 + t] = -1e30f;
        __syncthreads();

        float v = 0.f;
        if (t < NN) {
            float dot = 0.f;
            #pragma unroll
            for (int d = 0; d < 10; d++) dot = fmaf(E[n*10+d], E[t*10+d], dot);
            v = fmaxf(dot, 0.f);
        }
        red[t] = (t < NN) ? v : -1e30f;
        __syncthreads();
        #pragma unroll
        for (int s = 256; s > 0; s >>= 1) {
            if (t < s) red[t] = fmaxf(red[t], red[t+s]);
            __syncthreads();
        }
        float mx = red[0];
        __syncthreads();

        float ev = (t < NN) ? __expf(v - mx) : 0.f;
        red[t] = ev;
        if (t < 192) red[320 + t] = 0.f;
        __syncthreads();
        #pragma unroll
        for (int s = 256; s > 0; s >>= 1) {
            if (t < s) red[t] += red[t+s];
            __syncthreads();
        }
        float inv = 1.f / red[0];
        if (t < NN) {
            float a = ev * inv;
            g_A[n*NN + t] = a;
            __nv_bfloat16 h, l;
            bf16_split(a, h, l);
            g_Sh[n*SP + t] = h;          // plane 0 = supports, row-major
            g_Sl[n*SP + t] = l;
        }
    } else if (blk < 396) {
        int jt = (blk - 300) * 128;
        for (int idx = t; idx < NN*10; idx += 320) E[idx] = node_emb[idx];
        for (int idx = t; idx < 1280; idx += 320) {
            int d = idx >> 7, jj = idx & 127;
            wps[idx] = wpool[(size_t)d*12288 + jt + jj];
        }
        __syncthreads();
        if (t < 256) {
            int jj = t & 127, half = t >> 7;
            const float* w0 = wps + jj;
            for (int n = half; n < NN; n += 2) {
                float acc = 0.f;
                const float* en = E + n*10;
                #pragma unroll
                for (int d = 0; d < 10; d++)
                    acc = fmaf(en[d], w0[d*128], acc);
                g_Wn[(size_t)n*12288 + jt + jj] = acc;
            }
        }
    } else if (blk == 396) {
        for (int idx = t; idx < 640; idx += 320) wps[idx] = bpool[idx];
        for (int idx = t; idx < NN*10; idx += 320) E[idx] = node_emb[idx];
        __syncthreads();
        for (int idx = t; idx < NN*64; idx += 320) {
            int n = idx >> 6, o = idx & 63;
            float acc = 0.f;
            #pragma unroll
            for (int d = 0; d < 10; d++)
                acc = fmaf(E[n*10+d], wps[d*64 + o], acc);
            g_bn[idx] = acc;
        }
    } else {
        // transpose + bf16-split 64 columns of Hm -> HT[col][m]
        int cb = (blk - 397) * 64;
        for (int m0 = 0; m0 < NN; m0 += 64) {
            int mc = min(64, NN - m0);
            __syncthreads();
            for (int idx = t; idx < 4096; idx += 320) {
                int mm = idx >> 6, c = idx & 63;
                if (mm < mc)
                    Ts[mm*65 + c] = g_Hm[(size_t)(m0+mm)*HC2 + cb + c];
            }
            __syncthreads();
            for (int idx = t; idx < 4096; idx += 320) {
                int c = idx >> 6, mm = idx & 63;
                if (mm < mc) {
                    __nv_bfloat16 h, l;
                    bf16_split(Ts[mm*65 + c], h, l);
                    g_HTh[(size_t)(cb+c)*SP + m0 + mm] = h;
                    g_HTl[(size_t)(cb+c)*SP + m0 + mm] = l;
                }
            }
        }
    }
}

// ---------------- K3: S2 = 2 A A - I, bf16 split row-major (plane 1) -------
__global__ void __launch_bounds__(320) k3_cheb() {
    __shared__ float arow[NN];
    int t = threadIdx.x, n = blockIdx.x;
    for (int idx = t; idx < NN; idx += 320) arow[idx] = g_A[n*NN + idx];
    __syncthreads();
    if (t < NN) {
        float acc = 0.f;
        #pragma unroll 4
        for (int p = 0; p < NN; p++)
            acc = fmaf(arow[p], g_A[p*NN + t], acc);
        float v = 2.f*acc - ((t == n) ? 1.f : 0.f);
        __nv_bfloat16 h, l;
        bf16_split(v, h, l);
        g_Sh[384*SP + n*SP + t] = h;
        g_Sl[384*SP + n*SP + t] = l;
    }
}

// ---------------- K4: XG_k = S_k @ Hm via mma.sync bf16 split ---------------
// C[n][col]: A = S_k[n][m] (row), B = H^T[col][m] (col). K=320 in 10 chunks
// of 32, cp.async double-buffered. 128x128 block tile, 8 warps of 64x32.
__global__ void __launch_bounds__(256, 2) k4_mma() {
    extern __shared__ char smem[];
    uint32_t sb = smem_u32(smem);
    // A: stage*20480 + split*10240 + r*80 + b ; B: +40960 same
    int t = threadIdx.x, w = t >> 5, lane = t & 31;
    int rowBase = blockIdx.x * 128;
    int colBase = blockIdx.y * 128;
    int kz = blockIdx.z;
    const __nv_bfloat16* Sh = g_Sh + (size_t)kz*384*SP;
    const __nv_bfloat16* Sl = g_Sl + (size_t)kz*384*SP;
    float* C = g_XG12 + (size_t)kz * NN * HC2;
    int wm = (w & 1) * 64, wn = (w >> 1) * 32;

    int g4 = lane >> 3;
    int rsel = (g4 & 1) * 8 + (lane & 7);
    int kselA = (g4 >> 1) * 8;
    int nsel = lane & 7;
    int kselB = ((lane >> 3) & 1) * 8;
    uint32_t aOff[4], bOff[4];
    #pragma unroll
    for (int mt = 0; mt < 4; mt++)
        aOff[mt] = (uint32_t)((wm + mt*16 + rsel)*80 + kselA*2);
    #pragma unroll
    for (int nt = 0; nt < 4; nt++)
        bOff[nt] = (uint32_t)((wn + nt*8 + nsel)*80 + kselB*2);

    float acc[4][4][4];
    #pragma unroll
    for (int mt = 0; mt < 4; mt++)
        #pragma unroll
        for (int nt = 0; nt < 4; nt++)
            #pragma unroll
            for (int q = 0; q < 4; q++) acc[mt][nt][q] = 0.f;

    const int NC = 10;                 // 320 / 32
    // prologue: chunk 0 into stage 0
    for (int idx = t; idx < 1024; idx += 256) {
        int arr = idx >> 9, rem = idx & 511;
        int r = rem >> 2, c4 = rem & 3;
        cp16(sb + arr*10240 + r*80 + c4*16,
             (arr ? Sl : Sh) + (size_t)(rowBase + r)*SP + c4*8);
        cp16(sb + 40960 + arr*10240 + r*80 + c4*16,
             (arr ? g_HTl : g_HTh) + (size_t)(colBase + r)*SP + c4*8);
    }
    cp_commit();

    for (int c = 0; c < NC; c++) {
        int stage = c & 1;
        if (c + 1 < NC) {
            int m0 = (c + 1) * 32, ns = (c + 1) & 1;
            for (int idx = t; idx < 1024; idx += 256) {
                int arr = idx >> 9, rem = idx & 511;
                int r = rem >> 2, c4 = rem & 3;
                cp16(sb + ns*20480 + arr*10240 + r*80 + c4*16,
                     (arr ? Sl : Sh) + (size_t)(rowBase + r)*SP + m0 + c4*8);
                cp16(sb + 40960 + ns*20480 + arr*10240 + r*80 + c4*16,
                     (arr ? g_HTl : g_HTh) + (size_t)(colBase + r)*SP + m0 + c4*8);
            }
            cp_commit();
            cp_wait1();
        } else {
            cp_wait0();
        }
        __syncthreads();

        uint32_t sA = sb + stage*20480;
        uint32_t sB = sb + 40960 + stage*20480;
        #pragma unroll
        for (int ks = 0; ks < 2; ks++) {
            uint32_t ah[4][4], al[4][4], bh[4][2], bl[4][2];
            #pragma unroll
            for (int mt = 0; mt < 4; mt++) {
                ldm4(ah[mt], sA + aOff[mt] + ks*32);
                ldm4(al[mt], sA + 10240 + aOff[mt] + ks*32);
            }
            #pragma unroll
            for (int nt = 0; nt < 4; nt++) {
                ldm2(bh[nt], sB + bOff[nt] + ks*32);
                ldm2(bl[nt], sB + 10240 + bOff[nt] + ks*32);
            }
            #pragma unroll
            for (int mt = 0; mt < 4; mt++)
                #pragma unroll
                for (int nt = 0; nt < 4; nt++) {
                    mma_bf16(acc[mt][nt], ah[mt], bh[nt]);
                    mma_bf16(acc[mt][nt], ah[mt], bl[nt]);
                    mma_bf16(acc[mt][nt], al[mt], bh[nt]);
                }
        }
        __syncthreads();
    }

    // epilogue: store fp32, guard n < 300
    #pragma unroll
    for (int nt = 0; nt < 4; nt++) {
        int col = colBase + wn + nt*8 + (lane & 3)*2;
        #pragma unroll
        for (int mt = 0; mt < 4; mt++) {
            int n0 = rowBase + wm + mt*16 + (lane >> 2);
            if (n0 < NN)
                *(float2*)(C + (size_t)n0*HC2 + col) =
                    make_float2(acc[mt][nt][0], acc[mt][nt][1]);
            if (n0 + 8 < NN)
                *(float2*)(C + (size_t)(n0+8)*HC2 + col) =
                    make_float2(acc[mt][nt][2], acc[mt][nt][3]);
        }
    }
}

// ---------------- K5: per-node [64,192]@[192,64] + bias -> H2 bf16 splits ---
__global__ void __launch_bounds__(256) k5_nodegemm() {
    extern __shared__ float sm5[];
    float* XGs = sm5;               // [64 b][196] : 3 planes of 64
    float* Wns = sm5 + 64*196;      // [192][64]
    int n = blockIdx.x, t = threadIdx.x;
    const float* p0 = g_Hm   + (size_t)n*HC2;
    const float* p1 = g_XG12 + (size_t)n*HC2;
    const float* p2 = g_XG12 + (size_t)(NN + n)*HC2;
    const float* wn = g_Wn + (size_t)n*12288;
    for (int idx = t; idx < 4096; idx += 256) {
        int b = idx >> 6, i = idx & 63;
        XGs[b*196 + i]       = p0[idx];
        XGs[b*196 + 64 + i]  = p1[idx];
        XGs[b*196 + 128 + i] = p2[idx];
    }
    for (int idx = t; idx < 12288; idx += 256) Wns[idx] = wn[idx];
    __syncthreads();

    int o4 = (t & 15) * 4;
    int b4 = (t >> 4) * 4;
    ull acc[4][2];
    #pragma unroll
    for (int a = 0; a < 4; a++) { acc[a][0] = 0ull; acc[a][1] = 0ull; }

    const float* x0 = XGs + b4*196;
    #pragma unroll 2
    for (int j = 0; j < 192; j++) {
        ulonglong2 wv = *(const ulonglong2*)(Wns + j*64 + o4);
        #pragma unroll
        for (int bb = 0; bb < 4; bb++) {
            float xv = x0[bb*196 + j];
            ull xd = pack2(xv, xv);
            acc[bb][0] = ffma2(xd, wv.x, acc[bb][0]);
            acc[bb][1] = ffma2(xd, wv.y, acc[bb][1]);
        }
    }
    float4 bias = *(const float4*)(g_bn + n*64 + o4);
    #pragma unroll
    for (int bb = 0; bb < 4; bb++) {
        int row = (b4+bb)*NN + n;
        float2 v0 = unpack2(acc[bb][0]), v1 = unpack2(acc[bb][1]);
        float o0 = v0.x + bias.x, o1 = v0.y + bias.y;
        float o2 = v1.x + bias.z, o3 = v1.y + bias.w;
        __nv_bfloat16 h0, h1, h2, h3, l0, l1, l2, l3;
        bf16_split(o0, h0, l0); bf16_split(o1, h1, l1);
        bf16_split(o2, h2, l2); bf16_split(o3, h3, l3);
        size_t base = (size_t)row*64 + o4;
        *(__nv_bfloat162*)(g_H2h + base)     = __halves2bfloat162(h0, h1);
        *(__nv_bfloat162*)(g_H2h + base + 2) = __halves2bfloat162(h2, h3);
        *(__nv_bfloat162*)(g_H2l + base)     = __halves2bfloat162(l0, l1);
        *(__nv_bfloat162*)(g_H2l + base + 2) = __halves2bfloat162(l2, l3);
    }
}

// ---------------- K6: out = tanh(H2 @ W_out^T + b_out) via mma.sync bf16 ----
#define ASPLIT 18432                   /* 128*72*2 bytes per split */
__global__ void __launch_bounds__(256, 2) k6_mma(const float* __restrict__ b_out,
                                                 float* __restrict__ out) {
    extern __shared__ char smem[];
    uint32_t sb = smem_u32(smem);
    const int OFF_B = 2 * ASPLIT;
    int t = threadIdx.x, w = t >> 5, lane = t & 31;
    int rowBase = blockIdx.x * 128;
    int colSec  = blockIdx.y * 2048;
    int wm = (w & 1) * 64, wn = (w >> 1) * 32;

    for (int idx = t; idx < 2048; idx += 256) {
        int arr = idx >> 10, rem = idx & 1023;
        int r = rem >> 3, cb = rem & 7;
        const __nv_bfloat16* src = (arr ? g_H2l : g_H2h)
                                 + (size_t)(rowBase + r)*64 + cb*8;
        cp16(sb + arr*ASPLIT + r*144 + cb*16, src);
    }
    for (int idx = t; idx < 2048; idx += 256) {
        int arr = idx >> 10, rem = idx & 1023;
        int r = rem >> 3, cb = rem & 7;
        const __nv_bfloat16* src = (arr ? g_Wl : g_Wh)
                                 + (size_t)(colSec + r)*64 + cb*8;
        cp16(sb + OFF_B + arr*ASPLIT + r*144 + cb*16, src);
    }
    cp_commit();
    cp_wait0();
    __syncthreads();

    int g4 = lane >> 3;
    int rsel = (g4 & 1) * 8 + (lane & 7);
    int kselA = (g4 >> 1) * 8;
    int g2 = (lane >> 3) & 1;
    int nsel = lane & 7;
    int kselB = g2 * 8;

    uint32_t aBase[4][2];
    #pragma unroll
    for (int mt = 0; mt < 4; mt++) {
        uint32_t off = (uint32_t)((wm + mt*16 + rsel)*144 + kselA*2);
        aBase[mt][0] = sb + off;
        aBase[mt][1] = sb + ASPLIT + off;
    }
    uint32_t bOff[4];
    #pragma unroll
    for (int nt = 0; nt < 4; nt++)
        bOff[nt] = (uint32_t)((wn + nt*8 + nsel)*144 + kselB*2);

    for (int it = 0; it < 16; it++) {
        int stage = it & 1;
        if (it + 1 < 16) {
            int nc = colSec + (it + 1) * 128;
            for (int idx = t; idx < 2048; idx += 256) {
                int arr = idx >> 10, rem = idx & 1023;
                int r = rem >> 3, cb = rem & 7;
                const __nv_bfloat16* src = (arr ? g_Wl : g_Wh)
                                         + (size_t)(nc + r)*64 + cb*8;
                cp16(sb + OFF_B + (stage^1)*2*ASPLIT + arr*ASPLIT + r*144 + cb*16, src);
            }
        }
        cp_commit();

        float acc[4][4][4];
        #pragma unroll
        for (int mt = 0; mt < 4; mt++)
            #pragma unroll
            for (int nt = 0; nt < 4; nt++)
                #pragma unroll
                for (int q = 0; q < 4; q++) acc[mt][nt][q] = 0.f;

        uint32_t bStage = sb + OFF_B + stage*2*ASPLIT;
        #pragma unroll
        for (int ks = 0; ks < 4; ks++) {
            uint32_t ah[4][4], al[4][4], bh[4][2], bl[4][2];
            #pragma unroll
            for (int mt = 0; mt < 4; mt++) {
                ldm4(ah[mt], aBase[mt][0] + ks*32);
                ldm4(al[mt], aBase[mt][1] + ks*32);
            }
            #pragma unroll
            for (int nt = 0; nt < 4; nt++) {
                ldm2(bh[nt], bStage + bOff[nt] + ks*32);
                ldm2(bl[nt], bStage + ASPLIT + bOff[nt] + ks*32);
            }
            #pragma unroll
            for (int mt = 0; mt < 4; mt++)
                #pragma unroll
                for (int nt = 0; nt < 4; nt++) {
                    mma_bf16(acc[mt][nt], ah[mt], bh[nt]);
                    mma_bf16(acc[mt][nt], ah[mt], bl[nt]);
                    mma_bf16(acc[mt][nt], al[mt], bh[nt]);
                }
        }

        int colT = colSec + it*128 + wn;
        #pragma unroll
        for (int nt = 0; nt < 4; nt++) {
            int col = colT + nt*8 + (lane & 3)*2;
            float2 bv = *(const float2*)(b_out + col);
            #pragma unroll
            for (int mt = 0; mt < 4; mt++) {
                int row0 = rowBase + wm + mt*16 + (lane >> 2);
                float2 o0, o1;
                o0.x = my_tanh(acc[mt][nt][0] + bv.x);
                o0.y = my_tanh(acc[mt][nt][1] + bv.y);
                o1.x = my_tanh(acc[mt][nt][2] + bv.x);
                o1.y = my_tanh(acc[mt][nt][3] + bv.y);
                *(float2*)(out + (size_t)row0*HC2 + col)       = o0;
                *(float2*)(out + (size_t)(row0+8)*HC2 + col)   = o1;
            }
        }

        cp_wait0();
        __syncthreads();
    }
}

// ---------------- launch -----------------------------------------------------
extern "C" void kernel_launch(void* const* d_in, const int* in_sizes, int n_in,
                              void* d_out, int out_size) {
    const float* z      = (const float*)d_in[0];
    const float* W_in   = (const float*)d_in[1];
    const float* b_in   = (const float*)d_in[2];
    const float* W_out  = (const float*)d_in[3];
    const float* b_out  = (const float*)d_in[4];
    const float* emb    = (const float*)d_in[5];
    const float* wpool  = (const float*)d_in[6];
    const float* bpool  = (const float*)d_in[7];
    float* out = (float*)d_out;

    const int SM4 = 81920;        // 2 stages x (A 20KB + B 20KB)
    const int SM6 = 6 * ASPLIT;   // 110592
    cudaFuncSetAttribute(k4_mma,
        cudaFuncAttributeMaxDynamicSharedMemorySize, SM4);
    cudaFuncSetAttribute(k5_nodegemm,
        cudaFuncAttributeMaxDynamicSharedMemorySize, (64*196 + 12288)*4);
    cudaFuncSetAttribute(k6_mma,
        cudaFuncAttributeMaxDynamicSharedMemorySize, SM6);

    kA_inproj_splitW<<<332, 256>>>(z, W_in, b_in, W_out);
    kB_supports_nodeparams<<<461, 320>>>(emb, wpool, bpool);
    k3_cheb   <<<NN, 320>>>();
    k4_mma    <<<dim3(3, 32, 2), 256, SM4>>>();
    k5_nodegemm<<<NN, 256, (64*196 + 12288)*4>>>();
    k6_mma    <<<dim3(150, 2), 256, SM6>>>(b_out, out);
}

// round 11
// speedup vs baseline: 2.2221x; 1.0082x over previous
#include <cuda_runtime.h>
#include <cuda_bf16.h>
#include <math.h>
#include <cstdint>

#define NB 64
#define NN 300
#define NH 64
#define ROWS (NB*NN)        /* 19200 */
#define HC2  4096           /* HC*HC */
#define SP   320            /* padded contraction dim for S / H^T */

typedef unsigned long long ull;

// ---------------- scratch (device globals; .bss => zero-initialized) --------
__device__ float g_Hm  [NN*HC2];        // H node-major: [n][b*64+c]
__device__ float g_A   [NN*NN];         // supports fp32           [n][m]
__device__ float g_Wn  [NN*3*NH*NH];    // per-node weights        [n][(k*64+i)*64+o]
__device__ float g_bn  [NN*NH];         // per-node bias           [n][o]
__device__ float g_XG12[2*NN*HC2];      // diffusion results k=1,2 [k][n][b*64+c]
__device__ __align__(16) __nv_bfloat16 g_H2h[ROWS*NH]; // H2 hi split [row][i]
__device__ __align__(16) __nv_bfloat16 g_H2l[ROWS*NH]; // H2 lo split
__device__ __align__(16) __nv_bfloat16 g_Wh [HC2*NH];  // W_out hi (native [c][i])
__device__ __align__(16) __nv_bfloat16 g_Wl [HC2*NH];  // W_out lo
__device__ __align__(16) __nv_bfloat16 g_Sh [2*384*SP]; // S_k hi [k][n][m] rowmaj
__device__ __align__(16) __nv_bfloat16 g_Sl [2*384*SP]; // S_k lo
__device__ __align__(16) __nv_bfloat16 g_HTh[HC2*SP];   // H^T hi [col][m]
__device__ __align__(16) __nv_bfloat16 g_HTl[HC2*SP];   // H^T lo

// ---------------- f32x2 helpers ----------------------------------------------
__device__ __forceinline__ ull ffma2(ull a, ull b, ull c) {
    ull d;
    asm("fma.rn.f32x2 %0, %1, %2, %3;" : "=l"(d) : "l"(a), "l"(b), "l"(c));
    return d;
}
__device__ __forceinline__ ull pack2(float x, float y) {
    ull d;
    asm("mov.b64 %0, {%1, %2};" : "=l"(d) : "f"(x), "f"(y));
    return d;
}
__device__ __forceinline__ float2 unpack2(ull v) {
    float2 r;
    asm("mov.b64 {%0, %1}, %2;" : "=f"(r.x), "=f"(r.y) : "l"(v));
    return r;
}

__device__ __forceinline__ float my_tanh(float x) {
    float xc = fminf(x, 15.f);
    float e = __expf(2.f * xc);
    return __fdividef(e - 1.f, e + 1.f);
}

// ---------------- stable-PTX tensor helpers ---------------------------------
__device__ __forceinline__ uint32_t smem_u32(const void* p) {
    uint32_t a;
    asm("{ .reg .u64 t; cvta.to.shared.u64 t, %1; cvt.u32.u64 %0, t; }"
        : "=r"(a) : "l"(p));
    return a;
}
__device__ __forceinline__ void ldm4(uint32_t* r, uint32_t addr) {
    asm volatile("ldmatrix.sync.aligned.m8n8.x4.shared.b16 {%0,%1,%2,%3}, [%4];"
                 : "=r"(r[0]), "=r"(r[1]), "=r"(r[2]), "=r"(r[3]) : "r"(addr));
}
__device__ __forceinline__ void ldm2(uint32_t* r, uint32_t addr) {
    asm volatile("ldmatrix.sync.aligned.m8n8.x2.shared.b16 {%0,%1}, [%2];"
                 : "=r"(r[0]), "=r"(r[1]) : "r"(addr));
}
__device__ __forceinline__ void mma_bf16(float* c, const uint32_t* a,
                                         const uint32_t* b) {
    asm volatile(
        "mma.sync.aligned.m16n8k16.row.col.f32.bf16.bf16.f32 "
        "{%0,%1,%2,%3}, {%4,%5,%6,%7}, {%8,%9}, {%0,%1,%2,%3};"
        : "+f"(c[0]), "+f"(c[1]), "+f"(c[2]), "+f"(c[3])
        : "r"(a[0]), "r"(a[1]), "r"(a[2]), "r"(a[3]), "r"(b[0]), "r"(b[1]));
}
__device__ __forceinline__ void cp16(uint32_t smem, const void* g) {
    asm volatile("cp.async.cg.shared.global [%0], [%1], 16;"
                 :: "r"(smem), "l"(__cvta_generic_to_global(g)));
}
__device__ __forceinline__ void cp_commit() {
    asm volatile("cp.async.commit_group;" ::: "memory");
}
__device__ __forceinline__ void cp_wait0() {
    asm volatile("cp.async.wait_group 0;" ::: "memory");
}
__device__ __forceinline__ void cp_wait1() {
    asm volatile("cp.async.wait_group 1;" ::: "memory");
}
__device__ __forceinline__ void bf16_split(float v, __nv_bfloat16& h,
                                           __nv_bfloat16& l) {
    h = __float2bfloat16(v);
    l = __float2bfloat16(v - __bfloat162float(h));
}

// ---------------- KA: in-projection (blocks 0..299) + W_out bf16 split ------
__global__ void __launch_bounds__(256) kA_inproj_splitW(
        const float* __restrict__ z,
        const float* __restrict__ W_in,
        const float* __restrict__ b_in,
        const float* __restrict__ W_out) {
    __shared__ float sm[8320];
    int t = threadIdx.x;
    if (blockIdx.x < 300) {
        float* Wt = sm;            // [64][64]  Wt[i][o] = W_in[o][i]
        float* zs = sm + 4096;     // 64 rows of z
        int rowBase = blockIdx.x * 64;
        for (int idx = t; idx < 4096; idx += 256) {
            int o = idx >> 6, i = idx & 63;
            Wt[i*64 + o] = W_in[idx];
        }
        for (int idx4 = t; idx4 < 1024; idx4 += 256)
            *(float4*)(zs + idx4*4) = *(const float4*)(z + (size_t)rowBase*64 + idx4*4);
        __syncthreads();

        int o = t & 63, rg = t >> 6;
        float acc[16];
        float bo = b_in[o];
        #pragma unroll
        for (int r = 0; r < 16; r++) acc[r] = bo;
        const float* zrow = zs + rg*16*64;
        #pragma unroll 4
        for (int i = 0; i < 64; i++) {
            float w = Wt[i*64 + o];
            #pragma unroll
            for (int r = 0; r < 16; r++)
                acc[r] = fmaf(zrow[r*64 + i], w, acc[r]);
        }
        #pragma unroll
        for (int r = 0; r < 16; r++) {
            float h = fmaxf(acc[r], 0.f);
            int row = rowBase + rg*16 + r;
            int b = row / NN, n = row - b*NN;
            g_Hm[(size_t)n*HC2 + b*64 + o] = h;
        }
    } else {
        size_t base = (size_t)(blockIdx.x - 300) * 8192;
        for (int idx = t; idx < 8192; idx += 256) {
            float wv = W_out[base + idx];
            __nv_bfloat16 h, l;
            bf16_split(wv, h, l);
            g_Wh[base + idx] = h;
            g_Wl[base + idx] = l;
        }
    }
}

// ---------------- KB: supports (0..299), Wn (300..395), bias (396),
//                      H transpose+split (397..460) -------------------------
__global__ void __launch_bounds__(320) kB_supports_nodeparams(
        const float* __restrict__ node_emb,
        const float* __restrict__ wpool,
        const float* __restrict__ bpool) {
    __shared__ float E[NN*10];
    __shared__ float red[512];
    __shared__ float wps[1280];
    __shared__ float Ts[64*65];
    int t = threadIdx.x;
    int blk = blockIdx.x;
    if (blk < 300) {
        int n = blk;
        for (int idx = t; idx < NN*10; idx += 320) E[idx] = node_emb[idx];
        if (t < 192) red[320 + t] = -1e30f;
        __syncthreads();

        float v = 0.f;
        if (t < NN) {
            float dot = 0.f;
            #pragma unroll
            for (int d = 0; d < 10; d++) dot = fmaf(E[n*10+d], E[t*10+d], dot);
            v = fmaxf(dot, 0.f);
        }
        red[t] = (t < NN) ? v : -1e30f;
        __syncthreads();
        #pragma unroll
        for (int s = 256; s > 0; s >>= 1) {
            if (t < s) red[t] = fmaxf(red[t], red[t+s]);
            __syncthreads();
        }
        float mx = red[0];
        __syncthreads();

        float ev = (t < NN) ? __expf(v - mx) : 0.f;
        red[t] = ev;
        if (t < 192) red[320 + t] = 0.f;
        __syncthreads();
        #pragma unroll
        for (int s = 256; s > 0; s >>= 1) {
            if (t < s) red[t] += red[t+s];
            __syncthreads();
        }
        float inv = 1.f / red[0];
        if (t < NN) {
            float a = ev * inv;
            g_A[n*NN + t] = a;
            __nv_bfloat16 h, l;
            bf16_split(a, h, l);
            g_Sh[n*SP + t] = h;          // plane 0 = supports, row-major
            g_Sl[n*SP + t] = l;
        }
    } else if (blk < 396) {
        int jt = (blk - 300) * 128;
        for (int idx = t; idx < NN*10; idx += 320) E[idx] = node_emb[idx];
        for (int idx = t; idx < 1280; idx += 320) {
            int d = idx >> 7, jj = idx & 127;
            wps[idx] = wpool[(size_t)d*12288 + jt + jj];
        }
        __syncthreads();
        if (t < 256) {
            int jj = t & 127, half = t >> 7;
            const float* w0 = wps + jj;
            for (int n = half; n < NN; n += 2) {
                float acc = 0.f;
                const float* en = E + n*10;
                #pragma unroll
                for (int d = 0; d < 10; d++)
                    acc = fmaf(en[d], w0[d*128], acc);
                g_Wn[(size_t)n*12288 + jt + jj] = acc;
            }
        }
    } else if (blk == 396) {
        for (int idx = t; idx < 640; idx += 320) wps[idx] = bpool[idx];
        for (int idx = t; idx < NN*10; idx += 320) E[idx] = node_emb[idx];
        __syncthreads();
        for (int idx = t; idx < NN*64; idx += 320) {
            int n = idx >> 6, o = idx & 63;
            float acc = 0.f;
            #pragma unroll
            for (int d = 0; d < 10; d++)
                acc = fmaf(E[n*10+d], wps[d*64 + o], acc);
            g_bn[idx] = acc;
        }
    } else {
        // transpose + bf16-split 64 columns of Hm -> HT[col][m]
        int cb = (blk - 397) * 64;
        for (int m0 = 0; m0 < NN; m0 += 64) {
            int mc = min(64, NN - m0);
            __syncthreads();
            for (int idx = t; idx < 4096; idx += 320) {
                int mm = idx >> 6, c = idx & 63;
                if (mm < mc)
                    Ts[mm*65 + c] = g_Hm[(size_t)(m0+mm)*HC2 + cb + c];
            }
            __syncthreads();
            for (int idx = t; idx < 4096; idx += 320) {
                int c = idx >> 6, mm = idx & 63;
                if (mm < mc) {
                    __nv_bfloat16 h, l;
                    bf16_split(Ts[mm*65 + c], h, l);
                    g_HTh[(size_t)(cb+c)*SP + m0 + mm] = h;
                    g_HTl[(size_t)(cb+c)*SP + m0 + mm] = l;
                }
            }
        }
    }
}

// ---------------- K3: S2 = 2 A A - I, bf16 split row-major (plane 1) -------
__global__ void __launch_bounds__(320) k3_cheb() {
    __shared__ float arow[NN];
    int t = threadIdx.x, n = blockIdx.x;
    for (int idx = t; idx < NN; idx += 320) arow[idx] = g_A[n*NN + idx];
    __syncthreads();
    if (t < NN) {
        float acc = 0.f;
        #pragma unroll 4
        for (int p = 0; p < NN; p++)
            acc = fmaf(arow[p], g_A[p*NN + t], acc);
        float v = 2.f*acc - ((t == n) ? 1.f : 0.f);
        __nv_bfloat16 h, l;
        bf16_split(v, h, l);
        g_Sh[384*SP + n*SP + t] = h;
        g_Sl[384*SP + n*SP + t] = l;
    }
}

// ---------------- K4: XG_k = S_k @ Hm via mma.sync bf16 split ---------------
__global__ void __launch_bounds__(256, 2) k4_mma() {
    extern __shared__ char smem[];
    uint32_t sb = smem_u32(smem);
    int t = threadIdx.x, w = t >> 5, lane = t & 31;
    int rowBase = blockIdx.x * 128;
    int colBase = blockIdx.y * 128;
    int kz = blockIdx.z;
    const __nv_bfloat16* Sh = g_Sh + (size_t)kz*384*SP;
    const __nv_bfloat16* Sl = g_Sl + (size_t)kz*384*SP;
    float* C = g_XG12 + (size_t)kz * NN * HC2;
    int wm = (w & 1) * 64, wn = (w >> 1) * 32;

    int g4 = lane >> 3;
    int rsel = (g4 & 1) * 8 + (lane & 7);
    int kselA = (g4 >> 1) * 8;
    int nsel = lane & 7;
    int kselB = ((lane >> 3) & 1) * 8;
    uint32_t aOff[4], bOff[4];
    #pragma unroll
    for (int mt = 0; mt < 4; mt++)
        aOff[mt] = (uint32_t)((wm + mt*16 + rsel)*80 + kselA*2);
    #pragma unroll
    for (int nt = 0; nt < 4; nt++)
        bOff[nt] = (uint32_t)((wn + nt*8 + nsel)*80 + kselB*2);

    float acc[4][4][4];
    #pragma unroll
    for (int mt = 0; mt < 4; mt++)
        #pragma unroll
        for (int nt = 0; nt < 4; nt++)
            #pragma unroll
            for (int q = 0; q < 4; q++) acc[mt][nt][q] = 0.f;

    const int NC = 10;
    for (int idx = t; idx < 1024; idx += 256) {
        int arr = idx >> 9, rem = idx & 511;
        int r = rem >> 2, c4 = rem & 3;
        cp16(sb + arr*10240 + r*80 + c4*16,
             (arr ? Sl : Sh) + (size_t)(rowBase + r)*SP + c4*8);
        cp16(sb + 40960 + arr*10240 + r*80 + c4*16,
             (arr ? g_HTl : g_HTh) + (size_t)(colBase + r)*SP + c4*8);
    }
    cp_commit();

    for (int c = 0; c < NC; c++) {
        int stage = c & 1;
        if (c + 1 < NC) {
            int m0 = (c + 1) * 32, ns = (c + 1) & 1;
            for (int idx = t; idx < 1024; idx += 256) {
                int arr = idx >> 9, rem = idx & 511;
                int r = rem >> 2, c4 = rem & 3;
                cp16(sb + ns*20480 + arr*10240 + r*80 + c4*16,
                     (arr ? Sl : Sh) + (size_t)(rowBase + r)*SP + m0 + c4*8);
                cp16(sb + 40960 + ns*20480 + arr*10240 + r*80 + c4*16,
                     (arr ? g_HTl : g_HTh) + (size_t)(colBase + r)*SP + m0 + c4*8);
            }
            cp_commit();
            cp_wait1();
        } else {
            cp_wait0();
        }
        __syncthreads();

        uint32_t sA = sb + stage*20480;
        uint32_t sB = sb + 40960 + stage*20480;
        #pragma unroll
        for (int ks = 0; ks < 2; ks++) {
            uint32_t ah[4][4], al[4][4], bh[4][2], bl[4][2];
            #pragma unroll
            for (int mt = 0; mt < 4; mt++) {
                ldm4(ah[mt], sA + aOff[mt] + ks*32);
                ldm4(al[mt], sA + 10240 + aOff[mt] + ks*32);
            }
            #pragma unroll
            for (int nt = 0; nt < 4; nt++) {
                ldm2(bh[nt], sB + bOff[nt] + ks*32);
                ldm2(bl[nt], sB + 10240 + bOff[nt] + ks*32);
            }
            #pragma unroll
            for (int mt = 0; mt < 4; mt++)
                #pragma unroll
                for (int nt = 0; nt < 4; nt++) {
                    mma_bf16(acc[mt][nt], ah[mt], bh[nt]);
                    mma_bf16(acc[mt][nt], ah[mt], bl[nt]);
                    mma_bf16(acc[mt][nt], al[mt], bh[nt]);
                }
        }
        __syncthreads();
    }

    #pragma unroll
    for (int nt = 0; nt < 4; nt++) {
        int col = colBase + wn + nt*8 + (lane & 3)*2;
        #pragma unroll
        for (int mt = 0; mt < 4; mt++) {
            int n0 = rowBase + wm + mt*16 + (lane >> 2);
            if (n0 < NN)
                *(float2*)(C + (size_t)n0*HC2 + col) =
                    make_float2(acc[mt][nt][0], acc[mt][nt][1]);
            if (n0 + 8 < NN)
                *(float2*)(C + (size_t)(n0+8)*HC2 + col) =
                    make_float2(acc[mt][nt][2], acc[mt][nt][3]);
        }
    }
}

// ---------------- K5: per-node [64,192]@[192,64] + bias -> H2 bf16 splits ---
__global__ void __launch_bounds__(256) k5_nodegemm() {
    extern __shared__ float sm5[];
    float* XGs = sm5;               // [64 b][196] : 3 planes of 64
    float* Wns = sm5 + 64*196;      // [192][64]
    int n = blockIdx.x, t = threadIdx.x;
    const float* p0 = g_Hm   + (size_t)n*HC2;
    const float* p1 = g_XG12 + (size_t)n*HC2;
    const float* p2 = g_XG12 + (size_t)(NN + n)*HC2;
    const float* wn = g_Wn + (size_t)n*12288;
    for (int idx = t; idx < 4096; idx += 256) {
        int b = idx >> 6, i = idx & 63;
        XGs[b*196 + i]       = p0[idx];
        XGs[b*196 + 64 + i]  = p1[idx];
        XGs[b*196 + 128 + i] = p2[idx];
    }
    for (int idx = t; idx < 12288; idx += 256) Wns[idx] = wn[idx];
    __syncthreads();

    int o4 = (t & 15) * 4;
    int b4 = (t >> 4) * 4;
    ull acc[4][2];
    #pragma unroll
    for (int a = 0; a < 4; a++) { acc[a][0] = 0ull; acc[a][1] = 0ull; }

    const float* x0 = XGs + b4*196;
    #pragma unroll 2
    for (int j = 0; j < 192; j++) {
        ulonglong2 wv = *(const ulonglong2*)(Wns + j*64 + o4);
        #pragma unroll
        for (int bb = 0; bb < 4; bb++) {
            float xv = x0[bb*196 + j];
            ull xd = pack2(xv, xv);
            acc[bb][0] = ffma2(xd, wv.x, acc[bb][0]);
            acc[bb][1] = ffma2(xd, wv.y, acc[bb][1]);
        }
    }
    float4 bias = *(const float4*)(g_bn + n*64 + o4);
    #pragma unroll
    for (int bb = 0; bb < 4; bb++) {
        int row = (b4+bb)*NN + n;
        float2 v0 = unpack2(acc[bb][0]), v1 = unpack2(acc[bb][1]);
        float o0 = v0.x + bias.x, o1 = v0.y + bias.y;
        float o2 = v1.x + bias.z, o3 = v1.y + bias.w;
        __nv_bfloat16 h0, h1, h2, h3, l0, l1, l2, l3;
        bf16_split(o0, h0, l0); bf16_split(o1, h1, l1);
        bf16_split(o2, h2, l2); bf16_split(o3, h3, l3);
        size_t base = (size_t)row*64 + o4;
        *(__nv_bfloat162*)(g_H2h + base)     = __halves2bfloat162(h0, h1);
        *(__nv_bfloat162*)(g_H2h + base + 2) = __halves2bfloat162(h2, h3);
        *(__nv_bfloat162*)(g_H2l + base)     = __halves2bfloat162(l0, l1);
        *(__nv_bfloat162*)(g_H2l + base + 2) = __halves2bfloat162(l2, l3);
    }
}

// ---------------- K6: out = tanh(H2 @ W_out^T + b_out) via mma.sync bf16 ----
// Grid (150, 4): 600 blocks of 4 col-tiles each -> ~2 waves at 2 CTAs/SM,
// killing the 300-block/296-slot scheduling tail (was ~2x block-time wall).
#define ASPLIT 18432                   /* 128*72*2 bytes per split */
__global__ void __launch_bounds__(256, 2) k6_mma(const float* __restrict__ b_out,
                                                 float* __restrict__ out) {
    extern __shared__ char smem[];
    uint32_t sb = smem_u32(smem);
    const int OFF_B = 2 * ASPLIT;
    int t = threadIdx.x, w = t >> 5, lane = t & 31;
    int rowBase = blockIdx.x * 128;
    int colSec  = blockIdx.y * 1024;
    int wm = (w & 1) * 64, wn = (w >> 1) * 32;

    for (int idx = t; idx < 2048; idx += 256) {
        int arr = idx >> 10, rem = idx & 1023;
        int r = rem >> 3, cb = rem & 7;
        const __nv_bfloat16* src = (arr ? g_H2l : g_H2h)
                                 + (size_t)(rowBase + r)*64 + cb*8;
        cp16(sb + arr*ASPLIT + r*144 + cb*16, src);
    }
    for (int idx = t; idx < 2048; idx += 256) {
        int arr = idx >> 10, rem = idx & 1023;
        int r = rem >> 3, cb = rem & 7;
        const __nv_bfloat16* src = (arr ? g_Wl : g_Wh)
                                 + (size_t)(colSec + r)*64 + cb*8;
        cp16(sb + OFF_B + arr*ASPLIT + r*144 + cb*16, src);
    }
    cp_commit();
    cp_wait0();
    __syncthreads();

    int g4 = lane >> 3;
    int rsel = (g4 & 1) * 8 + (lane & 7);
    int kselA = (g4 >> 1) * 8;
    int g2 = (lane >> 3) & 1;
    int nsel = lane & 7;
    int kselB = g2 * 8;

    uint32_t aBase[4][2];
    #pragma unroll
    for (int mt = 0; mt < 4; mt++) {
        uint32_t off = (uint32_t)((wm + mt*16 + rsel)*144 + kselA*2);
        aBase[mt][0] = sb + off;
        aBase[mt][1] = sb + ASPLIT + off;
    }
    uint32_t bOff[4];
    #pragma unroll
    for (int nt = 0; nt < 4; nt++)
        bOff[nt] = (uint32_t)((wn + nt*8 + nsel)*144 + kselB*2);

    for (int it = 0; it < 8; it++) {
        int stage = it & 1;
        if (it + 1 < 8) {
            int nc = colSec + (it + 1) * 128;
            for (int idx = t; idx < 2048; idx += 256) {
                int arr = idx >> 10, rem = idx & 1023;
                int r = rem >> 3, cb = rem & 7;
                const __nv_bfloat16* src = (arr ? g_Wl : g_Wh)
                                         + (size_t)(nc + r)*64 + cb*8;
                cp16(sb + OFF_B + (stage^1)*2*ASPLIT + arr*ASPLIT + r*144 + cb*16, src);
            }
        }
        cp_commit();

        float acc[4][4][4];
        #pragma unroll
        for (int mt = 0; mt < 4; mt++)
            #pragma unroll
            for (int nt = 0; nt < 4; nt++)
                #pragma unroll
                for (int q = 0; q < 4; q++) acc[mt][nt][q] = 0.f;

        uint32_t bStage = sb + OFF_B + stage*2*ASPLIT;
        #pragma unroll
        for (int ks = 0; ks < 4; ks++) {
            uint32_t ah[4][4], al[4][4], bh[4][2], bl[4][2];
            #pragma unroll
            for (int mt = 0; mt < 4; mt++) {
                ldm4(ah[mt], aBase[mt][0] + ks*32);
                ldm4(al[mt], aBase[mt][1] + ks*32);
            }
            #pragma unroll
            for (int nt = 0; nt < 4; nt++) {
                ldm2(bh[nt], bStage + bOff[nt] + ks*32);
                ldm2(bl[nt], bStage + ASPLIT + bOff[nt] + ks*32);
            }
            #pragma unroll
            for (int mt = 0; mt < 4; mt++)
                #pragma unroll
                for (int nt = 0; nt < 4; nt++) {
                    mma_bf16(acc[mt][nt], ah[mt], bh[nt]);
                    mma_bf16(acc[mt][nt], ah[mt], bl[nt]);
                    mma_bf16(acc[mt][nt], al[mt], bh[nt]);
                }
        }

        int colT = colSec + it*128 + wn;
        #pragma unroll
        for (int nt = 0; nt < 4; nt++) {
            int col = colT + nt*8 + (lane & 3)*2;
            float2 bv = *(const float2*)(b_out + col);
            #pragma unroll
            for (int mt = 0; mt < 4; mt++) {
                int row0 = rowBase + wm + mt*16 + (lane >> 2);
                float2 o0, o1;
                o0.x = my_tanh(acc[mt][nt][0] + bv.x);
                o0.y = my_tanh(acc[mt][nt][1] + bv.y);
                o1.x = my_tanh(acc[mt][nt][2] + bv.x);
                o1.y = my_tanh(acc[mt][nt][3] + bv.y);
                *(float2*)(out + (size_t)row0*HC2 + col)       = o0;
                *(float2*)(out + (size_t)(row0+8)*HC2 + col)   = o1;
            }
        }

        cp_wait0();
        __syncthreads();
    }
}

// ---------------- launch -----------------------------------------------------
extern "C" void kernel_launch(void* const* d_in, const int* in_sizes, int n_in,
                              void* d_out, int out_size) {
    const float* z      = (const float*)d_in[0];
    const float* W_in   = (const float*)d_in[1];
    const float* b_in   = (const float*)d_in[2];
    const float* W_out  = (const float*)d_in[3];
    const float* b_out  = (const float*)d_in[4];
    const float* emb    = (const float*)d_in[5];
    const float* wpool  = (const float*)d_in[6];
    const float* bpool  = (const float*)d_in[7];
    float* out = (float*)d_out;

    const int SM4 = 81920;        // 2 stages x (A 20KB + B 20KB)
    const int SM6 = 6 * ASPLIT;   // 110592
    cudaFuncSetAttribute(k4_mma,
        cudaFuncAttributeMaxDynamicSharedMemorySize, SM4);
    cudaFuncSetAttribute(k5_nodegemm,
        cudaFuncAttributeMaxDynamicSharedMemorySize, (64*196 + 12288)*4);
    cudaFuncSetAttribute(k6_mma,
        cudaFuncAttributeMaxDynamicSharedMemorySize, SM6);

    kA_inproj_splitW<<<332, 256>>>(z, W_in, b_in, W_out);
    kB_supports_nodeparams<<<461, 320>>>(emb, wpool, bpool);
    k3_cheb   <<<NN, 320>>>();
    k4_mma    <<<dim3(3, 32, 2), 256, SM4>>>();
    k5_nodegemm<<<NN, 256, (64*196 + 12288)*4>>>();
    k6_mma    <<<dim3(150, 4), 256, SM6>>>(b_out, out);
}

// round 12
// speedup vs baseline: 2.3273x; 1.0473x over previous
#include <cuda_runtime.h>
#include <cuda_bf16.h>
#include <math.h>
#include <cstdint>

#define NB 64
#define NN 300
#define NH 64
#define ROWS (NB*NN)        /* 19200 */
#define HC2  4096           /* HC*HC */
#define SP   320            /* padded contraction dim for S / H^T */

typedef unsigned long long ull;

// ---------------- scratch (device globals; .bss => zero-initialized) --------
__device__ float g_Hm  [NN*HC2];        // H node-major: [n][b*64+c]
__device__ float g_A   [NN*NN];         // supports fp32           [n][m]
__device__ float g_Wn  [NN*3*NH*NH];    // per-node weights        [n][(k*64+i)*64+o]
__device__ float g_bn  [NN*NH];         // per-node bias           [n][o]
__device__ float g_XG12[2*NN*HC2];      // diffusion results k=1,2 [k][n][b*64+c]
__device__ __align__(16) __nv_bfloat16 g_H2h[ROWS*NH]; // H2 hi split [row][i]
__device__ __align__(16) __nv_bfloat16 g_H2l[ROWS*NH]; // H2 lo split
__device__ __align__(16) __nv_bfloat16 g_Wh [HC2*NH];  // W_out hi (native [c][i])
__device__ __align__(16) __nv_bfloat16 g_Wl [HC2*NH];  // W_out lo
__device__ __align__(16) __nv_bfloat16 g_Sh [2*384*SP]; // S_k hi [k][n][m] rowmaj
__device__ __align__(16) __nv_bfloat16 g_Sl [2*384*SP]; // S_k lo
__device__ __align__(16) __nv_bfloat16 g_HTh[HC2*SP];   // H^T hi [col][m]
__device__ __align__(16) __nv_bfloat16 g_HTl[HC2*SP];   // H^T lo

// ---------------- f32x2 helpers ----------------------------------------------
__device__ __forceinline__ ull ffma2(ull a, ull b, ull c) {
    ull d;
    asm("fma.rn.f32x2 %0, %1, %2, %3;" : "=l"(d) : "l"(a), "l"(b), "l"(c));
    return d;
}
__device__ __forceinline__ ull pack2(float x, float y) {
    ull d;
    asm("mov.b64 %0, {%1, %2};" : "=l"(d) : "f"(x), "f"(y));
    return d;
}
__device__ __forceinline__ float2 unpack2(ull v) {
    float2 r;
    asm("mov.b64 {%0, %1}, %2;" : "=f"(r.x), "=f"(r.y) : "l"(v));
    return r;
}

__device__ __forceinline__ float my_tanh(float x) {
    float xc = fminf(x, 15.f);
    float e = __expf(2.f * xc);
    return __fdividef(e - 1.f, e + 1.f);
}

// ---------------- stable-PTX tensor helpers ---------------------------------
__device__ __forceinline__ uint32_t smem_u32(const void* p) {
    uint32_t a;
    asm("{ .reg .u64 t; cvta.to.shared.u64 t, %1; cvt.u32.u64 %0, t; }"
        : "=r"(a) : "l"(p));
    return a;
}
__device__ __forceinline__ void ldm4(uint32_t* r, uint32_t addr) {
    asm volatile("ldmatrix.sync.aligned.m8n8.x4.shared.b16 {%0,%1,%2,%3}, [%4];"
                 : "=r"(r[0]), "=r"(r[1]), "=r"(r[2]), "=r"(r[3]) : "r"(addr));
}
__device__ __forceinline__ void ldm2(uint32_t* r, uint32_t addr) {
    asm volatile("ldmatrix.sync.aligned.m8n8.x2.shared.b16 {%0,%1}, [%2];"
                 : "=r"(r[0]), "=r"(r[1]) : "r"(addr));
}
__device__ __forceinline__ void mma_bf16(float* c, const uint32_t* a,
                                         const uint32_t* b) {
    asm volatile(
        "mma.sync.aligned.m16n8k16.row.col.f32.bf16.bf16.f32 "
        "{%0,%1,%2,%3}, {%4,%5,%6,%7}, {%8,%9}, {%0,%1,%2,%3};"
        : "+f"(c[0]), "+f"(c[1]), "+f"(c[2]), "+f"(c[3])
        : "r"(a[0]), "r"(a[1]), "r"(a[2]), "r"(a[3]), "r"(b[0]), "r"(b[1]));
}
__device__ __forceinline__ void cp16(uint32_t smem, const void* g) {
    asm volatile("cp.async.cg.shared.global [%0], [%1], 16;"
                 :: "r"(smem), "l"(__cvta_generic_to_global(g)));
}
__device__ __forceinline__ void cp_commit() {
    asm volatile("cp.async.commit_group;" ::: "memory");
}
__device__ __forceinline__ void cp_wait0() {
    asm volatile("cp.async.wait_group 0;" ::: "memory");
}
__device__ __forceinline__ void cp_wait1() {
    asm volatile("cp.async.wait_group 1;" ::: "memory");
}
__device__ __forceinline__ void bf16_split(float v, __nv_bfloat16& h,
                                           __nv_bfloat16& l) {
    h = __float2bfloat16(v);
    l = __float2bfloat16(v - __bfloat162float(h));
}

// ---------------- L1: all independent prologue work in one grid -------------
// blocks [0,300)   : in-projection -> g_Hm
// blocks [300,332) : W_out bf16 hi/lo split
// blocks [332,632) : supports softmax row n -> g_A + bf16 split (plane 0)
// blocks [632,728) : Wn j-tiles
// block  728       : bias
__global__ void __launch_bounds__(320) L1_prologue(
        const float* __restrict__ z,
        const float* __restrict__ W_in,
        const float* __restrict__ b_in,
        const float* __restrict__ W_out,
        const float* __restrict__ node_emb,
        const float* __restrict__ wpool,
        const float* __restrict__ bpool) {
    __shared__ float buf[8320];
    int t = threadIdx.x;
    int blk = blockIdx.x;
    if (blk < 300) {
        float* Wt = buf;            // [64][64]  Wt[i][o] = W_in[o][i]
        float* zs = buf + 4096;     // 64 rows of z
        int rowBase = blk * 64;
        for (int idx = t; idx < 4096; idx += 320) {
            int o = idx >> 6, i = idx & 63;
            Wt[i*64 + o] = W_in[idx];
        }
        for (int idx4 = t; idx4 < 1024; idx4 += 320)
            *(float4*)(zs + idx4*4) = *(const float4*)(z + (size_t)rowBase*64 + idx4*4);
        __syncthreads();

        if (t < 256) {
            int o = t & 63, rg = t >> 6;
            float acc[16];
            float bo = b_in[o];
            #pragma unroll
            for (int r = 0; r < 16; r++) acc[r] = bo;
            const float* zrow = zs + rg*16*64;
            #pragma unroll 4
            for (int i = 0; i < 64; i++) {
                float w = Wt[i*64 + o];
                #pragma unroll
                for (int r = 0; r < 16; r++)
                    acc[r] = fmaf(zrow[r*64 + i], w, acc[r]);
            }
            #pragma unroll
            for (int r = 0; r < 16; r++) {
                float h = fmaxf(acc[r], 0.f);
                int row = rowBase + rg*16 + r;
                int b = row / NN, n = row - b*NN;
                g_Hm[(size_t)n*HC2 + b*64 + o] = h;
            }
        }
    } else if (blk < 332) {
        size_t base = (size_t)(blk - 300) * 8192;
        for (int idx = t; idx < 8192; idx += 320) {
            float wv = W_out[base + idx];
            __nv_bfloat16 h, l;
            bf16_split(wv, h, l);
            g_Wh[base + idx] = h;
            g_Wl[base + idx] = l;
        }
    } else if (blk < 632) {
        int n = blk - 332;
        float* E   = buf;           // [300*10]
        float* red = buf + 3000;    // [512]
        for (int idx = t; idx < NN*10; idx += 320) E[idx] = node_emb[idx];
        if (t < 192) red[320 + t] = -1e30f;
        __syncthreads();

        float v = 0.f;
        if (t < NN) {
            float dot = 0.f;
            #pragma unroll
            for (int d = 0; d < 10; d++) dot = fmaf(E[n*10+d], E[t*10+d], dot);
            v = fmaxf(dot, 0.f);
        }
        red[t] = (t < NN) ? v : -1e30f;
        __syncthreads();
        #pragma unroll
        for (int s = 256; s > 0; s >>= 1) {
            if (t < s) red[t] = fmaxf(red[t], red[t+s]);
            __syncthreads();
        }
        float mx = red[0];
        __syncthreads();

        float ev = (t < NN) ? __expf(v - mx) : 0.f;
        red[t] = ev;
        if (t < 192) red[320 + t] = 0.f;
        __syncthreads();
        #pragma unroll
        for (int s = 256; s > 0; s >>= 1) {
            if (t < s) red[t] += red[t+s];
            __syncthreads();
        }
        float inv = 1.f / red[0];
        if (t < NN) {
            float a = ev * inv;
            g_A[n*NN + t] = a;
            __nv_bfloat16 h, l;
            bf16_split(a, h, l);
            g_Sh[n*SP + t] = h;
            g_Sl[n*SP + t] = l;
        }
    } else if (blk < 728) {
        int jt = (blk - 632) * 128;
        float* E   = buf;           // [3000]
        float* wps = buf + 3000;    // [1280]
        for (int idx = t; idx < NN*10; idx += 320) E[idx] = node_emb[idx];
        for (int idx = t; idx < 1280; idx += 320) {
            int d = idx >> 7, jj = idx & 127;
            wps[idx] = wpool[(size_t)d*12288 + jt + jj];
        }
        __syncthreads();
        if (t < 256) {
            int jj = t & 127, half = t >> 7;
            const float* w0 = wps + jj;
            for (int n = half; n < NN; n += 2) {
                float acc = 0.f;
                const float* en = E + n*10;
                #pragma unroll
                for (int d = 0; d < 10; d++)
                    acc = fmaf(en[d], w0[d*128], acc);
                g_Wn[(size_t)n*12288 + jt + jj] = acc;
            }
        }
    } else {
        float* E   = buf;
        float* wps = buf + 3000;
        for (int idx = t; idx < 640; idx += 320) wps[idx] = bpool[idx];
        for (int idx = t; idx < NN*10; idx += 320) E[idx] = node_emb[idx];
        __syncthreads();
        for (int idx = t; idx < NN*64; idx += 320) {
            int n = idx >> 6, o = idx & 63;
            float acc = 0.f;
            #pragma unroll
            for (int d = 0; d < 10; d++)
                acc = fmaf(E[n*10+d], wps[d*64 + o], acc);
            g_bn[idx] = acc;
        }
    }
}

// ---------------- L2: Chebyshev (0..299) + H transpose/split (300..363) -----
__global__ void __launch_bounds__(320) L2_cheb_ht() {
    __shared__ float buf[4160];
    int t = threadIdx.x;
    int blk = blockIdx.x;
    if (blk < 300) {
        int n = blk;
        float* arow = buf;
        for (int idx = t; idx < NN; idx += 320) arow[idx] = g_A[n*NN + idx];
        __syncthreads();
        if (t < NN) {
            float acc = 0.f;
            #pragma unroll 4
            for (int p = 0; p < NN; p++)
                acc = fmaf(arow[p], g_A[p*NN + t], acc);
            float v = 2.f*acc - ((t == n) ? 1.f : 0.f);
            __nv_bfloat16 h, l;
            bf16_split(v, h, l);
            g_Sh[384*SP + n*SP + t] = h;
            g_Sl[384*SP + n*SP + t] = l;
        }
    } else {
        float* Ts = buf;            // [64][65]
        int cb = (blk - 300) * 64;
        for (int m0 = 0; m0 < NN; m0 += 64) {
            int mc = min(64, NN - m0);
            __syncthreads();
            for (int idx = t; idx < 4096; idx += 320) {
                int mm = idx >> 6, c = idx & 63;
                if (mm < mc)
                    Ts[mm*65 + c] = g_Hm[(size_t)(m0+mm)*HC2 + cb + c];
            }
            __syncthreads();
            for (int idx = t; idx < 4096; idx += 320) {
                int c = idx >> 6, mm = idx & 63;
                if (mm < mc) {
                    __nv_bfloat16 h, l;
                    bf16_split(Ts[mm*65 + c], h, l);
                    g_HTh[(size_t)(cb+c)*SP + m0 + mm] = h;
                    g_HTl[(size_t)(cb+c)*SP + m0 + mm] = l;
                }
            }
        }
    }
}

// ---------------- K4: XG_k = S_k @ Hm via mma.sync bf16 split ---------------
__global__ void __launch_bounds__(256, 2) k4_mma() {
    extern __shared__ char smem[];
    uint32_t sb = smem_u32(smem);
    int t = threadIdx.x, w = t >> 5, lane = t & 31;
    int rowBase = blockIdx.x * 128;
    int colBase = blockIdx.y * 128;
    int kz = blockIdx.z;
    const __nv_bfloat16* Sh = g_Sh + (size_t)kz*384*SP;
    const __nv_bfloat16* Sl = g_Sl + (size_t)kz*384*SP;
    float* C = g_XG12 + (size_t)kz * NN * HC2;
    int wm = (w & 1) * 64, wn = (w >> 1) * 32;

    int g4 = lane >> 3;
    int rsel = (g4 & 1) * 8 + (lane & 7);
    int kselA = (g4 >> 1) * 8;
    int nsel = lane & 7;
    int kselB = ((lane >> 3) & 1) * 8;
    uint32_t aOff[4], bOff[4];
    #pragma unroll
    for (int mt = 0; mt < 4; mt++)
        aOff[mt] = (uint32_t)((wm + mt*16 + rsel)*80 + kselA*2);
    #pragma unroll
    for (int nt = 0; nt < 4; nt++)
        bOff[nt] = (uint32_t)((wn + nt*8 + nsel)*80 + kselB*2);

    float acc[4][4][4];
    #pragma unroll
    for (int mt = 0; mt < 4; mt++)
        #pragma unroll
        for (int nt = 0; nt < 4; nt++)
            #pragma unroll
            for (int q = 0; q < 4; q++) acc[mt][nt][q] = 0.f;

    const int NC = 10;
    for (int idx = t; idx < 1024; idx += 256) {
        int arr = idx >> 9, rem = idx & 511;
        int r = rem >> 2, c4 = rem & 3;
        cp16(sb + arr*10240 + r*80 + c4*16,
             (arr ? Sl : Sh) + (size_t)(rowBase + r)*SP + c4*8);
        cp16(sb + 40960 + arr*10240 + r*80 + c4*16,
             (arr ? g_HTl : g_HTh) + (size_t)(colBase + r)*SP + c4*8);
    }
    cp_commit();

    for (int c = 0; c < NC; c++) {
        int stage = c & 1;
        if (c + 1 < NC) {
            int m0 = (c + 1) * 32, ns = (c + 1) & 1;
            for (int idx = t; idx < 1024; idx += 256) {
                int arr = idx >> 9, rem = idx & 511;
                int r = rem >> 2, c4 = rem & 3;
                cp16(sb + ns*20480 + arr*10240 + r*80 + c4*16,
                     (arr ? Sl : Sh) + (size_t)(rowBase + r)*SP + m0 + c4*8);
                cp16(sb + 40960 + ns*20480 + arr*10240 + r*80 + c4*16,
                     (arr ? g_HTl : g_HTh) + (size_t)(colBase + r)*SP + m0 + c4*8);
            }
            cp_commit();
            cp_wait1();
        } else {
            cp_wait0();
        }
        __syncthreads();

        uint32_t sA = sb + stage*20480;
        uint32_t sB = sb + 40960 + stage*20480;
        #pragma unroll
        for (int ks = 0; ks < 2; ks++) {
            uint32_t ah[4][4], al[4][4], bh[4][2], bl[4][2];
            #pragma unroll
            for (int mt = 0; mt < 4; mt++) {
                ldm4(ah[mt], sA + aOff[mt] + ks*32);
                ldm4(al[mt], sA + 10240 + aOff[mt] + ks*32);
            }
            #pragma unroll
            for (int nt = 0; nt < 4; nt++) {
                ldm2(bh[nt], sB + bOff[nt] + ks*32);
                ldm2(bl[nt], sB + 10240 + bOff[nt] + ks*32);
            }
            #pragma unroll
            for (int mt = 0; mt < 4; mt++)
                #pragma unroll
                for (int nt = 0; nt < 4; nt++) {
                    mma_bf16(acc[mt][nt], ah[mt], bh[nt]);
                    mma_bf16(acc[mt][nt], ah[mt], bl[nt]);
                    mma_bf16(acc[mt][nt], al[mt], bh[nt]);
                }
        }
        __syncthreads();
    }

    #pragma unroll
    for (int nt = 0; nt < 4; nt++) {
        int col = colBase + wn + nt*8 + (lane & 3)*2;
        #pragma unroll
        for (int mt = 0; mt < 4; mt++) {
            int n0 = rowBase + wm + mt*16 + (lane >> 2);
            if (n0 < NN)
                *(float2*)(C + (size_t)n0*HC2 + col) =
                    make_float2(acc[mt][nt][0], acc[mt][nt][1]);
            if (n0 + 8 < NN)
                *(float2*)(C + (size_t)(n0+8)*HC2 + col) =
                    make_float2(acc[mt][nt][2], acc[mt][nt][3]);
        }
    }
}

// ---------------- K5: per-node [64,192]@[192,64] + bias -> H2 bf16 splits ---
__global__ void __launch_bounds__(256) k5_nodegemm() {
    extern __shared__ float sm5[];
    float* XGs = sm5;               // [64 b][196] : 3 planes of 64
    float* Wns = sm5 + 64*196;      // [192][64]
    int n = blockIdx.x, t = threadIdx.x;
    const float* p0 = g_Hm   + (size_t)n*HC2;
    const float* p1 = g_XG12 + (size_t)n*HC2;
    const float* p2 = g_XG12 + (size_t)(NN + n)*HC2;
    const float* wn = g_Wn + (size_t)n*12288;
    for (int idx = t; idx < 4096; idx += 256) {
        int b = idx >> 6, i = idx & 63;
        XGs[b*196 + i]       = p0[idx];
        XGs[b*196 + 64 + i]  = p1[idx];
        XGs[b*196 + 128 + i] = p2[idx];
    }
    for (int idx = t; idx < 12288; idx += 256) Wns[idx] = wn[idx];
    __syncthreads();

    int o4 = (t & 15) * 4;
    int b4 = (t >> 4) * 4;
    ull acc[4][2];
    #pragma unroll
    for (int a = 0; a < 4; a++) { acc[a][0] = 0ull; acc[a][1] = 0ull; }

    const float* x0 = XGs + b4*196;
    #pragma unroll 2
    for (int j = 0; j < 192; j++) {
        ulonglong2 wv = *(const ulonglong2*)(Wns + j*64 + o4);
        #pragma unroll
        for (int bb = 0; bb < 4; bb++) {
            float xv = x0[bb*196 + j];
            ull xd = pack2(xv, xv);
            acc[bb][0] = ffma2(xd, wv.x, acc[bb][0]);
            acc[bb][1] = ffma2(xd, wv.y, acc[bb][1]);
        }
    }
    float4 bias = *(const float4*)(g_bn + n*64 + o4);
    #pragma unroll
    for (int bb = 0; bb < 4; bb++) {
        int row = (b4+bb)*NN + n;
        float2 v0 = unpack2(acc[bb][0]), v1 = unpack2(acc[bb][1]);
        float o0 = v0.x + bias.x, o1 = v0.y + bias.y;
        float o2 = v1.x + bias.z, o3 = v1.y + bias.w;
        __nv_bfloat16 h0, h1, h2, h3, l0, l1, l2, l3;
        bf16_split(o0, h0, l0); bf16_split(o1, h1, l1);
        bf16_split(o2, h2, l2); bf16_split(o3, h3, l3);
        size_t base = (size_t)row*64 + o4;
        *(__nv_bfloat162*)(g_H2h + base)     = __halves2bfloat162(h0, h1);
        *(__nv_bfloat162*)(g_H2h + base + 2) = __halves2bfloat162(h2, h3);
        *(__nv_bfloat162*)(g_H2l + base)     = __halves2bfloat162(l0, l1);
        *(__nv_bfloat162*)(g_H2l + base + 2) = __halves2bfloat162(l2, l3);
    }
}

// ---------------- K6: out = tanh(H2 @ W_out^T + b_out) via mma.sync bf16 ----
#define ASPLIT 18432                   /* 128*72*2 bytes per split */
__global__ void __launch_bounds__(256, 2) k6_mma(const float* __restrict__ b_out,
                                                 float* __restrict__ out) {
    extern __shared__ char smem[];
    uint32_t sb = smem_u32(smem);
    const int OFF_B = 2 * ASPLIT;
    int t = threadIdx.x, w = t >> 5, lane = t & 31;
    int rowBase = blockIdx.x * 128;
    int colSec  = blockIdx.y * 1024;
    int wm = (w & 1) * 64, wn = (w >> 1) * 32;

    for (int idx = t; idx < 2048; idx += 256) {
        int arr = idx >> 10, rem = idx & 1023;
        int r = rem >> 3, cb = rem & 7;
        const __nv_bfloat16* src = (arr ? g_H2l : g_H2h)
                                 + (size_t)(rowBase + r)*64 + cb*8;
        cp16(sb + arr*ASPLIT + r*144 + cb*16, src);
    }
    for (int idx = t; idx < 2048; idx += 256) {
        int arr = idx >> 10, rem = idx & 1023;
        int r = rem >> 3, cb = rem & 7;
        const __nv_bfloat16* src = (arr ? g_Wl : g_Wh)
                                 + (size_t)(colSec + r)*64 + cb*8;
        cp16(sb + OFF_B + arr*ASPLIT + r*144 + cb*16, src);
    }
    cp_commit();
    cp_wait0();
    __syncthreads();

    int g4 = lane >> 3;
    int rsel = (g4 & 1) * 8 + (lane & 7);
    int kselA = (g4 >> 1) * 8;
    int g2 = (lane >> 3) & 1;
    int nsel = lane & 7;
    int kselB = g2 * 8;

    uint32_t aBase[4][2];
    #pragma unroll
    for (int mt = 0; mt < 4; mt++) {
        uint32_t off = (uint32_t)((wm + mt*16 + rsel)*144 + kselA*2);
        aBase[mt][0] = sb + off;
        aBase[mt][1] = sb + ASPLIT + off;
    }
    uint32_t bOff[4];
    #pragma unroll
    for (int nt = 0; nt < 4; nt++)
        bOff[nt] = (uint32_t)((wn + nt*8 + nsel)*144 + kselB*2);

    for (int it = 0; it < 8; it++) {
        int stage = it & 1;
        if (it + 1 < 8) {
            int nc = colSec + (it + 1) * 128;
            for (int idx = t; idx < 2048; idx += 256) {
                int arr = idx >> 10, rem = idx & 1023;
                int r = rem >> 3, cb = rem & 7;
                const __nv_bfloat16* src = (arr ? g_Wl : g_Wh)
                                         + (size_t)(nc + r)*64 + cb*8;
                cp16(sb + OFF_B + (stage^1)*2*ASPLIT + arr*ASPLIT + r*144 + cb*16, src);
            }
        }
        cp_commit();

        float acc[4][4][4];
        #pragma unroll
        for (int mt = 0; mt < 4; mt++)
            #pragma unroll
            for (int nt = 0; nt < 4; nt++)
                #pragma unroll
                for (int q = 0; q < 4; q++) acc[mt][nt][q] = 0.f;

        uint32_t bStage = sb + OFF_B + stage*2*ASPLIT;
        #pragma unroll
        for (int ks = 0; ks < 4; ks++) {
            uint32_t ah[4][4], al[4][4], bh[4][2], bl[4][2];
            #pragma unroll
            for (int mt = 0; mt < 4; mt++) {
                ldm4(ah[mt], aBase[mt][0] + ks*32);
                ldm4(al[mt], aBase[mt][1] + ks*32);
            }
            #pragma unroll
            for (int nt = 0; nt < 4; nt++) {
                ldm2(bh[nt], bStage + bOff[nt] + ks*32);
                ldm2(bl[nt], bStage + ASPLIT + bOff[nt] + ks*32);
            }
            #pragma unroll
            for (int mt = 0; mt < 4; mt++)
                #pragma unroll
                for (int nt = 0; nt < 4; nt++) {
                    mma_bf16(acc[mt][nt], ah[mt], bh[nt]);
                    mma_bf16(acc[mt][nt], ah[mt], bl[nt]);
                    mma_bf16(acc[mt][nt], al[mt], bh[nt]);
                }
        }

        int colT = colSec + it*128 + wn;
        #pragma unroll
        for (int nt = 0; nt < 4; nt++) {
            int col = colT + nt*8 + (lane & 3)*2;
            float2 bv = *(const float2*)(b_out + col);
            #pragma unroll
            for (int mt = 0; mt < 4; mt++) {
                int row0 = rowBase + wm + mt*16 + (lane >> 2);
                float2 o0, o1;
                o0.x = my_tanh(acc[mt][nt][0] + bv.x);
                o0.y = my_tanh(acc[mt][nt][1] + bv.y);
                o1.x = my_tanh(acc[mt][nt][2] + bv.x);
                o1.y = my_tanh(acc[mt][nt][3] + bv.y);
                *(float2*)(out + (size_t)row0*HC2 + col)       = o0;
                *(float2*)(out + (size_t)(row0+8)*HC2 + col)   = o1;
            }
        }

        cp_wait0();
        __syncthreads();
    }
}

// ---------------- launch -----------------------------------------------------
extern "C" void kernel_launch(void* const* d_in, const int* in_sizes, int n_in,
                              void* d_out, int out_size) {
    const float* z      = (const float*)d_in[0];
    const float* W_in   = (const float*)d_in[1];
    const float* b_in   = (const float*)d_in[2];
    const float* W_out  = (const float*)d_in[3];
    const float* b_out  = (const float*)d_in[4];
    const float* emb    = (const float*)d_in[5];
    const float* wpool  = (const float*)d_in[6];
    const float* bpool  = (const float*)d_in[7];
    float* out = (float*)d_out;

    const int SM4 = 81920;        // 2 stages x (A 20KB + B 20KB)
    const int SM6 = 6 * ASPLIT;   // 110592
    cudaFuncSetAttribute(k4_mma,
        cudaFuncAttributeMaxDynamicSharedMemorySize, SM4);
    cudaFuncSetAttribute(k5_nodegemm,
        cudaFuncAttributeMaxDynamicSharedMemorySize, (64*196 + 12288)*4);
    cudaFuncSetAttribute(k6_mma,
        cudaFuncAttributeMaxDynamicSharedMemorySize, SM6);

    L1_prologue<<<729, 320>>>(z, W_in, b_in, W_out, emb, wpool, bpool);
    L2_cheb_ht <<<364, 320>>>();
    k4_mma     <<<dim3(3, 32, 2), 256, SM4>>>();
    k5_nodegemm<<<NN, 256, (64*196 + 12288)*4>>>();
    k6_mma     <<<dim3(150, 4), 256, SM6>>>(b_out, out);
}

// round 13
// speedup vs baseline: 2.4047x; 1.0333x over previous
#include <cuda_runtime.h>
#include <cuda_bf16.h>
#include <math.h>
#include <cstdint>

#define NB 64
#define NN 300
#define NH 64
#define ROWS (NB*NN)        /* 19200 */
#define HC2  4096           /* HC*HC */
#define SP   320            /* padded contraction dim for S / H^T */

typedef unsigned long long ull;

// ---------------- scratch (device globals; .bss => zero-initialized) --------
__device__ float g_Hm  [NN*HC2];        // H node-major fp32 [n][b*64+c] (feeds HT)
__device__ float g_A   [NN*NN];         // supports fp32     [n][m]
__device__ float g_bn  [NN*NH];         // per-node bias     [n][o]
__device__ __align__(16) __nv_bfloat16 g_XGh[NN*12288]; // XG hi [n][b*192+j]
__device__ __align__(16) __nv_bfloat16 g_XGl[NN*12288]; // XG lo
__device__ __align__(16) __nv_bfloat16 g_Wnh[NN*12288]; // Wn hi [n][j*64+o]
__device__ __align__(16) __nv_bfloat16 g_Wnl[NN*12288]; // Wn lo
__device__ __align__(16) __nv_bfloat16 g_H2h[ROWS*NH];  // H2 hi [row][i]
__device__ __align__(16) __nv_bfloat16 g_H2l[ROWS*NH];  // H2 lo
__device__ __align__(16) __nv_bfloat16 g_Wh [HC2*NH];   // W_out hi (native [c][i])
__device__ __align__(16) __nv_bfloat16 g_Wl [HC2*NH];   // W_out lo
__device__ __align__(16) __nv_bfloat16 g_Sh [2*384*SP]; // S_k hi [k][n][m]
__device__ __align__(16) __nv_bfloat16 g_Sl [2*384*SP]; // S_k lo
__device__ __align__(16) __nv_bfloat16 g_HTh[HC2*SP];   // H^T hi [col][m]
__device__ __align__(16) __nv_bfloat16 g_HTl[HC2*SP];   // H^T lo

__device__ __forceinline__ float my_tanh(float x) {
    float xc = fminf(x, 15.f);
    float e = __expf(2.f * xc);
    return __fdividef(e - 1.f, e + 1.f);
}

// ---------------- stable-PTX tensor helpers ---------------------------------
__device__ __forceinline__ uint32_t smem_u32(const void* p) {
    uint32_t a;
    asm("{ .reg .u64 t; cvta.to.shared.u64 t, %1; cvt.u32.u64 %0, t; }"
        : "=r"(a) : "l"(p));
    return a;
}
__device__ __forceinline__ void ldm4(uint32_t* r, uint32_t addr) {
    asm volatile("ldmatrix.sync.aligned.m8n8.x4.shared.b16 {%0,%1,%2,%3}, [%4];"
                 : "=r"(r[0]), "=r"(r[1]), "=r"(r[2]), "=r"(r[3]) : "r"(addr));
}
__device__ __forceinline__ void ldm2(uint32_t* r, uint32_t addr) {
    asm volatile("ldmatrix.sync.aligned.m8n8.x2.shared.b16 {%0,%1}, [%2];"
                 : "=r"(r[0]), "=r"(r[1]) : "r"(addr));
}
__device__ __forceinline__ void ldm2t(uint32_t* r, uint32_t addr) {
    asm volatile("ldmatrix.sync.aligned.m8n8.x2.trans.shared.b16 {%0,%1}, [%2];"
                 : "=r"(r[0]), "=r"(r[1]) : "r"(addr));
}
__device__ __forceinline__ void mma_bf16(float* c, const uint32_t* a,
                                         const uint32_t* b) {
    asm volatile(
        "mma.sync.aligned.m16n8k16.row.col.f32.bf16.bf16.f32 "
        "{%0,%1,%2,%3}, {%4,%5,%6,%7}, {%8,%9}, {%0,%1,%2,%3};"
        : "+f"(c[0]), "+f"(c[1]), "+f"(c[2]), "+f"(c[3])
        : "r"(a[0]), "r"(a[1]), "r"(a[2]), "r"(a[3]), "r"(b[0]), "r"(b[1]));
}
__device__ __forceinline__ void cp16(uint32_t smem, const void* g) {
    asm volatile("cp.async.cg.shared.global [%0], [%1], 16;"
                 :: "r"(smem), "l"(__cvta_generic_to_global(g)));
}
__device__ __forceinline__ void cp_commit() {
    asm volatile("cp.async.commit_group;" ::: "memory");
}
__device__ __forceinline__ void cp_wait0() {
    asm volatile("cp.async.wait_group 0;" ::: "memory");
}
__device__ __forceinline__ void cp_wait1() {
    asm volatile("cp.async.wait_group 1;" ::: "memory");
}
__device__ __forceinline__ void bf16_split(float v, __nv_bfloat16& h,
                                           __nv_bfloat16& l) {
    h = __float2bfloat16(v);
    l = __float2bfloat16(v - __bfloat162float(h));
}

// ---------------- L1: all independent prologue work in one grid -------------
// [0,300)  in-proj -> g_Hm fp32 + XG plane 0 bf16 splits
// [300,332) W_out bf16 split
// [332,632) supports softmax -> g_A + S plane 0 splits
// [632,728) Wn j-tiles -> bf16 splits
// 728      bias
__global__ void __launch_bounds__(320) L1_prologue(
        const float* __restrict__ z,
        const float* __restrict__ W_in,
        const float* __restrict__ b_in,
        const float* __restrict__ W_out,
        const float* __restrict__ node_emb,
        const float* __restrict__ wpool,
        const float* __restrict__ bpool) {
    __shared__ float buf[8320];
    int t = threadIdx.x;
    int blk = blockIdx.x;
    if (blk < 300) {
        float* Wt = buf;            // [64][64]  Wt[i][o] = W_in[o][i]
        float* zs = buf + 4096;     // 64 rows of z
        int rowBase = blk * 64;
        for (int idx = t; idx < 4096; idx += 320) {
            int o = idx >> 6, i = idx & 63;
            Wt[i*64 + o] = W_in[idx];
        }
        for (int idx4 = t; idx4 < 1024; idx4 += 320)
            *(float4*)(zs + idx4*4) = *(const float4*)(z + (size_t)rowBase*64 + idx4*4);
        __syncthreads();

        if (t < 256) {
            int o = t & 63, rg = t >> 6;
            float acc[16];
            float bo = b_in[o];
            #pragma unroll
            for (int r = 0; r < 16; r++) acc[r] = bo;
            const float* zrow = zs + rg*16*64;
            #pragma unroll 4
            for (int i = 0; i < 64; i++) {
                float w = Wt[i*64 + o];
                #pragma unroll
                for (int r = 0; r < 16; r++)
                    acc[r] = fmaf(zrow[r*64 + i], w, acc[r]);
            }
            #pragma unroll
            for (int r = 0; r < 16; r++) {
                float h = fmaxf(acc[r], 0.f);
                int row = rowBase + rg*16 + r;
                int b = row / NN, n = row - b*NN;
                g_Hm[(size_t)n*HC2 + b*64 + o] = h;
                __nv_bfloat16 hh, hl;
                bf16_split(h, hh, hl);
                size_t dst = (size_t)n*12288 + b*192 + o;   // XG plane 0
                g_XGh[dst] = hh;
                g_XGl[dst] = hl;
            }
        }
    } else if (blk < 332) {
        size_t base = (size_t)(blk - 300) * 8192;
        for (int idx = t; idx < 8192; idx += 320) {
            float wv = W_out[base + idx];
            __nv_bfloat16 h, l;
            bf16_split(wv, h, l);
            g_Wh[base + idx] = h;
            g_Wl[base + idx] = l;
        }
    } else if (blk < 632) {
        int n = blk - 332;
        float* E   = buf;
        float* red = buf + 3000;
        for (int idx = t; idx < NN*10; idx += 320) E[idx] = node_emb[idx];
        if (t < 192) red[320 + t] = -1e30f;
        __syncthreads();

        float v = 0.f;
        if (t < NN) {
            float dot = 0.f;
            #pragma unroll
            for (int d = 0; d < 10; d++) dot = fmaf(E[n*10+d], E[t*10+d], dot);
            v = fmaxf(dot, 0.f);
        }
        red[t] = (t < NN) ? v : -1e30f;
        __syncthreads();
        #pragma unroll
        for (int s = 256; s > 0; s >>= 1) {
            if (t < s) red[t] = fmaxf(red[t], red[t+s]);
            __syncthreads();
        }
        float mx = red[0];
        __syncthreads();

        float ev = (t < NN) ? __expf(v - mx) : 0.f;
        red[t] = ev;
        if (t < 192) red[320 + t] = 0.f;
        __syncthreads();
        #pragma unroll
        for (int s = 256; s > 0; s >>= 1) {
            if (t < s) red[t] += red[t+s];
            __syncthreads();
        }
        float inv = 1.f / red[0];
        if (t < NN) {
            float a = ev * inv;
            g_A[n*NN + t] = a;
            __nv_bfloat16 h, l;
            bf16_split(a, h, l);
            g_Sh[n*SP + t] = h;
            g_Sl[n*SP + t] = l;
        }
    } else if (blk < 728) {
        int jt = (blk - 632) * 128;
        float* E   = buf;
        float* wps = buf + 3000;
        for (int idx = t; idx < NN*10; idx += 320) E[idx] = node_emb[idx];
        for (int idx = t; idx < 1280; idx += 320) {
            int d = idx >> 7, jj = idx & 127;
            wps[idx] = wpool[(size_t)d*12288 + jt + jj];
        }
        __syncthreads();
        if (t < 256) {
            int jj = t & 127, half = t >> 7;
            const float* w0 = wps + jj;
            for (int n = half; n < NN; n += 2) {
                float acc = 0.f;
                const float* en = E + n*10;
                #pragma unroll
                for (int d = 0; d < 10; d++)
                    acc = fmaf(en[d], w0[d*128], acc);
                __nv_bfloat16 h, l;
                bf16_split(acc, h, l);
                size_t dst = (size_t)n*12288 + jt + jj;
                g_Wnh[dst] = h;
                g_Wnl[dst] = l;
            }
        }
    } else {
        float* E   = buf;
        float* wps = buf + 3000;
        for (int idx = t; idx < 640; idx += 320) wps[idx] = bpool[idx];
        for (int idx = t; idx < NN*10; idx += 320) E[idx] = node_emb[idx];
        __syncthreads();
        for (int idx = t; idx < NN*64; idx += 320) {
            int n = idx >> 6, o = idx & 63;
            float acc = 0.f;
            #pragma unroll
            for (int d = 0; d < 10; d++)
                acc = fmaf(E[n*10+d], wps[d*64 + o], acc);
            g_bn[idx] = acc;
        }
    }
}

// ---------------- L2: Chebyshev (0..299) + H transpose/split (300..363) -----
__global__ void __launch_bounds__(320) L2_cheb_ht() {
    __shared__ float buf[4160];
    int t = threadIdx.x;
    int blk = blockIdx.x;
    if (blk < 300) {
        int n = blk;
        float* arow = buf;
        for (int idx = t; idx < NN; idx += 320) arow[idx] = g_A[n*NN + idx];
        __syncthreads();
        if (t < NN) {
            float acc = 0.f;
            #pragma unroll 4
            for (int p = 0; p < NN; p++)
                acc = fmaf(arow[p], g_A[p*NN + t], acc);
            float v = 2.f*acc - ((t == n) ? 1.f : 0.f);
            __nv_bfloat16 h, l;
            bf16_split(v, h, l);
            g_Sh[384*SP + n*SP + t] = h;
            g_Sl[384*SP + n*SP + t] = l;
        }
    } else {
        float* Ts = buf;            // [64][65]
        int cb = (blk - 300) * 64;
        for (int m0 = 0; m0 < NN; m0 += 64) {
            int mc = min(64, NN - m0);
            __syncthreads();
            for (int idx = t; idx < 4096; idx += 320) {
                int mm = idx >> 6, c = idx & 63;
                if (mm < mc)
                    Ts[mm*65 + c] = g_Hm[(size_t)(m0+mm)*HC2 + cb + c];
            }
            __syncthreads();
            for (int idx = t; idx < 4096; idx += 320) {
                int c = idx >> 6, mm = idx & 63;
                if (mm < mc) {
                    __nv_bfloat16 h, l;
                    bf16_split(Ts[mm*65 + c], h, l);
                    g_HTh[(size_t)(cb+c)*SP + m0 + mm] = h;
                    g_HTl[(size_t)(cb+c)*SP + m0 + mm] = l;
                }
            }
        }
    }
}

// ---------------- K4: XG_k = S_k @ Hm via mma.sync; bf16-split epilogue -----
__global__ void __launch_bounds__(256, 2) k4_mma() {
    extern __shared__ char smem[];
    uint32_t sb = smem_u32(smem);
    int t = threadIdx.x, w = t >> 5, lane = t & 31;
    int rowBase = blockIdx.x * 128;
    int colBase = blockIdx.y * 128;
    int kz = blockIdx.z;
    const __nv_bfloat16* Sh = g_Sh + (size_t)kz*384*SP;
    const __nv_bfloat16* Sl = g_Sl + (size_t)kz*384*SP;
    int wm = (w & 1) * 64, wn = (w >> 1) * 32;

    int g4 = lane >> 3;
    int rsel = (g4 & 1) * 8 + (lane & 7);
    int kselA = (g4 >> 1) * 8;
    int nsel = lane & 7;
    int kselB = ((lane >> 3) & 1) * 8;
    uint32_t aOff[4], bOff[4];
    #pragma unroll
    for (int mt = 0; mt < 4; mt++)
        aOff[mt] = (uint32_t)((wm + mt*16 + rsel)*80 + kselA*2);
    #pragma unroll
    for (int nt = 0; nt < 4; nt++)
        bOff[nt] = (uint32_t)((wn + nt*8 + nsel)*80 + kselB*2);

    float acc[4][4][4];
    #pragma unroll
    for (int mt = 0; mt < 4; mt++)
        #pragma unroll
        for (int nt = 0; nt < 4; nt++)
            #pragma unroll
            for (int q = 0; q < 4; q++) acc[mt][nt][q] = 0.f;

    const int NC = 10;
    for (int idx = t; idx < 1024; idx += 256) {
        int arr = idx >> 9, rem = idx & 511;
        int r = rem >> 2, c4 = rem & 3;
        cp16(sb + arr*10240 + r*80 + c4*16,
             (arr ? Sl : Sh) + (size_t)(rowBase + r)*SP + c4*8);
        cp16(sb + 40960 + arr*10240 + r*80 + c4*16,
             (arr ? g_HTl : g_HTh) + (size_t)(colBase + r)*SP + c4*8);
    }
    cp_commit();

    for (int c = 0; c < NC; c++) {
        int stage = c & 1;
        if (c + 1 < NC) {
            int m0 = (c + 1) * 32, ns = (c + 1) & 1;
            for (int idx = t; idx < 1024; idx += 256) {
                int arr = idx >> 9, rem = idx & 511;
                int r = rem >> 2, c4 = rem & 3;
                cp16(sb + ns*20480 + arr*10240 + r*80 + c4*16,
                     (arr ? Sl : Sh) + (size_t)(rowBase + r)*SP + m0 + c4*8);
                cp16(sb + 40960 + ns*20480 + arr*10240 + r*80 + c4*16,
                     (arr ? g_HTl : g_HTh) + (size_t)(colBase + r)*SP + m0 + c4*8);
            }
            cp_commit();
            cp_wait1();
        } else {
            cp_wait0();
        }
        __syncthreads();

        uint32_t sA = sb + stage*20480;
        uint32_t sB = sb + 40960 + stage*20480;
        #pragma unroll
        for (int ks = 0; ks < 2; ks++) {
            uint32_t ah[4][4], al[4][4], bh[4][2], bl[4][2];
            #pragma unroll
            for (int mt = 0; mt < 4; mt++) {
                ldm4(ah[mt], sA + aOff[mt] + ks*32);
                ldm4(al[mt], sA + 10240 + aOff[mt] + ks*32);
            }
            #pragma unroll
            for (int nt = 0; nt < 4; nt++) {
                ldm2(bh[nt], sB + bOff[nt] + ks*32);
                ldm2(bl[nt], sB + 10240 + bOff[nt] + ks*32);
            }
            #pragma unroll
            for (int mt = 0; mt < 4; mt++)
                #pragma unroll
                for (int nt = 0; nt < 4; nt++) {
                    mma_bf16(acc[mt][nt], ah[mt], bh[nt]);
                    mma_bf16(acc[mt][nt], ah[mt], bl[nt]);
                    mma_bf16(acc[mt][nt], al[mt], bh[nt]);
                }
        }
        __syncthreads();
    }

    // epilogue: bf16 hi/lo split directly into k5's A layout
    int plane = (kz + 1) * 64;
    #pragma unroll
    for (int nt = 0; nt < 4; nt++) {
        int col = colBase + wn + nt*8 + (lane & 3)*2;
        int b = col >> 6, cc = col & 63;
        size_t boff = (size_t)b*192 + plane + cc;
        #pragma unroll
        for (int mt = 0; mt < 4; mt++) {
            int n0 = rowBase + wm + mt*16 + (lane >> 2);
            if (n0 < NN) {
                __nv_bfloat16 h0, l0, h1, l1;
                bf16_split(acc[mt][nt][0], h0, l0);
                bf16_split(acc[mt][nt][1], h1, l1);
                *(__nv_bfloat162*)(g_XGh + (size_t)n0*12288 + boff) = __halves2bfloat162(h0, h1);
                *(__nv_bfloat162*)(g_XGl + (size_t)n0*12288 + boff) = __halves2bfloat162(l0, l1);
            }
            if (n0 + 8 < NN) {
                __nv_bfloat16 h0, l0, h1, l1;
                bf16_split(acc[mt][nt][2], h0, l0);
                bf16_split(acc[mt][nt][3], h1, l1);
                *(__nv_bfloat162*)(g_XGh + (size_t)(n0+8)*12288 + boff) = __halves2bfloat162(h0, h1);
                *(__nv_bfloat162*)(g_XGl + (size_t)(n0+8)*12288 + boff) = __halves2bfloat162(l0, l1);
            }
        }
    }
}

// ---------------- K5: per-node [64,192]@[192,64] via mma.sync ---------------
// A = XG[b][j] (row, ldm4, pitch 400B); B = Wn[j][o] via ldmatrix.x2.trans
// (pitch 144B). D = AhBh + AhBl + AlBh. Epilogue: +bias, bf16 split -> H2.
#define K5_AL 25600
#define K5_BH 51200
#define K5_BL 78848
__global__ void __launch_bounds__(256, 2) k5_mma() {
    extern __shared__ char smem[];
    uint32_t sb = smem_u32(smem);
    int t = threadIdx.x, w = t >> 5, lane = t & 31;
    int n = blockIdx.x;

    const __nv_bfloat16* Ah = g_XGh + (size_t)n*12288;
    const __nv_bfloat16* Al = g_XGl + (size_t)n*12288;
    const __nv_bfloat16* Bh = g_Wnh + (size_t)n*12288;
    const __nv_bfloat16* Bl = g_Wnl + (size_t)n*12288;

    for (int idx = t; idx < 1536; idx += 256) {       // A: 64 rows x 24 chunks
        int r = idx / 24, cc = idx - r*24;
        cp16(sb + r*400 + cc*16,          Ah + r*192 + cc*8);
        cp16(sb + K5_AL + r*400 + cc*16,  Al + r*192 + cc*8);
    }
    for (int idx = t; idx < 1536; idx += 256) {       // B: 192 rows x 8 chunks
        int r = idx >> 3, cc = idx & 7;
        cp16(sb + K5_BH + r*144 + cc*16,  Bh + r*64 + cc*8);
        cp16(sb + K5_BL + r*144 + cc*16,  Bl + r*64 + cc*8);
    }
    cp_commit();
    cp_wait0();
    __syncthreads();

    int wm = (w & 3) * 16, wn = (w >> 2) * 32;
    int g4 = lane >> 3;
    int rsel = (g4 & 1) * 8 + (lane & 7);
    int kselA = (g4 >> 1) * 8;
    uint32_t aAddrH = sb + (uint32_t)((wm + rsel)*400 + kselA*2);
    uint32_t aAddrL = aAddrH + K5_AL;
    uint32_t bRow = (uint32_t)(lane & 15);
    uint32_t bAddr[4];
    #pragma unroll
    for (int nt = 0; nt < 4; nt++)
        bAddr[nt] = sb + K5_BH + bRow*144 + (uint32_t)((wn + nt*8)*2);

    float acc[4][4];
    #pragma unroll
    for (int nt = 0; nt < 4; nt++)
        #pragma unroll
        for (int q = 0; q < 4; q++) acc[nt][q] = 0.f;

    #pragma unroll
    for (int kc = 0; kc < 12; kc++) {
        uint32_t ah[4], al[4];
        ldm4(ah, aAddrH + kc*32);
        ldm4(al, aAddrL + kc*32);
        #pragma unroll
        for (int nt = 0; nt < 4; nt++) {
            uint32_t bh[2], bl[2];
            ldm2t(bh, bAddr[nt] + (uint32_t)(kc*16*144));
            ldm2t(bl, bAddr[nt] + (uint32_t)(K5_BL - K5_BH) + (uint32_t)(kc*16*144));
            mma_bf16(acc[nt], ah, bh);
            mma_bf16(acc[nt], ah, bl);
            mma_bf16(acc[nt], al, bh);
        }
    }

    // epilogue: +bias, bf16 split, write H2 (row = b*NN + n)
    #pragma unroll
    for (int nt = 0; nt < 4; nt++) {
        int o = wn + nt*8 + (lane & 3)*2;
        float2 bv = *(const float2*)(g_bn + n*64 + o);
        int b0 = wm + (lane >> 2);
        float v0 = acc[nt][0] + bv.x, v1 = acc[nt][1] + bv.y;
        float v2 = acc[nt][2] + bv.x, v3 = acc[nt][3] + bv.y;
        __nv_bfloat16 h0, l0, h1, l1, h2, l2, h3, l3;
        bf16_split(v0, h0, l0); bf16_split(v1, h1, l1);
        bf16_split(v2, h2, l2); bf16_split(v3, h3, l3);
        size_t r0 = ((size_t)(b0*NN + n))*64 + o;
        size_t r1 = ((size_t)((b0+8)*NN + n))*64 + o;
        *(__nv_bfloat162*)(g_H2h + r0) = __halves2bfloat162(h0, h1);
        *(__nv_bfloat162*)(g_H2l + r0) = __halves2bfloat162(l0, l1);
        *(__nv_bfloat162*)(g_H2h + r1) = __halves2bfloat162(h2, h3);
        *(__nv_bfloat162*)(g_H2l + r1) = __halves2bfloat162(l2, l3);
    }
}

// ---------------- K6: out = tanh(H2 @ W_out^T + b_out) via mma.sync bf16 ----
#define ASPLIT 18432                   /* 128*72*2 bytes per split */
__global__ void __launch_bounds__(256, 2) k6_mma(const float* __restrict__ b_out,
                                                 float* __restrict__ out) {
    extern __shared__ char smem[];
    uint32_t sb = smem_u32(smem);
    const int OFF_B = 2 * ASPLIT;
    int t = threadIdx.x, w = t >> 5, lane = t & 31;
    int rowBase = blockIdx.x * 128;
    int colSec  = blockIdx.y * 1024;
    int wm = (w & 1) * 64, wn = (w >> 1) * 32;

    for (int idx = t; idx < 2048; idx += 256) {
        int arr = idx >> 10, rem = idx & 1023;
        int r = rem >> 3, cb = rem & 7;
        const __nv_bfloat16* src = (arr ? g_H2l : g_H2h)
                                 + (size_t)(rowBase + r)*64 + cb*8;
        cp16(sb + arr*ASPLIT + r*144 + cb*16, src);
    }
    for (int idx = t; idx < 2048; idx += 256) {
        int arr = idx >> 10, rem = idx & 1023;
        int r = rem >> 3, cb = rem & 7;
        const __nv_bfloat16* src = (arr ? g_Wl : g_Wh)
                                 + (size_t)(colSec + r)*64 + cb*8;
        cp16(sb + OFF_B + arr*ASPLIT + r*144 + cb*16, src);
    }
    cp_commit();
    cp_wait0();
    __syncthreads();

    int g4 = lane >> 3;
    int rsel = (g4 & 1) * 8 + (lane & 7);
    int kselA = (g4 >> 1) * 8;
    int g2 = (lane >> 3) & 1;
    int nsel = lane & 7;
    int kselB = g2 * 8;

    uint32_t aBase[4][2];
    #pragma unroll
    for (int mt = 0; mt < 4; mt++) {
        uint32_t off = (uint32_t)((wm + mt*16 + rsel)*144 + kselA*2);
        aBase[mt][0] = sb + off;
        aBase[mt][1] = sb + ASPLIT + off;
    }
    uint32_t bOff[4];
    #pragma unroll
    for (int nt = 0; nt < 4; nt++)
        bOff[nt] = (uint32_t)((wn + nt*8 + nsel)*144 + kselB*2);

    for (int it = 0; it < 8; it++) {
        int stage = it & 1;
        if (it + 1 < 8) {
            int nc = colSec + (it + 1) * 128;
            for (int idx = t; idx < 2048; idx += 256) {
                int arr = idx >> 10, rem = idx & 1023;
                int r = rem >> 3, cb = rem & 7;
                const __nv_bfloat16* src = (arr ? g_Wl : g_Wh)
                                         + (size_t)(nc + r)*64 + cb*8;
                cp16(sb + OFF_B + (stage^1)*2*ASPLIT + arr*ASPLIT + r*144 + cb*16, src);
            }
        }
        cp_commit();

        float acc[4][4][4];
        #pragma unroll
        for (int mt = 0; mt < 4; mt++)
            #pragma unroll
            for (int nt = 0; nt < 4; nt++)
                #pragma unroll
                for (int q = 0; q < 4; q++) acc[mt][nt][q] = 0.f;

        uint32_t bStage = sb + OFF_B + stage*2*ASPLIT;
        #pragma unroll
        for (int ks = 0; ks < 4; ks++) {
            uint32_t ah[4][4], al[4][4], bh[4][2], bl[4][2];
            #pragma unroll
            for (int mt = 0; mt < 4; mt++) {
                ldm4(ah[mt], aBase[mt][0] + ks*32);
                ldm4(al[mt], aBase[mt][1] + ks*32);
            }
            #pragma unroll
            for (int nt = 0; nt < 4; nt++) {
                ldm2(bh[nt], bStage + bOff[nt] + ks*32);
                ldm2(bl[nt], bStage + ASPLIT + bOff[nt] + ks*32);
            }
            #pragma unroll
            for (int mt = 0; mt < 4; mt++)
                #pragma unroll
                for (int nt = 0; nt < 4; nt++) {
                    mma_bf16(acc[mt][nt], ah[mt], bh[nt]);
                    mma_bf16(acc[mt][nt], ah[mt], bl[nt]);
                    mma_bf16(acc[mt][nt], al[mt], bh[nt]);
                }
        }

        int colT = colSec + it*128 + wn;
        #pragma unroll
        for (int nt = 0; nt < 4; nt++) {
            int col = colT + nt*8 + (lane & 3)*2;
            float2 bv = *(const float2*)(b_out + col);
            #pragma unroll
            for (int mt = 0; mt < 4; mt++) {
                int row0 = rowBase + wm + mt*16 + (lane >> 2);
                float2 o0, o1;
                o0.x = my_tanh(acc[mt][nt][0] + bv.x);
                o0.y = my_tanh(acc[mt][nt][1] + bv.y);
                o1.x = my_tanh(acc[mt][nt][2] + bv.x);
                o1.y = my_tanh(acc[mt][nt][3] + bv.y);
                *(float2*)(out + (size_t)row0*HC2 + col)       = o0;
                *(float2*)(out + (size_t)(row0+8)*HC2 + col)   = o1;
            }
        }

        cp_wait0();
        __syncthreads();
    }
}

// ---------------- launch -----------------------------------------------------
extern "C" void kernel_launch(void* const* d_in, const int* in_sizes, int n_in,
                              void* d_out, int out_size) {
    const float* z      = (const float*)d_in[0];
    const float* W_in   = (const float*)d_in[1];
    const float* b_in   = (const float*)d_in[2];
    const float* W_out  = (const float*)d_in[3];
    const float* b_out  = (const float*)d_in[4];
    const float* emb    = (const float*)d_in[5];
    const float* wpool  = (const float*)d_in[6];
    const float* bpool  = (const float*)d_in[7];
    float* out = (float*)d_out;

    const int SM4 = 81920;        // 2 stages x (A 20KB + B 20KB)
    const int SM5 = 106496;       // A 2x25600 + B 2x27648
    const int SM6 = 6 * ASPLIT;   // 110592
    cudaFuncSetAttribute(k4_mma,
        cudaFuncAttributeMaxDynamicSharedMemorySize, SM4);
    cudaFuncSetAttribute(k5_mma,
        cudaFuncAttributeMaxDynamicSharedMemorySize, SM5);
    cudaFuncSetAttribute(k6_mma,
        cudaFuncAttributeMaxDynamicSharedMemorySize, SM6);

    L1_prologue<<<729, 320>>>(z, W_in, b_in, W_out, emb, wpool, bpool);
    L2_cheb_ht <<<364, 320>>>();
    k4_mma     <<<dim3(3, 32, 2), 256, SM4>>>();
    k5_mma     <<<NN, 256, SM5>>>();
    k6_mma     <<<dim3(150, 4), 256, SM6>>>(b_out, out);
}

// round 14
// speedup vs baseline: 2.4660x; 1.0255x over previous
#include <cuda_runtime.h>
#include <cuda_bf16.h>
#include <math.h>
#include <cstdint>

#define NB 64
#define NN 300
#define NH 64
#define ROWS (NB*NN)        /* 19200 */
#define HC2  4096           /* HC*HC */
#define SP   320            /* padded contraction dim for S / H^T */

typedef unsigned long long ull;

// ---------------- scratch (device globals; .bss => zero-initialized) --------
__device__ float g_Hm  [NN*HC2];        // H node-major fp32 [n][b*64+c] (feeds HT)
__device__ float g_A   [NN*NN];         // supports fp32     [n][m]
__device__ float g_bn  [NN*NH];         // per-node bias     [n][o]
__device__ __align__(16) __nv_bfloat16 g_XGh[NN*12288]; // XG hi [n][b*192+j]
__device__ __align__(16) __nv_bfloat16 g_XGl[NN*12288]; // XG lo
__device__ __align__(16) __nv_bfloat16 g_Wnh[NN*12288]; // Wn hi [n][j*64+o]
__device__ __align__(16) __nv_bfloat16 g_Wnl[NN*12288]; // Wn lo
__device__ __align__(16) __nv_bfloat16 g_H2h[ROWS*NH];  // H2 hi [row][i]
__device__ __align__(16) __nv_bfloat16 g_H2l[ROWS*NH];  // H2 lo
__device__ __align__(16) __nv_bfloat16 g_Wh [HC2*NH];   // W_out hi (native [c][i])
__device__ __align__(16) __nv_bfloat16 g_Wl [HC2*NH];   // W_out lo
__device__ __align__(16) __nv_bfloat16 g_Sh [2*384*SP]; // S_k hi [k][n][m]
__device__ __align__(16) __nv_bfloat16 g_Sl [2*384*SP]; // S_k lo
__device__ __align__(16) __nv_bfloat16 g_HTh[HC2*SP];   // H^T hi [col][m]
__device__ __align__(16) __nv_bfloat16 g_HTl[HC2*SP];   // H^T lo

// tanh = 1 - 2/(e^{2x}+1): 3 FMA-pipe ops + 2 MUFU, no clamp needed
// (e->inf => q->0 => 1; e->0 => q->2 => -1; near-0 abs err ~2e-7).
__device__ __forceinline__ float my_tanh(float x) {
    float e = __expf(2.f * x);
    float q = __fdividef(2.f, e + 1.f);
    return 1.f - q;
}

// ---------------- stable-PTX tensor helpers ---------------------------------
__device__ __forceinline__ uint32_t smem_u32(const void* p) {
    uint32_t a;
    asm("{ .reg .u64 t; cvta.to.shared.u64 t, %1; cvt.u32.u64 %0, t; }"
        : "=r"(a) : "l"(p));
    return a;
}
__device__ __forceinline__ void ldm4(uint32_t* r, uint32_t addr) {
    asm volatile("ldmatrix.sync.aligned.m8n8.x4.shared.b16 {%0,%1,%2,%3}, [%4];"
                 : "=r"(r[0]), "=r"(r[1]), "=r"(r[2]), "=r"(r[3]) : "r"(addr));
}
__device__ __forceinline__ void ldm2(uint32_t* r, uint32_t addr) {
    asm volatile("ldmatrix.sync.aligned.m8n8.x2.shared.b16 {%0,%1}, [%2];"
                 : "=r"(r[0]), "=r"(r[1]) : "r"(addr));
}
__device__ __forceinline__ void ldm2t(uint32_t* r, uint32_t addr) {
    asm volatile("ldmatrix.sync.aligned.m8n8.x2.trans.shared.b16 {%0,%1}, [%2];"
                 : "=r"(r[0]), "=r"(r[1]) : "r"(addr));
}
__device__ __forceinline__ void mma_bf16(float* c, const uint32_t* a,
                                         const uint32_t* b) {
    asm volatile(
        "mma.sync.aligned.m16n8k16.row.col.f32.bf16.bf16.f32 "
        "{%0,%1,%2,%3}, {%4,%5,%6,%7}, {%8,%9}, {%0,%1,%2,%3};"
        : "+f"(c[0]), "+f"(c[1]), "+f"(c[2]), "+f"(c[3])
        : "r"(a[0]), "r"(a[1]), "r"(a[2]), "r"(a[3]), "r"(b[0]), "r"(b[1]));
}
__device__ __forceinline__ void cp16(uint32_t smem, const void* g) {
    asm volatile("cp.async.cg.shared.global [%0], [%1], 16;"
                 :: "r"(smem), "l"(__cvta_generic_to_global(g)));
}
__device__ __forceinline__ void cp_commit() {
    asm volatile("cp.async.commit_group;" ::: "memory");
}
__device__ __forceinline__ void cp_wait0() {
    asm volatile("cp.async.wait_group 0;" ::: "memory");
}
__device__ __forceinline__ void cp_wait1() {
    asm volatile("cp.async.wait_group 1;" ::: "memory");
}
__device__ __forceinline__ void bf16_split(float v, __nv_bfloat16& h,
                                           __nv_bfloat16& l) {
    h = __float2bfloat16(v);
    l = __float2bfloat16(v - __bfloat162float(h));
}

// ---------------- L1: all independent prologue work in one grid -------------
__global__ void __launch_bounds__(320) L1_prologue(
        const float* __restrict__ z,
        const float* __restrict__ W_in,
        const float* __restrict__ b_in,
        const float* __restrict__ W_out,
        const float* __restrict__ node_emb,
        const float* __restrict__ wpool,
        const float* __restrict__ bpool) {
    __shared__ float buf[8320];
    int t = threadIdx.x;
    int blk = blockIdx.x;
    if (blk < 300) {
        float* Wt = buf;            // [64][64]  Wt[i][o] = W_in[o][i]
        float* zs = buf + 4096;     // 64 rows of z
        int rowBase = blk * 64;
        for (int idx = t; idx < 4096; idx += 320) {
            int o = idx >> 6, i = idx & 63;
            Wt[i*64 + o] = W_in[idx];
        }
        for (int idx4 = t; idx4 < 1024; idx4 += 320)
            *(float4*)(zs + idx4*4) = *(const float4*)(z + (size_t)rowBase*64 + idx4*4);
        __syncthreads();

        if (t < 256) {
            int o = t & 63, rg = t >> 6;
            float acc[16];
            float bo = b_in[o];
            #pragma unroll
            for (int r = 0; r < 16; r++) acc[r] = bo;
            const float* zrow = zs + rg*16*64;
            #pragma unroll 4
            for (int i = 0; i < 64; i++) {
                float w = Wt[i*64 + o];
                #pragma unroll
                for (int r = 0; r < 16; r++)
                    acc[r] = fmaf(zrow[r*64 + i], w, acc[r]);
            }
            #pragma unroll
            for (int r = 0; r < 16; r++) {
                float h = fmaxf(acc[r], 0.f);
                int row = rowBase + rg*16 + r;
                int b = row / NN, n = row - b*NN;
                g_Hm[(size_t)n*HC2 + b*64 + o] = h;
                __nv_bfloat16 hh, hl;
                bf16_split(h, hh, hl);
                size_t dst = (size_t)n*12288 + b*192 + o;   // XG plane 0
                g_XGh[dst] = hh;
                g_XGl[dst] = hl;
            }
        }
    } else if (blk < 332) {
        size_t base = (size_t)(blk - 300) * 8192;
        for (int idx = t; idx < 8192; idx += 320) {
            float wv = W_out[base + idx];
            __nv_bfloat16 h, l;
            bf16_split(wv, h, l);
            g_Wh[base + idx] = h;
            g_Wl[base + idx] = l;
        }
    } else if (blk < 632) {
        int n = blk - 332;
        float* E   = buf;
        float* red = buf + 3000;
        for (int idx = t; idx < NN*10; idx += 320) E[idx] = node_emb[idx];
        if (t < 192) red[320 + t] = -1e30f;
        __syncthreads();

        float v = 0.f;
        if (t < NN) {
            float dot = 0.f;
            #pragma unroll
            for (int d = 0; d < 10; d++) dot = fmaf(E[n*10+d], E[t*10+d], dot);
            v = fmaxf(dot, 0.f);
        }
        red[t] = (t < NN) ? v : -1e30f;
        __syncthreads();
        #pragma unroll
        for (int s = 256; s > 0; s >>= 1) {
            if (t < s) red[t] = fmaxf(red[t], red[t+s]);
            __syncthreads();
        }
        float mx = red[0];
        __syncthreads();

        float ev = (t < NN) ? __expf(v - mx) : 0.f;
        red[t] = ev;
        if (t < 192) red[320 + t] = 0.f;
        __syncthreads();
        #pragma unroll
        for (int s = 256; s > 0; s >>= 1) {
            if (t < s) red[t] += red[t+s];
            __syncthreads();
        }
        float inv = 1.f / red[0];
        if (t < NN) {
            float a = ev * inv;
            g_A[n*NN + t] = a;
            __nv_bfloat16 h, l;
            bf16_split(a, h, l);
            g_Sh[n*SP + t] = h;
            g_Sl[n*SP + t] = l;
        }
    } else if (blk < 728) {
        int jt = (blk - 632) * 128;
        float* E   = buf;
        float* wps = buf + 3000;
        for (int idx = t; idx < NN*10; idx += 320) E[idx] = node_emb[idx];
        for (int idx = t; idx < 1280; idx += 320) {
            int d = idx >> 7, jj = idx & 127;
            wps[idx] = wpool[(size_t)d*12288 + jt + jj];
        }
        __syncthreads();
        if (t < 256) {
            int jj = t & 127, half = t >> 7;
            const float* w0 = wps + jj;
            for (int n = half; n < NN; n += 2) {
                float acc = 0.f;
                const float* en = E + n*10;
                #pragma unroll
                for (int d = 0; d < 10; d++)
                    acc = fmaf(en[d], w0[d*128], acc);
                __nv_bfloat16 h, l;
                bf16_split(acc, h, l);
                size_t dst = (size_t)n*12288 + jt + jj;
                g_Wnh[dst] = h;
                g_Wnl[dst] = l;
            }
        }
    } else {
        float* E   = buf;
        float* wps = buf + 3000;
        for (int idx = t; idx < 640; idx += 320) wps[idx] = bpool[idx];
        for (int idx = t; idx < NN*10; idx += 320) E[idx] = node_emb[idx];
        __syncthreads();
        for (int idx = t; idx < NN*64; idx += 320) {
            int n = idx >> 6, o = idx & 63;
            float acc = 0.f;
            #pragma unroll
            for (int d = 0; d < 10; d++)
                acc = fmaf(E[n*10+d], wps[d*64 + o], acc);
            g_bn[idx] = acc;
        }
    }
}

// ---------------- L2: Chebyshev (0..299) + H transpose/split (300..363) -----
__global__ void __launch_bounds__(320) L2_cheb_ht() {
    __shared__ float buf[4160];
    int t = threadIdx.x;
    int blk = blockIdx.x;
    if (blk < 300) {
        int n = blk;
        float* arow = buf;
        for (int idx = t; idx < NN; idx += 320) arow[idx] = g_A[n*NN + idx];
        __syncthreads();
        if (t < NN) {
            float acc = 0.f;
            #pragma unroll 4
            for (int p = 0; p < NN; p++)
                acc = fmaf(arow[p], g_A[p*NN + t], acc);
            float v = 2.f*acc - ((t == n) ? 1.f : 0.f);
            __nv_bfloat16 h, l;
            bf16_split(v, h, l);
            g_Sh[384*SP + n*SP + t] = h;
            g_Sl[384*SP + n*SP + t] = l;
        }
    } else {
        float* Ts = buf;            // [64][65]
        int cb = (blk - 300) * 64;
        for (int m0 = 0; m0 < NN; m0 += 64) {
            int mc = min(64, NN - m0);
            __syncthreads();
            for (int idx = t; idx < 4096; idx += 320) {
                int mm = idx >> 6, c = idx & 63;
                if (mm < mc)
                    Ts[mm*65 + c] = g_Hm[(size_t)(m0+mm)*HC2 + cb + c];
            }
            __syncthreads();
            for (int idx = t; idx < 4096; idx += 320) {
                int c = idx >> 6, mm = idx & 63;
                if (mm < mc) {
                    __nv_bfloat16 h, l;
                    bf16_split(Ts[mm*65 + c], h, l);
                    g_HTh[(size_t)(cb+c)*SP + m0 + mm] = h;
                    g_HTl[(size_t)(cb+c)*SP + m0 + mm] = l;
                }
            }
        }
    }
}

// ---------------- K4: XG_k = S_k @ Hm via mma.sync; 96-row tiles ------------
// grid (4,32,2) = 256 blocks (vs 192): better chip fill. Rows 300..383 of S
// are .bss zeros; stores guarded by n < NN.
__global__ void __launch_bounds__(256, 2) k4_mma() {
    extern __shared__ char smem[];
    uint32_t sb = smem_u32(smem);
    // A: stage*15360 + split*7680 + r*80 (r<96); B at 30720: stage*20480 + split*10240
    int t = threadIdx.x, w = t >> 5, lane = t & 31;
    int rowBase = blockIdx.x * 96;
    int colBase = blockIdx.y * 128;
    int kz = blockIdx.z;
    const __nv_bfloat16* Sh = g_Sh + (size_t)kz*384*SP;
    const __nv_bfloat16* Sl = g_Sl + (size_t)kz*384*SP;
    int wm = (w & 1) * 48, wn = (w >> 1) * 32;

    int g4 = lane >> 3;
    int rsel = (g4 & 1) * 8 + (lane & 7);
    int kselA = (g4 >> 1) * 8;
    int nsel = lane & 7;
    int kselB = ((lane >> 3) & 1) * 8;
    uint32_t aOff[3], bOff[4];
    #pragma unroll
    for (int mt = 0; mt < 3; mt++)
        aOff[mt] = (uint32_t)((wm + mt*16 + rsel)*80 + kselA*2);
    #pragma unroll
    for (int nt = 0; nt < 4; nt++)
        bOff[nt] = (uint32_t)((wn + nt*8 + nsel)*80 + kselB*2);

    float acc[3][4][4];
    #pragma unroll
    for (int mt = 0; mt < 3; mt++)
        #pragma unroll
        for (int nt = 0; nt < 4; nt++)
            #pragma unroll
            for (int q = 0; q < 4; q++) acc[mt][nt][q] = 0.f;

    const int NC = 10;
    for (int idx = t; idx < 768; idx += 256) {        // A chunk 0
        int arr = idx / 384, rem = idx % 384;
        int r = rem >> 2, c4 = rem & 3;
        cp16(sb + arr*7680 + r*80 + c4*16,
             (arr ? Sl : Sh) + (size_t)(rowBase + r)*SP + c4*8);
    }
    for (int idx = t; idx < 1024; idx += 256) {       // B chunk 0
        int arr = idx >> 9, rem = idx & 511;
        int r = rem >> 2, c4 = rem & 3;
        cp16(sb + 30720 + arr*10240 + r*80 + c4*16,
             (arr ? g_HTl : g_HTh) + (size_t)(colBase + r)*SP + c4*8);
    }
    cp_commit();

    for (int c = 0; c < NC; c++) {
        int stage = c & 1;
        if (c + 1 < NC) {
            int m0 = (c + 1) * 32, ns = (c + 1) & 1;
            for (int idx = t; idx < 768; idx += 256) {
                int arr = idx / 384, rem = idx % 384;
                int r = rem >> 2, c4 = rem & 3;
                cp16(sb + ns*15360 + arr*7680 + r*80 + c4*16,
                     (arr ? Sl : Sh) + (size_t)(rowBase + r)*SP + m0 + c4*8);
            }
            for (int idx = t; idx < 1024; idx += 256) {
                int arr = idx >> 9, rem = idx & 511;
                int r = rem >> 2, c4 = rem & 3;
                cp16(sb + 30720 + ns*20480 + arr*10240 + r*80 + c4*16,
                     (arr ? g_HTl : g_HTh) + (size_t)(colBase + r)*SP + m0 + c4*8);
            }
            cp_commit();
            cp_wait1();
        } else {
            cp_wait0();
        }
        __syncthreads();

        uint32_t sA = sb + stage*15360;
        uint32_t sB = sb + 30720 + stage*20480;
        #pragma unroll
        for (int ks = 0; ks < 2; ks++) {
            uint32_t ah[3][4], al[3][4], bh[4][2], bl[4][2];
            #pragma unroll
            for (int mt = 0; mt < 3; mt++) {
                ldm4(ah[mt], sA + aOff[mt] + ks*32);
                ldm4(al[mt], sA + 7680 + aOff[mt] + ks*32);
            }
            #pragma unroll
            for (int nt = 0; nt < 4; nt++) {
                ldm2(bh[nt], sB + bOff[nt] + ks*32);
                ldm2(bl[nt], sB + 10240 + bOff[nt] + ks*32);
            }
            #pragma unroll
            for (int mt = 0; mt < 3; mt++)
                #pragma unroll
                for (int nt = 0; nt < 4; nt++) {
                    mma_bf16(acc[mt][nt], ah[mt], bh[nt]);
                    mma_bf16(acc[mt][nt], ah[mt], bl[nt]);
                    mma_bf16(acc[mt][nt], al[mt], bh[nt]);
                }
        }
        __syncthreads();
    }

    // epilogue: bf16 hi/lo split directly into k5's A layout
    int plane = (kz + 1) * 64;
    #pragma unroll
    for (int nt = 0; nt < 4; nt++) {
        int col = colBase + wn + nt*8 + (lane & 3)*2;
        int b = col >> 6, cc = col & 63;
        size_t boff = (size_t)b*192 + plane + cc;
        #pragma unroll
        for (int mt = 0; mt < 3; mt++) {
            int n0 = rowBase + wm + mt*16 + (lane >> 2);
            if (n0 < NN) {
                __nv_bfloat16 h0, l0, h1, l1;
                bf16_split(acc[mt][nt][0], h0, l0);
                bf16_split(acc[mt][nt][1], h1, l1);
                *(__nv_bfloat162*)(g_XGh + (size_t)n0*12288 + boff) = __halves2bfloat162(h0, h1);
                *(__nv_bfloat162*)(g_XGl + (size_t)n0*12288 + boff) = __halves2bfloat162(l0, l1);
            }
            if (n0 + 8 < NN) {
                __nv_bfloat16 h0, l0, h1, l1;
                bf16_split(acc[mt][nt][2], h0, l0);
                bf16_split(acc[mt][nt][3], h1, l1);
                *(__nv_bfloat162*)(g_XGh + (size_t)(n0+8)*12288 + boff) = __halves2bfloat162(h0, h1);
                *(__nv_bfloat162*)(g_XGl + (size_t)(n0+8)*12288 + boff) = __halves2bfloat162(l0, l1);
            }
        }
    }
}

// ---------------- K5: per-node GEMM, split b-dim: grid (300, 2) -------------
// Block = (node n, batch half bh): A = XG[32 b-rows][192], B = Wn[192][64].
#define K5_AL 12800
#define K5_BH 25600
#define K5_BL 53248
__global__ void __launch_bounds__(256, 2) k5_mma() {
    extern __shared__ char smem[];
    uint32_t sb = smem_u32(smem);
    int t = threadIdx.x, w = t >> 5, lane = t & 31;
    int n = blockIdx.x, bh = blockIdx.y;

    const __nv_bfloat16* Ah = g_XGh + (size_t)n*12288 + bh*32*192;
    const __nv_bfloat16* Al = g_XGl + (size_t)n*12288 + bh*32*192;
    const __nv_bfloat16* Bh = g_Wnh + (size_t)n*12288;
    const __nv_bfloat16* Bl = g_Wnl + (size_t)n*12288;

    for (int idx = t; idx < 768; idx += 256) {        // A: 32 rows x 24 chunks
        int r = idx / 24, cc = idx - r*24;
        cp16(sb + r*400 + cc*16,          Ah + r*192 + cc*8);
        cp16(sb + K5_AL + r*400 + cc*16,  Al + r*192 + cc*8);
    }
    for (int idx = t; idx < 1536; idx += 256) {       // B: 192 rows x 8 chunks
        int r = idx >> 3, cc = idx & 7;
        cp16(sb + K5_BH + r*144 + cc*16,  Bh + r*64 + cc*8);
        cp16(sb + K5_BL + r*144 + cc*16,  Bl + r*64 + cc*8);
    }
    cp_commit();
    cp_wait0();
    __syncthreads();

    int wm = (w & 1) * 16, wn = (w >> 1) * 16;
    int g4 = lane >> 3;
    int rsel = (g4 & 1) * 8 + (lane & 7);
    int kselA = (g4 >> 1) * 8;
    uint32_t aAddrH = sb + (uint32_t)((wm + rsel)*400 + kselA*2);
    uint32_t aAddrL = aAddrH + K5_AL;
    uint32_t bRow = (uint32_t)(lane & 15);
    uint32_t bAddr[2];
    #pragma unroll
    for (int nt = 0; nt < 2; nt++)
        bAddr[nt] = sb + K5_BH + bRow*144 + (uint32_t)((wn + nt*8)*2);

    float acc[2][4];
    #pragma unroll
    for (int nt = 0; nt < 2; nt++)
        #pragma unroll
        for (int q = 0; q < 4; q++) acc[nt][q] = 0.f;

    #pragma unroll
    for (int kc = 0; kc < 12; kc++) {
        uint32_t ah[4], al[4];
        ldm4(ah, aAddrH + kc*32);
        ldm4(al, aAddrL + kc*32);
        #pragma unroll
        for (int nt = 0; nt < 2; nt++) {
            uint32_t bh[2], bl[2];
            ldm2t(bh, bAddr[nt] + (uint32_t)(kc*16*144));
            ldm2t(bl, bAddr[nt] + (uint32_t)(K5_BL - K5_BH) + (uint32_t)(kc*16*144));
            mma_bf16(acc[nt], ah, bh);
            mma_bf16(acc[nt], ah, bl);
            mma_bf16(acc[nt], al, bh);
        }
    }

    // epilogue: +bias, bf16 split, write H2 (row = b*NN + n)
    #pragma unroll
    for (int nt = 0; nt < 2; nt++) {
        int o = wn + nt*8 + (lane & 3)*2;
        float2 bv = *(const float2*)(g_bn + n*64 + o);
        int b0 = bh*32 + wm + (lane >> 2);
        float v0 = acc[nt][0] + bv.x, v1 = acc[nt][1] + bv.y;
        float v2 = acc[nt][2] + bv.x, v3 = acc[nt][3] + bv.y;
        __nv_bfloat16 h0, l0, h1, l1, h2, l2, h3, l3;
        bf16_split(v0, h0, l0); bf16_split(v1, h1, l1);
        bf16_split(v2, h2, l2); bf16_split(v3, h3, l3);
        size_t r0 = ((size_t)(b0*NN + n))*64 + o;
        size_t r1 = ((size_t)((b0+8)*NN + n))*64 + o;
        *(__nv_bfloat162*)(g_H2h + r0) = __halves2bfloat162(h0, h1);
        *(__nv_bfloat162*)(g_H2l + r0) = __halves2bfloat162(l0, l1);
        *(__nv_bfloat162*)(g_H2h + r1) = __halves2bfloat162(h2, h3);
        *(__nv_bfloat162*)(g_H2l + r1) = __halves2bfloat162(l2, l3);
    }
}

// ---------------- K6: out = tanh(H2 @ W_out^T + b_out) via mma.sync bf16 ----
#define ASPLIT 18432                   /* 128*72*2 bytes per split */
__global__ void __launch_bounds__(256, 2) k6_mma(const float* __restrict__ b_out,
                                                 float* __restrict__ out) {
    extern __shared__ char smem[];
    uint32_t sb = smem_u32(smem);
    const int OFF_B = 2 * ASPLIT;
    int t = threadIdx.x, w = t >> 5, lane = t & 31;
    int rowBase = blockIdx.x * 128;
    int colSec  = blockIdx.y * 1024;
    int wm = (w & 1) * 64, wn = (w >> 1) * 32;

    for (int idx = t; idx < 2048; idx += 256) {
        int arr = idx >> 10, rem = idx & 1023;
        int r = rem >> 3, cb = rem & 7;
        const __nv_bfloat16* src = (arr ? g_H2l : g_H2h)
                                 + (size_t)(rowBase + r)*64 + cb*8;
        cp16(sb + arr*ASPLIT + r*144 + cb*16, src);
    }
    for (int idx = t; idx < 2048; idx += 256) {
        int arr = idx >> 10, rem = idx & 1023;
        int r = rem >> 3, cb = rem & 7;
        const __nv_bfloat16* src = (arr ? g_Wl : g_Wh)
                                 + (size_t)(colSec + r)*64 + cb*8;
        cp16(sb + OFF_B + arr*ASPLIT + r*144 + cb*16, src);
    }
    cp_commit();
    cp_wait0();
    __syncthreads();

    int g4 = lane >> 3;
    int rsel = (g4 & 1) * 8 + (lane & 7);
    int kselA = (g4 >> 1) * 8;
    int g2 = (lane >> 3) & 1;
    int nsel = lane & 7;
    int kselB = g2 * 8;

    uint32_t aBase[4][2];
    #pragma unroll
    for (int mt = 0; mt < 4; mt++) {
        uint32_t off = (uint32_t)((wm + mt*16 + rsel)*144 + kselA*2);
        aBase[mt][0] = sb + off;
        aBase[mt][1] = sb + ASPLIT + off;
    }
    uint32_t bOff[4];
    #pragma unroll
    for (int nt = 0; nt < 4; nt++)
        bOff[nt] = (uint32_t)((wn + nt*8 + nsel)*144 + kselB*2);

    for (int it = 0; it < 8; it++) {
        int stage = it & 1;
        if (it + 1 < 8) {
            int nc = colSec + (it + 1) * 128;
            for (int idx = t; idx < 2048; idx += 256) {
                int arr = idx >> 10, rem = idx & 1023;
                int r = rem >> 3, cb = rem & 7;
                const __nv_bfloat16* src = (arr ? g_Wl : g_Wh)
                                         + (size_t)(nc + r)*64 + cb*8;
                cp16(sb + OFF_B + (stage^1)*2*ASPLIT + arr*ASPLIT + r*144 + cb*16, src);
            }
        }
        cp_commit();

        float acc[4][4][4];
        #pragma unroll
        for (int mt = 0; mt < 4; mt++)
            #pragma unroll
            for (int nt = 0; nt < 4; nt++)
                #pragma unroll
                for (int q = 0; q < 4; q++) acc[mt][nt][q] = 0.f;

        uint32_t bStage = sb + OFF_B + stage*2*ASPLIT;
        #pragma unroll
        for (int ks = 0; ks < 4; ks++) {
            uint32_t ah[4][4], al[4][4], bh[4][2], bl[4][2];
            #pragma unroll
            for (int mt = 0; mt < 4; mt++) {
                ldm4(ah[mt], aBase[mt][0] + ks*32);
                ldm4(al[mt], aBase[mt][1] + ks*32);
            }
            #pragma unroll
            for (int nt = 0; nt < 4; nt++) {
                ldm2(bh[nt], bStage + bOff[nt] + ks*32);
                ldm2(bl[nt], bStage + ASPLIT + bOff[nt] + ks*32);
            }
            #pragma unroll
            for (int mt = 0; mt < 4; mt++)
                #pragma unroll
                for (int nt = 0; nt < 4; nt++) {
                    mma_bf16(acc[mt][nt], ah[mt], bh[nt]);
                    mma_bf16(acc[mt][nt], ah[mt], bl[nt]);
                    mma_bf16(acc[mt][nt], al[mt], bh[nt]);
                }
        }

        int colT = colSec + it*128 + wn;
        #pragma unroll
        for (int nt = 0; nt < 4; nt++) {
            int col = colT + nt*8 + (lane & 3)*2;
            float2 bv = *(const float2*)(b_out + col);
            #pragma unroll
            for (int mt = 0; mt < 4; mt++) {
                int row0 = rowBase + wm + mt*16 + (lane >> 2);
                float2 o0, o1;
                o0.x = my_tanh(acc[mt][nt][0] + bv.x);
                o0.y = my_tanh(acc[mt][nt][1] + bv.y);
                o1.x = my_tanh(acc[mt][nt][2] + bv.x);
                o1.y = my_tanh(acc[mt][nt][3] + bv.y);
                *(float2*)(out + (size_t)row0*HC2 + col)       = o0;
                *(float2*)(out + (size_t)(row0+8)*HC2 + col)   = o1;
            }
        }

        cp_wait0();
        __syncthreads();
    }
}

// ---------------- launch -----------------------------------------------------
extern "C" void kernel_launch(void* const* d_in, const int* in_sizes, int n_in,
                              void* d_out, int out_size) {
    const float* z      = (const float*)d_in[0];
    const float* W_in   = (const float*)d_in[1];
    const float* b_in   = (const float*)d_in[2];
    const float* W_out  = (const float*)d_in[3];
    const float* b_out  = (const float*)d_in[4];
    const float* emb    = (const float*)d_in[5];
    const float* wpool  = (const float*)d_in[6];
    const float* bpool  = (const float*)d_in[7];
    float* out = (float*)d_out;

    const int SM4 = 71680;        // A 2x15360 + B 2x20480
    const int SM5 = 80896;        // A 2x12800 + B 2x27648
    const int SM6 = 6 * ASPLIT;   // 110592
    cudaFuncSetAttribute(k4_mma,
        cudaFuncAttributeMaxDynamicSharedMemorySize, SM4);
    cudaFuncSetAttribute(k5_mma,
        cudaFuncAttributeMaxDynamicSharedMemorySize, SM5);
    cudaFuncSetAttribute(k6_mma,
        cudaFuncAttributeMaxDynamicSharedMemorySize, SM6);

    L1_prologue<<<729, 320>>>(z, W_in, b_in, W_out, emb, wpool, bpool);
    L2_cheb_ht <<<364, 320>>>();
    k4_mma     <<<dim3(4, 32, 2), 256, SM4>>>();
    k5_mma     <<<dim3(NN, 2), 256, SM5>>>();
    k6_mma     <<<dim3(150, 4), 256, SM6>>>(b_out, out);
}